// round 1
// baseline (speedup 1.0000x reference)
#include <cuda_runtime.h>
#include <math.h>

// Problem constants
#define BB 2
#define SS 1024
#define HH 16
#define DD 64
#define DM 1024
#define NREL 257

// Scratch (device globals: no runtime allocation allowed)
__device__ float g_Q[BB*SS*DM];            // [B,S,H*D] post-proj (+RoPE)
__device__ float g_K[BB*SS*DM];
__device__ float g_V[BB*SS*DM];
__device__ float g_qbar[BB*HH*SS*DD];      // [B,M,S,D] pre-mixed q
__device__ float g_Rbar[BB*HH*SS*NREL];    // [B,M,S,257]
__device__ float g_S[BB*HH*SS*SS];         // scores -> attn (in place)
__device__ float g_Ap[BB*HH*SS*NREL];      // band-summed attention
__device__ float g_Y[BB*HH*SS*DD];         // A' @ relv
__device__ float g_ctx[BB*SS*DM];          // [B,S,H*D] context

// ---------------------------------------------------------------------------
// Generic tiled fp32 GEMM: C = A @ B(^T) [+ bias] [+ addend]
// 64x64 tile, KT=16, 256 threads, 4x4 micro-tile.
// Batch offsets: z -> (zo, zi) with zo = z / bInner, zi = z % bInner.
// ---------------------------------------------------------------------------
template<bool TRANSB>
__global__ void __launch_bounds__(256)
gemm_kernel(const float* __restrict__ A, const float* __restrict__ Bm,
            float* __restrict__ C,
            int M, int N, int K, int lda, int ldb, int ldc,
            long sAin, long sAout, long sBin, long sBout, long sCin, long sCout,
            int bInner,
            const float* __restrict__ bias,
            const float* __restrict__ addend, int ldadd, long sAddIn, long sAddOut)
{
    __shared__ __align__(16) float As[16][68];
    __shared__ __align__(16) float Bs[16][68];

    int z = blockIdx.z;
    int zo = z / bInner, zi = z - zo * bInner;
    A  += zo * sAout + zi * sAin;
    Bm += zo * sBout + zi * sBin;
    C  += zo * sCout + zi * sCin;
    if (addend) addend += zo * sAddOut + zi * sAddIn;

    int tid = threadIdx.x;
    int tx = tid & 15, ty = tid >> 4;
    int m0 = blockIdx.y * 64, n0 = blockIdx.x * 64;

    float acc[4][4];
    #pragma unroll
    for (int i = 0; i < 4; i++)
        #pragma unroll
        for (int j = 0; j < 4; j++) acc[i][j] = 0.f;

    int ka = tid & 15, ra = tid >> 4;     // A / B-NT loader coords
    int cb = tid & 63, kb0 = tid >> 6;    // B-NN loader coords

    for (int kt = 0; kt < K; kt += 16) {
        #pragma unroll
        for (int u = 0; u < 4; u++) {
            int r = ra + u * 16;
            int gm = m0 + r, gk = kt + ka;
            As[ka][r] = (gm < M && gk < K) ? A[(long)gm * lda + gk] : 0.f;
        }
        if (TRANSB) {
            #pragma unroll
            for (int u = 0; u < 4; u++) {
                int c = ra + u * 16;
                int gn = n0 + c, gk = kt + ka;
                Bs[ka][c] = (gn < N && gk < K) ? Bm[(long)gn * ldb + gk] : 0.f;
            }
        } else {
            #pragma unroll
            for (int u = 0; u < 4; u++) {
                int kk = kb0 + u * 4;
                int gk = kt + kk, gn = n0 + cb;
                Bs[kk][cb] = (gk < K && gn < N) ? Bm[(long)gk * ldb + gn] : 0.f;
            }
        }
        __syncthreads();
        #pragma unroll
        for (int j = 0; j < 16; j++) {
            float4 av = *reinterpret_cast<const float4*>(&As[j][ty * 4]);
            float4 bv = *reinterpret_cast<const float4*>(&Bs[j][tx * 4]);
            float a_[4] = {av.x, av.y, av.z, av.w};
            float b_[4] = {bv.x, bv.y, bv.z, bv.w};
            #pragma unroll
            for (int i = 0; i < 4; i++)
                #pragma unroll
                for (int ii = 0; ii < 4; ii++)
                    acc[i][ii] += a_[i] * b_[ii];
        }
        __syncthreads();
    }

    #pragma unroll
    for (int i = 0; i < 4; i++) {
        int m = m0 + ty * 4 + i;
        if (m >= M) continue;
        #pragma unroll
        for (int ii = 0; ii < 4; ii++) {
            int n = n0 + tx * 4 + ii;
            if (n >= N) continue;
            float v = acc[i][ii];
            if (bias)   v += bias[n];
            if (addend) v += addend[(long)m * ldadd + n];
            C[(long)m * ldc + n] = v;
        }
    }
}

// ---------------------------------------------------------------------------
// In-place RoPE (sinusoidal, NeoX-style rotate-half) on [B,S,H*D]
// double precision trig to match the numpy float64 table closely.
// ---------------------------------------------------------------------------
__global__ void rope_kernel(float* __restrict__ X, const int* __restrict__ pos_ids)
{
    int idx = blockIdx.x * blockDim.x + threadIdx.x;   // B*S*H*32 = 1M
    if (idx >= BB * SS * HH * 32) return;
    int i = idx & 31;
    int h = (idx >> 5) & 15;
    int s = (idx >> 9) & 1023;
    int b = idx >> 19;
    int pos = pos_ids[b * SS + s];
    double inv = exp(-(double)i / 32.0 * log(10000.0));
    double a = (double)pos * inv;
    double ds, dc;
    sincos(a, &ds, &dc);
    float c = (float)dc, sn = (float)ds;
    float* p = X + ((size_t)(b * SS + s)) * DM + h * DD + i;
    float x1 = p[0], x2 = p[32];
    p[0]  = x1 * c - x2 * sn;
    p[32] = x2 * c + x1 * sn;
}

// ---------------------------------------------------------------------------
// qbar[b,m,s,d] = sum_n w_pre[n,m] * Q[b,s,n*64+d]
// ---------------------------------------------------------------------------
__global__ void qbar_kernel(const float* __restrict__ Q, const float* __restrict__ wpre,
                            float* __restrict__ qbar)
{
    int idx = blockIdx.x * blockDim.x + threadIdx.x;   // B*H*S*D = 2M
    if (idx >= BB * HH * SS * DD) return;
    int d = idx & 63;
    int s = (idx >> 6) & 1023;
    int m = (idx >> 16) & 15;
    int b = idx >> 20;
    const float* qrow = Q + ((size_t)(b * SS + s)) * DM + d;
    float acc = 0.f;
    #pragma unroll
    for (int n = 0; n < 16; n++) acc += __ldg(&wpre[n * 16 + m]) * qrow[n * 64];
    qbar[idx] = acc;
}

// ---------------------------------------------------------------------------
// Fused: pre-mix (w_pre) + rel-K bias + /8 + causal mask + softmax
//        + post-mix (w_post) + A' band-extraction.  One CTA per (b, q) row.
// Scores buffer is rewritten in place with post-mix attention.
// ---------------------------------------------------------------------------
#define MIX_SMEM ((16*1024 + 16*257 + 256 + 256 + 16 + 16) * 4)

__global__ void __launch_bounds__(512)
mix_softmax_kernel(float* __restrict__ S, const float* __restrict__ Rbar,
                   const float* __restrict__ wpre, const float* __restrict__ wpost,
                   float* __restrict__ Ap)
{
    extern __shared__ float shm[];
    float* sm     = shm;                 // [16][1024]
    float* srb    = sm + 16 * 1024;      // [16][257]
    float* swpre  = srb + 16 * 257;      // [256]
    float* swpost = swpre + 256;         // [256]
    float* sinv   = swpost + 256;        // [16]
    float* stail  = sinv + 16;           // [16]

    int q = blockIdx.x, b = blockIdx.y;
    int tid = threadIdx.x;
    int wid = tid >> 5, lane = tid & 31;

    if (tid < 256) { swpre[tid] = wpre[tid]; swpost[tid] = wpost[tid]; }
    #pragma unroll
    for (int n = 0; n < 16; n++) {
        const float* src = S + (((size_t)(b * 16 + n) * SS + q) * SS);
        for (int k = tid; k < SS; k += 512) sm[n * 1024 + k] = src[k];
    }
    for (int t = tid; t < 16 * NREL; t += 512) {
        int m = t / NREL, j = t - m * NREL;
        srb[t] = Rbar[((size_t)(b * 16 + m) * SS + q) * NREL + j];
    }
    __syncthreads();

    // Phase 1: per-column pre-mix + rel bias + scale + mask (in place per column)
    for (int k = tid; k < SS; k += 512) {
        float r[16];
        #pragma unroll
        for (int n = 0; n < 16; n++) r[n] = sm[n * 1024 + k];
        int d = q - k;
        int cl = d > 128 ? 128 : (d < -128 ? -128 : d);
        int idx = cl + 128;
        bool masked = (k > q);
        #pragma unroll
        for (int m = 0; m < 16; m++) {
            float accv = 0.f;
            #pragma unroll
            for (int n = 0; n < 16; n++) accv += swpre[n * 16 + m] * r[n];
            float v = (accv + srb[m * NREL + idx]) * 0.125f;
            sm[m * 1024 + k] = masked ? -1e30f : v;
        }
    }
    __syncthreads();

    // Phase 2: softmax (warp per head), only k <= q contribute (mask underflows to 0)
    {
        int m = wid;
        float mx = -1e30f;
        for (int k = lane; k <= q; k += 32) mx = fmaxf(mx, sm[m * 1024 + k]);
        #pragma unroll
        for (int o = 16; o; o >>= 1) mx = fmaxf(mx, __shfl_xor_sync(0xffffffffu, mx, o));
        float sum = 0.f;
        for (int k = lane; k <= q; k += 32) {
            float p = __expf(sm[m * 1024 + k] - mx);
            sm[m * 1024 + k] = p;
            sum += p;
        }
        #pragma unroll
        for (int o = 16; o; o >>= 1) sum += __shfl_xor_sync(0xffffffffu, sum, o);
        for (int k = q + 1 + lane; k < SS; k += 32) sm[m * 1024 + k] = 0.f;
        if (lane == 0) sinv[m] = 1.f / sum;
    }
    __syncthreads();

    // Phase 3: per-column post-mix (in place per column)
    float inv[16];
    #pragma unroll
    for (int m = 0; m < 16; m++) inv[m] = sinv[m];
    for (int k = tid; k < SS; k += 512) {
        float p[16];
        #pragma unroll
        for (int m = 0; m < 16; m++) p[m] = sm[m * 1024 + k] * inv[m];
        #pragma unroll
        for (int n = 0; n < 16; n++) {
            float accv = 0.f;
            #pragma unroll
            for (int m = 0; m < 16; m++) accv += p[m] * swpost[m * 16 + n];
            sm[n * 1024 + k] = accv;
        }
    }
    __syncthreads();

    // Write attention back (in place over scores) + tail sums for A'
    #pragma unroll
    for (int n = 0; n < 16; n++) {
        float* dst = S + (((size_t)(b * 16 + n) * SS + q) * SS);
        for (int k = tid; k < SS; k += 512) dst[k] = sm[n * 1024 + k];
    }
    {
        int m = wid;
        float ts = 0.f;
        for (int k = lane; k <= q - 128; k += 32) ts += sm[m * 1024 + k];
        #pragma unroll
        for (int o = 16; o; o >>= 1) ts += __shfl_xor_sync(0xffffffffu, ts, o);
        if (lane == 0) stail[m] = ts;
    }
    __syncthreads();

    // A'[b,n,q,j]: j in [128,255] -> single element k = q-(j-128); j==256 -> tail
    for (int t = tid; t < 16 * NREL; t += 512) {
        int n = t / NREL, j = t - n * NREL;
        float v = 0.f;
        if (j == 256) v = stail[n];
        else if (j >= 128) {
            int k = q - (j - 128);
            if (k >= 0) v = sm[n * 1024 + k];
        }
        Ap[((size_t)(b * 16 + n) * SS + q) * NREL + j] = v;
    }
}

// ---------------------------------------------------------------------------
// Launch sequence
// ---------------------------------------------------------------------------
extern "C" void kernel_launch(void* const* d_in, const int* in_sizes, int n_in,
                              void* d_out, int out_size)
{
    const float* query = (const float*)d_in[0];
    const float* key_  = (const float*)d_in[1];
    const float* value = (const float*)d_in[2];
    const int*   qpos  = (const int*)d_in[4];
    const int*   kpos  = (const int*)d_in[5];
    const float* Wq = (const float*)d_in[6];  const float* bq = (const float*)d_in[7];
    const float* Wk = (const float*)d_in[8];  const float* bk = (const float*)d_in[9];
    const float* Wv = (const float*)d_in[10]; const float* bv = (const float*)d_in[11];
    const float* Wo = (const float*)d_in[12]; const float* bo = (const float*)d_in[13];
    const float* relk  = (const float*)d_in[14];
    const float* relv  = (const float*)d_in[15];
    const float* wpre  = (const float*)d_in[16];
    const float* wpost = (const float*)d_in[17];
    float* out = (float*)d_out;

    float *Q, *Kc, *V, *qbar, *Rbar, *Sc, *Ap, *Y, *ctx;
    cudaGetSymbolAddress((void**)&Q,    g_Q);
    cudaGetSymbolAddress((void**)&Kc,   g_K);
    cudaGetSymbolAddress((void**)&V,    g_V);
    cudaGetSymbolAddress((void**)&qbar, g_qbar);
    cudaGetSymbolAddress((void**)&Rbar, g_Rbar);
    cudaGetSymbolAddress((void**)&Sc,   g_S);
    cudaGetSymbolAddress((void**)&Ap,   g_Ap);
    cudaGetSymbolAddress((void**)&Y,    g_Y);
    cudaGetSymbolAddress((void**)&ctx,  g_ctx);

    dim3 blk(256);
    const long S2 = (long)SS * SS;          // 1048576
    const long SD = (long)SS * DM;          // 1048576

    // Projections: [2048,1024] = X @ W^T + b
    gemm_kernel<true><<<dim3(16, 32, 1), blk>>>(query, Wq, Q, 2048, 1024, 1024,
        1024, 1024, 1024, 0, 0, 0, 0, 0, 0, 1, bq, nullptr, 0, 0, 0);
    gemm_kernel<true><<<dim3(16, 32, 1), blk>>>(key_, Wk, Kc, 2048, 1024, 1024,
        1024, 1024, 1024, 0, 0, 0, 0, 0, 0, 1, bk, nullptr, 0, 0, 0);
    gemm_kernel<true><<<dim3(16, 32, 1), blk>>>(value, Wv, V, 2048, 1024, 1024,
        1024, 1024, 1024, 0, 0, 0, 0, 0, 0, 1, bv, nullptr, 0, 0, 0);

    // RoPE on Q and K
    rope_kernel<<<4096, 256>>>(Q, qpos);
    rope_kernel<<<4096, 256>>>(Kc, kpos);

    // qbar = w_pre-mixed q; Rbar = qbar @ relk^T
    qbar_kernel<<<8192, 256>>>(Q, wpre, qbar);
    gemm_kernel<true><<<dim3(5, 512, 1), blk>>>(qbar, relk, Rbar, 32768, NREL, 64,
        64, 64, NREL, 0, 0, 0, 0, 0, 0, 1, nullptr, nullptr, 0, 0, 0);

    // Per-head QK^T (batch = 32 over (b, n))
    gemm_kernel<true><<<dim3(16, 16, 32), blk>>>(Q, Kc, Sc, 1024, 1024, 64,
        1024, 1024, 1024,
        64L, SD,            // A: +64 per head, +S*DM per batch
        64L, SD,            // B: same
        S2, 16L * S2,       // C: +S*S per head, +16*S*S per batch
        16, nullptr, nullptr, 0, 0, 0);

    // Fused mix + softmax + post-mix + A'
    cudaFuncSetAttribute(mix_softmax_kernel,
                         cudaFuncAttributeMaxDynamicSharedMemorySize, MIX_SMEM);
    mix_softmax_kernel<<<dim3(1024, 2), 512, MIX_SMEM>>>(Sc, Rbar, wpre, wpost, Ap);

    // Y = A' @ relv
    gemm_kernel<false><<<dim3(1, 512, 1), blk>>>(Ap, relv, Y, 32768, 64, NREL,
        NREL, 64, 64, 0, 0, 0, 0, 0, 0, 1, nullptr, nullptr, 0, 0, 0);

    // ctx = attn @ v + Y   (batch = 32 over (b, n)); ctx layout [B,S,H*D]
    gemm_kernel<false><<<dim3(1, 16, 32), blk>>>(Sc, V, ctx, 1024, 64, 1024,
        1024, 1024, 1024,
        S2, 16L * S2,       // A (attn): +S*S per head, +16*S*S per batch
        64L, SD,            // B (v): +64 per head, +S*DM per batch
        64L, SD,            // C (ctx): +64 per head, +S*DM per batch
        16, nullptr,
        Y, 64, 65536L, 16L * 65536L);

    // out = ctx @ Wo^T + bo
    gemm_kernel<true><<<dim3(16, 32, 1), blk>>>(ctx, Wo, out, 2048, 1024, 1024,
        1024, 1024, 1024, 0, 0, 0, 0, 0, 0, 1, bo, nullptr, 0, 0, 0);
}

// round 2
// speedup vs baseline: 1.4516x; 1.4516x over previous
#include <cuda_runtime.h>
#include <cuda_bf16.h>
#include <mma.h>
#include <math.h>

using namespace nvcuda;

// Problem constants
#define BB 2
#define SS 1024
#define HH 16
#define DD 64
#define DM 1024
#define NREL 257

// Scratch (device globals: no runtime allocation allowed)
__device__ float g_Q[BB*SS*DM];            // [B,S,H*D] post-proj (+RoPE)
__device__ float g_K[BB*SS*DM];
__device__ float g_V[BB*SS*DM];
__device__ float g_qbar[BB*HH*SS*DD];      // [B,M,S,D] pre-mixed q
__device__ float g_Rbar[BB*HH*SS*NREL];    // [B,M,S,257]
__device__ float g_S[BB*HH*SS*SS];         // scores -> attn (in place)
__device__ float g_Ap[BB*HH*SS*NREL];      // band-summed attention
__device__ float g_Y[BB*HH*SS*DD];         // A' @ relv
__device__ float g_ctx[BB*SS*DM];          // [B,S,H*D] context
__device__ float g_ropeT[2048*64];         // [pos][0:32]=cos, [32:64]=sin

// ---------------------------------------------------------------------------
// Tensor-core GEMM (bf16 split-precision, 3 MMA passes = ~fp32 accuracy)
// C = A @ B(^T) [+ bias] [+ addend].  CTA tile 128x64, K-step 32, 256 threads.
// Batch offsets: z -> (zo, zi) with zo = z / bInner, zi = z % bInner.
// ---------------------------------------------------------------------------
#define LDA_S 48      // smem A leading dim (bf16 elems)
#define LDB_S 80      // smem B leading dim (bf16 elems)
#define LDC_S 68      // smem stage leading dim (float elems)

#define GEMM_SMEM_BYTES (2*(128*LDA_S + 32*LDB_S)*2 > 128*LDC_S*4 ? \
                         2*(128*LDA_S + 32*LDB_S)*2 : 128*LDC_S*4)

template<bool TRANSB>
__global__ void __launch_bounds__(256)
gemm_kernel(const float* __restrict__ A, const float* __restrict__ Bm,
            float* __restrict__ C,
            int M, int N, int K, int lda, int ldb, int ldc,
            long sAin, long sAout, long sBin, long sBout, long sCin, long sCout,
            int bInner,
            const float* __restrict__ bias,
            const float* __restrict__ addend, int ldadd, long sAddIn, long sAddOut)
{
    __shared__ __align__(16) unsigned char smbuf[GEMM_SMEM_BYTES];
    __nv_bfloat16* Ahi = (__nv_bfloat16*)smbuf;                 // [128][LDA_S]
    __nv_bfloat16* Alo = Ahi + 128 * LDA_S;
    __nv_bfloat16* Bhi = Alo + 128 * LDA_S;                     // [32][LDB_S]
    __nv_bfloat16* Blo = Bhi + 32 * LDB_S;
    float* stage = (float*)smbuf;                               // [128][LDC_S]

    int z = blockIdx.z;
    int zo = z / bInner, zi = z - zo * bInner;
    A  += zo * sAout + zi * sAin;
    Bm += zo * sBout + zi * sBin;
    C  += zo * sCout + zi * sCin;
    if (addend) addend += zo * sAddOut + zi * sAddIn;

    int tid = threadIdx.x;
    int wid = tid >> 5;
    int wm = wid >> 1;            // 0..3 : 32-row slab
    int wn = wid & 1;             // 0..1 : 32-col slab
    int m0 = blockIdx.y * 128, n0 = blockIdx.x * 64;

    wmma::fragment<wmma::accumulator, 16, 16, 16, float> acc[2][2];
    #pragma unroll
    for (int i = 0; i < 2; i++)
        #pragma unroll
        for (int j = 0; j < 2; j++) wmma::fill_fragment(acc[i][j], 0.0f);

    for (int kt = 0; kt < K; kt += 32) {
        // Load A tile [128][32] -> hi/lo bf16 (coalesced: 32 consecutive k)
        #pragma unroll
        for (int u = 0; u < 16; u++) {
            int idx = tid + u * 256;
            int r = idx >> 5, kk = idx & 31;
            int gm = m0 + r, gk = kt + kk;
            float v = (gm < M && gk < K) ? A[(long)gm * lda + gk] : 0.f;
            __nv_bfloat16 h = __float2bfloat16(v);
            Ahi[r * LDA_S + kk] = h;
            Alo[r * LDA_S + kk] = __float2bfloat16(v - __bfloat162float(h));
        }
        // Load B tile -> Bs[k][n]
        if (TRANSB) {
            #pragma unroll
            for (int u = 0; u < 8; u++) {
                int idx = tid + u * 256;
                int n = idx >> 5, kk = idx & 31;
                int gn = n0 + n, gk = kt + kk;
                float v = (gn < N && gk < K) ? Bm[(long)gn * ldb + gk] : 0.f;
                __nv_bfloat16 h = __float2bfloat16(v);
                Bhi[kk * LDB_S + n] = h;
                Blo[kk * LDB_S + n] = __float2bfloat16(v - __bfloat162float(h));
            }
        } else {
            #pragma unroll
            for (int u = 0; u < 8; u++) {
                int idx = tid + u * 256;
                int kk = idx >> 6, n = idx & 63;
                int gk = kt + kk, gn = n0 + n;
                float v = (gk < K && gn < N) ? Bm[(long)gk * ldb + gn] : 0.f;
                __nv_bfloat16 h = __float2bfloat16(v);
                Bhi[kk * LDB_S + n] = h;
                Blo[kk * LDB_S + n] = __float2bfloat16(v - __bfloat162float(h));
            }
        }
        __syncthreads();

        #pragma unroll
        for (int kk = 0; kk < 32; kk += 16) {
            wmma::fragment<wmma::matrix_a, 16, 16, 16, __nv_bfloat16, wmma::row_major> ah[2], al[2];
            wmma::fragment<wmma::matrix_b, 16, 16, 16, __nv_bfloat16, wmma::row_major> bh[2], bl[2];
            #pragma unroll
            for (int i = 0; i < 2; i++) {
                wmma::load_matrix_sync(ah[i], &Ahi[(wm * 32 + i * 16) * LDA_S + kk], LDA_S);
                wmma::load_matrix_sync(al[i], &Alo[(wm * 32 + i * 16) * LDA_S + kk], LDA_S);
            }
            #pragma unroll
            for (int j = 0; j < 2; j++) {
                wmma::load_matrix_sync(bh[j], &Bhi[kk * LDB_S + wn * 32 + j * 16], LDB_S);
                wmma::load_matrix_sync(bl[j], &Blo[kk * LDB_S + wn * 32 + j * 16], LDB_S);
            }
            #pragma unroll
            for (int i = 0; i < 2; i++)
                #pragma unroll
                for (int j = 0; j < 2; j++) {
                    wmma::mma_sync(acc[i][j], ah[i], bh[j], acc[i][j]);
                    wmma::mma_sync(acc[i][j], ah[i], bl[j], acc[i][j]);
                    wmma::mma_sync(acc[i][j], al[i], bh[j], acc[i][j]);
                }
        }
        __syncthreads();
    }

    // Epilogue: stage in smem, then bounded coalesced writeback
    #pragma unroll
    for (int i = 0; i < 2; i++)
        #pragma unroll
        for (int j = 0; j < 2; j++)
            wmma::store_matrix_sync(&stage[(wm * 32 + i * 16) * LDC_S + wn * 32 + j * 16],
                                    acc[i][j], LDC_S, wmma::mem_row_major);
    __syncthreads();

    #pragma unroll
    for (int u = 0; u < 32; u++) {
        int idx = tid + u * 256;
        int r = idx >> 6, c = idx & 63;
        int gm = m0 + r, gn = n0 + c;
        if (gm < M && gn < N) {
            float v = stage[r * LDC_S + c];
            if (bias)   v += bias[gn];
            if (addend) v += addend[(long)gm * ldadd + gn];
            C[(long)gm * ldc + gn] = v;
        }
    }
}

// ---------------------------------------------------------------------------
// RoPE table (double trig once per launch; 64K entries) + cheap apply
// ---------------------------------------------------------------------------
__global__ void rope_table_kernel(float* __restrict__ T)
{
    int idx = blockIdx.x * blockDim.x + threadIdx.x;   // 2048*32
    if (idx >= 2048 * 32) return;
    int i = idx & 31, pos = idx >> 5;
    double inv = exp(-(double)i / 32.0 * log(10000.0));
    double ds, dc;
    sincos((double)pos * inv, &ds, &dc);
    T[pos * 64 + i]      = (float)dc;
    T[pos * 64 + 32 + i] = (float)ds;
}

__global__ void rope_kernel(float* __restrict__ X, const int* __restrict__ pos_ids,
                            const float* __restrict__ T)
{
    int idx = blockIdx.x * blockDim.x + threadIdx.x;   // B*S*H*32 = 1M
    if (idx >= BB * SS * HH * 32) return;
    int i = idx & 31;
    int h = (idx >> 5) & 15;
    int s = (idx >> 9) & 1023;
    int b = idx >> 19;
    int pos = pos_ids[b * SS + s];
    float c  = T[pos * 64 + i];
    float sn = T[pos * 64 + 32 + i];
    float* p = X + ((size_t)(b * SS + s)) * DM + h * DD + i;
    float x1 = p[0], x2 = p[32];
    p[0]  = x1 * c - x2 * sn;
    p[32] = x2 * c + x1 * sn;
}

// ---------------------------------------------------------------------------
// qbar[b,m,s,d] = sum_n w_pre[n,m] * Q[b,s,n*64+d]
// ---------------------------------------------------------------------------
__global__ void qbar_kernel(const float* __restrict__ Q, const float* __restrict__ wpre,
                            float* __restrict__ qbar)
{
    int idx = blockIdx.x * blockDim.x + threadIdx.x;   // B*H*S*D = 2M
    if (idx >= BB * HH * SS * DD) return;
    int d = idx & 63;
    int s = (idx >> 6) & 1023;
    int m = (idx >> 16) & 15;
    int b = idx >> 20;
    const float* qrow = Q + ((size_t)(b * SS + s)) * DM + d;
    float acc = 0.f;
    #pragma unroll
    for (int n = 0; n < 16; n++) acc += __ldg(&wpre[n * 16 + m]) * qrow[n * 64];
    qbar[idx] = acc;
}

// ---------------------------------------------------------------------------
// Fused: pre-mix (w_pre) + rel-K bias + /8 + causal mask + softmax
//        + post-mix (w_post) + A' band-extraction.  One CTA per (b, q) row.
// ---------------------------------------------------------------------------
#define MIX_SMEM ((16*1024 + 16*257 + 256 + 256 + 16 + 16) * 4)

__global__ void __launch_bounds__(512)
mix_softmax_kernel(float* __restrict__ S, const float* __restrict__ Rbar,
                   const float* __restrict__ wpre, const float* __restrict__ wpost,
                   float* __restrict__ Ap)
{
    extern __shared__ float shm[];
    float* sm     = shm;                 // [16][1024]
    float* srb    = sm + 16 * 1024;      // [16][257]
    float* swpre  = srb + 16 * 257;      // [256]
    float* swpost = swpre + 256;         // [256]
    float* sinv   = swpost + 256;        // [16]
    float* stail  = sinv + 16;           // [16]

    int q = blockIdx.x, b = blockIdx.y;
    int tid = threadIdx.x;
    int wid = tid >> 5, lane = tid & 31;

    if (tid < 256) { swpre[tid] = wpre[tid]; swpost[tid] = wpost[tid]; }
    #pragma unroll
    for (int n = 0; n < 16; n++) {
        const float* src = S + (((size_t)(b * 16 + n) * SS + q) * SS);
        for (int k = tid; k < SS; k += 512) sm[n * 1024 + k] = src[k];
    }
    for (int t = tid; t < 16 * NREL; t += 512) {
        int m = t / NREL, j = t - m * NREL;
        srb[t] = Rbar[((size_t)(b * 16 + m) * SS + q) * NREL + j];
    }
    __syncthreads();

    // Phase 1: pre-mix + rel bias + scale + mask
    for (int k = tid; k < SS; k += 512) {
        float r[16];
        #pragma unroll
        for (int n = 0; n < 16; n++) r[n] = sm[n * 1024 + k];
        int d = q - k;
        int cl = d > 128 ? 128 : (d < -128 ? -128 : d);
        int idx = cl + 128;
        bool masked = (k > q);
        #pragma unroll
        for (int m = 0; m < 16; m++) {
            float accv = 0.f;
            #pragma unroll
            for (int n = 0; n < 16; n++) accv += swpre[n * 16 + m] * r[n];
            float v = (accv + srb[m * NREL + idx]) * 0.125f;
            sm[m * 1024 + k] = masked ? -1e30f : v;
        }
    }
    __syncthreads();

    // Phase 2: softmax (warp per head)
    {
        int m = wid;
        float mx = -1e30f;
        for (int k = lane; k <= q; k += 32) mx = fmaxf(mx, sm[m * 1024 + k]);
        #pragma unroll
        for (int o = 16; o; o >>= 1) mx = fmaxf(mx, __shfl_xor_sync(0xffffffffu, mx, o));
        float sum = 0.f;
        for (int k = lane; k <= q; k += 32) {
            float p = __expf(sm[m * 1024 + k] - mx);
            sm[m * 1024 + k] = p;
            sum += p;
        }
        #pragma unroll
        for (int o = 16; o; o >>= 1) sum += __shfl_xor_sync(0xffffffffu, sum, o);
        for (int k = q + 1 + lane; k < SS; k += 32) sm[m * 1024 + k] = 0.f;
        if (lane == 0) sinv[m] = 1.f / sum;
    }
    __syncthreads();

    // Phase 3: post-mix
    float inv[16];
    #pragma unroll
    for (int m = 0; m < 16; m++) inv[m] = sinv[m];
    for (int k = tid; k < SS; k += 512) {
        float p[16];
        #pragma unroll
        for (int m = 0; m < 16; m++) p[m] = sm[m * 1024 + k] * inv[m];
        #pragma unroll
        for (int n = 0; n < 16; n++) {
            float accv = 0.f;
            #pragma unroll
            for (int m = 0; m < 16; m++) accv += p[m] * swpost[m * 16 + n];
            sm[n * 1024 + k] = accv;
        }
    }
    __syncthreads();

    // Write attention back + tail sums
    #pragma unroll
    for (int n = 0; n < 16; n++) {
        float* dst = S + (((size_t)(b * 16 + n) * SS + q) * SS);
        for (int k = tid; k < SS; k += 512) dst[k] = sm[n * 1024 + k];
    }
    {
        int m = wid;
        float ts = 0.f;
        for (int k = lane; k <= q - 128; k += 32) ts += sm[m * 1024 + k];
        #pragma unroll
        for (int o = 16; o; o >>= 1) ts += __shfl_xor_sync(0xffffffffu, ts, o);
        if (lane == 0) stail[m] = ts;
    }
    __syncthreads();

    // A'[b,n,q,j]
    for (int t = tid; t < 16 * NREL; t += 512) {
        int n = t / NREL, j = t - n * NREL;
        float v = 0.f;
        if (j == 256) v = stail[n];
        else if (j >= 128) {
            int k = q - (j - 128);
            if (k >= 0) v = sm[n * 1024 + k];
        }
        Ap[((size_t)(b * 16 + n) * SS + q) * NREL + j] = v;
    }
}

// ---------------------------------------------------------------------------
// Launch sequence
// ---------------------------------------------------------------------------
extern "C" void kernel_launch(void* const* d_in, const int* in_sizes, int n_in,
                              void* d_out, int out_size)
{
    const float* query = (const float*)d_in[0];
    const float* key_  = (const float*)d_in[1];
    const float* value = (const float*)d_in[2];
    const int*   qpos  = (const int*)d_in[4];
    const int*   kpos  = (const int*)d_in[5];
    const float* Wq = (const float*)d_in[6];  const float* bq = (const float*)d_in[7];
    const float* Wk = (const float*)d_in[8];  const float* bk = (const float*)d_in[9];
    const float* Wv = (const float*)d_in[10]; const float* bv = (const float*)d_in[11];
    const float* Wo = (const float*)d_in[12]; const float* bo = (const float*)d_in[13];
    const float* relk  = (const float*)d_in[14];
    const float* relv  = (const float*)d_in[15];
    const float* wpre  = (const float*)d_in[16];
    const float* wpost = (const float*)d_in[17];
    float* out = (float*)d_out;

    float *Q, *Kc, *V, *qbar, *Rbar, *Sc, *Ap, *Y, *ctx, *ropeT;
    cudaGetSymbolAddress((void**)&Q,     g_Q);
    cudaGetSymbolAddress((void**)&Kc,    g_K);
    cudaGetSymbolAddress((void**)&V,     g_V);
    cudaGetSymbolAddress((void**)&qbar,  g_qbar);
    cudaGetSymbolAddress((void**)&Rbar,  g_Rbar);
    cudaGetSymbolAddress((void**)&Sc,    g_S);
    cudaGetSymbolAddress((void**)&Ap,    g_Ap);
    cudaGetSymbolAddress((void**)&Y,     g_Y);
    cudaGetSymbolAddress((void**)&ctx,   g_ctx);
    cudaGetSymbolAddress((void**)&ropeT, g_ropeT);

    dim3 blk(256);
    const long S2 = (long)SS * SS;          // 1048576
    const long SD = (long)SS * DM;          // 1048576

    // RoPE table (independent of projections; launch first)
    rope_table_kernel<<<256, 256>>>(ropeT);

    // Projections: [2048,1024] = X @ W^T + b  (M tiles of 128, N tiles of 64)
    gemm_kernel<true><<<dim3(16, 16, 1), blk>>>(query, Wq, Q, 2048, 1024, 1024,
        1024, 1024, 1024, 0, 0, 0, 0, 0, 0, 1, bq, nullptr, 0, 0, 0);
    gemm_kernel<true><<<dim3(16, 16, 1), blk>>>(key_, Wk, Kc, 2048, 1024, 1024,
        1024, 1024, 1024, 0, 0, 0, 0, 0, 0, 1, bk, nullptr, 0, 0, 0);
    gemm_kernel<true><<<dim3(16, 16, 1), blk>>>(value, Wv, V, 2048, 1024, 1024,
        1024, 1024, 1024, 0, 0, 0, 0, 0, 0, 1, bv, nullptr, 0, 0, 0);

    // RoPE on Q and K
    rope_kernel<<<4096, 256>>>(Q, qpos, ropeT);
    rope_kernel<<<4096, 256>>>(Kc, kpos, ropeT);

    // qbar = w_pre-mixed q; Rbar = qbar @ relk^T
    qbar_kernel<<<8192, 256>>>(Q, wpre, qbar);
    gemm_kernel<true><<<dim3(5, 256, 1), blk>>>(qbar, relk, Rbar, 32768, NREL, 64,
        64, 64, NREL, 0, 0, 0, 0, 0, 0, 1, nullptr, nullptr, 0, 0, 0);

    // Per-head QK^T (batch = 32 over (b, n))
    gemm_kernel<true><<<dim3(16, 8, 32), blk>>>(Q, Kc, Sc, 1024, 1024, 64,
        1024, 1024, 1024,
        64L, SD, 64L, SD, S2, 16L * S2,
        16, nullptr, nullptr, 0, 0, 0);

    // Fused mix + softmax + post-mix + A'
    cudaFuncSetAttribute(mix_softmax_kernel,
                         cudaFuncAttributeMaxDynamicSharedMemorySize, MIX_SMEM);
    mix_softmax_kernel<<<dim3(1024, 2), 512, MIX_SMEM>>>(Sc, Rbar, wpre, wpost, Ap);

    // Y = A' @ relv
    gemm_kernel<false><<<dim3(1, 256, 1), blk>>>(Ap, relv, Y, 32768, 64, NREL,
        NREL, 64, 64, 0, 0, 0, 0, 0, 0, 1, nullptr, nullptr, 0, 0, 0);

    // ctx = attn @ v + Y   (batch = 32 over (b, n)); ctx layout [B,S,H*D]
    gemm_kernel<false><<<dim3(1, 8, 32), blk>>>(Sc, V, ctx, 1024, 64, 1024,
        1024, 1024, 1024,
        S2, 16L * S2, 64L, SD, 64L, SD,
        16, nullptr,
        Y, 64, 65536L, 16L * 65536L);

    // out = ctx @ Wo^T + bo
    gemm_kernel<true><<<dim3(16, 16, 1), blk>>>(ctx, Wo, out, 2048, 1024, 1024,
        1024, 1024, 1024, 0, 0, 0, 0, 0, 0, 1, bo, nullptr, 0, 0, 0);
}

// round 4
// speedup vs baseline: 1.5643x; 1.0776x over previous
#include <cuda_runtime.h>
#include <cuda_bf16.h>
#include <mma.h>
#include <math.h>

using namespace nvcuda;

// Problem constants
#define BB 2
#define SS 1024
#define HH 16
#define DD 64
#define DM 1024
#define NREL 257

// Scratch (device globals)
__device__ float g_Q[BB*SS*DM];
__device__ float g_K[BB*SS*DM];
__device__ float g_V[BB*SS*DM];
__device__ float g_qbar[BB*HH*SS*DD];
__device__ float g_Rbar[BB*HH*SS*NREL];
__device__ float g_S[BB*HH*SS*SS];
__device__ float g_Ap[BB*HH*SS*NREL];
__device__ float g_Y[BB*HH*SS*DD];
__device__ float g_ctx[BB*SS*DM];
__device__ float g_ropeT[2048*64];

// ---------------------------------------------------------------------------
// bf16 split-precision wmma GEMM (3 MMA passes ~ fp32 accuracy).
// CTA tile 128 x TN, 256 threads (8 warps: 4 row-slabs x 2 col-slabs), K=32 step.
// ---------------------------------------------------------------------------
#define LDA_BF 48

template<bool TRANSB, int TN>
__global__ void __launch_bounds__(256)
gemm_bf16_kernel(const float* __restrict__ A, const float* __restrict__ Bm,
                 float* __restrict__ C,
                 int M, int N, int K, int lda, int ldb, int ldc,
                 const float* __restrict__ bias)
{
    constexpr int JF = TN / 32;
    constexpr int LDB_BF = TN + 16;
    constexpr int LDST = TN + 4;
    constexpr int SM_MAIN = (128*LDA_BF*2 + 32*LDB_BF*2) * 2;
    constexpr int SM_ST = 64 * LDST * 4;
    constexpr int SMB = SM_MAIN > SM_ST ? SM_MAIN : SM_ST;

    __shared__ __align__(16) unsigned char smbuf[SMB];
    __nv_bfloat16* Ahi = (__nv_bfloat16*)smbuf;
    __nv_bfloat16* Alo = Ahi + 128 * LDA_BF;
    __nv_bfloat16* Bhi = Alo + 128 * LDA_BF;
    __nv_bfloat16* Blo = Bhi + 32 * LDB_BF;
    float* stage = (float*)smbuf;

    int tid = threadIdx.x;
    int wid = tid >> 5;
    int wm = wid >> 1;
    int wn = wid & 1;
    int m0 = blockIdx.y * 128, n0 = blockIdx.x * TN;

    wmma::fragment<wmma::accumulator, 16, 16, 16, float> acc[2][JF];
    #pragma unroll
    for (int i = 0; i < 2; i++)
        #pragma unroll
        for (int j = 0; j < JF; j++) wmma::fill_fragment(acc[i][j], 0.0f);

    for (int kt = 0; kt < K; kt += 32) {
        #pragma unroll
        for (int e = 0; e < 128 * 32; e += 256) {
            int idx = e + tid;
            int r = idx >> 5, kk = idx & 31;
            int gm = m0 + r, gk = kt + kk;
            float v = (gm < M && gk < K) ? A[(long)gm * lda + gk] : 0.f;
            __nv_bfloat16 h = __float2bfloat16(v);
            Ahi[r * LDA_BF + kk] = h;
            Alo[r * LDA_BF + kk] = __float2bfloat16(v - __bfloat162float(h));
        }
        #pragma unroll
        for (int e = 0; e < TN * 32; e += 256) {
            int idx = e + tid;
            int n, kk;
            float v;
            if (TRANSB) {
                n = idx >> 5; kk = idx & 31;
                int gn = n0 + n, gk = kt + kk;
                v = (gn < N && gk < K) ? Bm[(long)gn * ldb + gk] : 0.f;
            } else {
                kk = idx / TN; n = idx - kk * TN;
                int gk = kt + kk, gn = n0 + n;
                v = (gk < K && gn < N) ? Bm[(long)gk * ldb + gn] : 0.f;
            }
            __nv_bfloat16 h = __float2bfloat16(v);
            Bhi[kk * LDB_BF + n] = h;
            Blo[kk * LDB_BF + n] = __float2bfloat16(v - __bfloat162float(h));
        }
        __syncthreads();

        #pragma unroll
        for (int kk = 0; kk < 32; kk += 16) {
            wmma::fragment<wmma::matrix_a, 16, 16, 16, __nv_bfloat16, wmma::row_major> ah[2], al[2];
            #pragma unroll
            for (int i = 0; i < 2; i++) {
                wmma::load_matrix_sync(ah[i], &Ahi[(wm * 32 + i * 16) * LDA_BF + kk], LDA_BF);
                wmma::load_matrix_sync(al[i], &Alo[(wm * 32 + i * 16) * LDA_BF + kk], LDA_BF);
            }
            #pragma unroll
            for (int j = 0; j < JF; j++) {
                wmma::fragment<wmma::matrix_b, 16, 16, 16, __nv_bfloat16, wmma::row_major> bh, bl;
                wmma::load_matrix_sync(bh, &Bhi[kk * LDB_BF + wn * (TN / 2) + j * 16], LDB_BF);
                wmma::load_matrix_sync(bl, &Blo[kk * LDB_BF + wn * (TN / 2) + j * 16], LDB_BF);
                #pragma unroll
                for (int i = 0; i < 2; i++) {
                    wmma::mma_sync(acc[i][j], ah[i], bh, acc[i][j]);
                    wmma::mma_sync(acc[i][j], ah[i], bl, acc[i][j]);
                    wmma::mma_sync(acc[i][j], al[i], bh, acc[i][j]);
                }
            }
        }
        __syncthreads();
    }

    #pragma unroll
    for (int step = 0; step < 2; step++) {
        if ((wm >> 1) == step) {
            #pragma unroll
            for (int i = 0; i < 2; i++)
                #pragma unroll
                for (int j = 0; j < JF; j++)
                    wmma::store_matrix_sync(&stage[((wm & 1) * 32 + i * 16) * LDST + wn * (TN / 2) + j * 16],
                                            acc[i][j], LDST, wmma::mem_row_major);
        }
        __syncthreads();
        #pragma unroll
        for (int e = 0; e < 64 * TN; e += 256) {
            int idx = e + tid;
            int r = idx / TN, c = idx - r * TN;
            int gm = m0 + step * 64 + r, gn = n0 + c;
            if (gm < M && gn < N) {
                float v = stage[r * LDST + c];
                if (bias) v += bias[gn];
                C[(long)gm * ldc + gn] = v;
            }
        }
        __syncthreads();
    }
}

// ---------------------------------------------------------------------------
// tf32 GEMM via PTX mma.sync.aligned.m16n8k8.row.col.f32.tf32.tf32.f32.
// CTA tile 128 x TN, 256 threads (8 warps: 4x2), K-step 32.
// Per warp: 32 rows x TN/2 cols -> 2 x (TN/16) fragments of 16x8.
// ---------------------------------------------------------------------------
__device__ __forceinline__ unsigned f2tf32(float v) {
    unsigned u;
    asm("cvt.rna.tf32.f32 %0, %1;" : "=r"(u) : "f"(v));
    return u;
}

__device__ __forceinline__ void mma_tf32(float c[4],
                                         unsigned a0, unsigned a1, unsigned a2, unsigned a3,
                                         unsigned b0, unsigned b1) {
    asm volatile("mma.sync.aligned.m16n8k8.row.col.f32.tf32.tf32.f32 "
                 "{%0,%1,%2,%3}, {%4,%5,%6,%7}, {%8,%9}, {%0,%1,%2,%3};"
                 : "+f"(c[0]), "+f"(c[1]), "+f"(c[2]), "+f"(c[3])
                 : "r"(a0), "r"(a1), "r"(a2), "r"(a3), "r"(b0), "r"(b1));
}

template<bool TRANSB, int TN>
__global__ void __launch_bounds__(256)
gemm_tf32_kernel(const float* __restrict__ A, const float* __restrict__ Bm,
                 float* __restrict__ C,
                 int M, int N, int K, int lda, int ldb, int ldc,
                 long sAin, long sAout, long sBin, long sBout, long sCin, long sCout,
                 int bInner,
                 const float* __restrict__ bias,
                 const float* __restrict__ addend, int ldadd, long sAddIn, long sAddOut)
{
    constexpr int LDA = 36;                 // words
    constexpr int LDB = TN + 8;
    constexpr int LDST = TN + 4;
    constexpr int NJ = TN / 16;             // 8-col fragments per warp
    constexpr int SM_MAIN = (128*LDA + 32*LDB) * 4;
    constexpr int SM_ST = 64 * LDST * 4;
    constexpr int SMB = SM_MAIN > SM_ST ? SM_MAIN : SM_ST;

    __shared__ __align__(16) unsigned char smbuf[SMB];
    unsigned* Af = (unsigned*)smbuf;        // [128][LDA]
    unsigned* Bf = Af + 128 * LDA;          // [32][LDB]
    float* stage = (float*)smbuf;

    int z = blockIdx.z;
    int zo = z / bInner, zi = z - zo * bInner;
    A  += zo * sAout + zi * sAin;
    Bm += zo * sBout + zi * sBin;
    C  += zo * sCout + zi * sCin;
    if (addend) addend += zo * sAddOut + zi * sAddIn;

    int tid = threadIdx.x;
    int wid = tid >> 5, lane = tid & 31;
    int wm = wid >> 1;                      // rows wm*32
    int wn = wid & 1;                       // cols wn*(TN/2)
    int g = lane >> 2, t = lane & 3;
    int m0 = blockIdx.y * 128, n0 = blockIdx.x * TN;

    float acc[2][NJ][4];
    #pragma unroll
    for (int i = 0; i < 2; i++)
        #pragma unroll
        for (int j = 0; j < NJ; j++)
            #pragma unroll
            for (int e = 0; e < 4; e++) acc[i][j][e] = 0.f;

    for (int kt = 0; kt < K; kt += 32) {
        // A tile [128][32]
        #pragma unroll
        for (int e = 0; e < 128 * 32; e += 256) {
            int idx = e + tid;
            int r = idx >> 5, kk = idx & 31;
            int gm = m0 + r, gk = kt + kk;
            float v = (gm < M && gk < K) ? A[(long)gm * lda + gk] : 0.f;
            Af[r * LDA + kk] = f2tf32(v);
        }
        // B tile [32][TN] (as k x n)
        #pragma unroll
        for (int e = 0; e < TN * 32; e += 256) {
            int idx = e + tid;
            int n, kk;
            float v;
            if (TRANSB) {
                n = idx >> 5; kk = idx & 31;
                int gn = n0 + n, gk = kt + kk;
                v = (gn < N && gk < K) ? Bm[(long)gn * ldb + gk] : 0.f;
            } else {
                kk = idx / TN; n = idx - kk * TN;
                int gk = kt + kk, gn = n0 + n;
                v = (gk < K && gn < N) ? Bm[(long)gk * ldb + gn] : 0.f;
            }
            Bf[kk * LDB + n] = f2tf32(v);
        }
        __syncthreads();

        #pragma unroll
        for (int ks = 0; ks < 32; ks += 8) {
            unsigned a[2][4];
            #pragma unroll
            for (int i = 0; i < 2; i++) {
                int rb = wm * 32 + i * 16;
                a[i][0] = Af[(rb + g    ) * LDA + ks + t    ];
                a[i][1] = Af[(rb + g + 8) * LDA + ks + t    ];
                a[i][2] = Af[(rb + g    ) * LDA + ks + t + 4];
                a[i][3] = Af[(rb + g + 8) * LDA + ks + t + 4];
            }
            #pragma unroll
            for (int j = 0; j < NJ; j++) {
                int nb = wn * (TN / 2) + j * 8;
                unsigned b0 = Bf[(ks + t    ) * LDB + nb + g];
                unsigned b1 = Bf[(ks + t + 4) * LDB + nb + g];
                #pragma unroll
                for (int i = 0; i < 2; i++)
                    mma_tf32(acc[i][j], a[i][0], a[i][1], a[i][2], a[i][3], b0, b1);
            }
        }
        __syncthreads();
    }

    // Epilogue: two 64-row windows via smem stage
    #pragma unroll
    for (int step = 0; step < 2; step++) {
        if ((wm >> 1) == step) {
            int rbase = (wm & 1) * 32;
            #pragma unroll
            for (int i = 0; i < 2; i++)
                #pragma unroll
                for (int j = 0; j < NJ; j++) {
                    int r0 = rbase + i * 16 + g;
                    int c0 = wn * (TN / 2) + j * 8 + 2 * t;
                    stage[ r0      * LDST + c0    ] = acc[i][j][0];
                    stage[ r0      * LDST + c0 + 1] = acc[i][j][1];
                    stage[(r0 + 8) * LDST + c0    ] = acc[i][j][2];
                    stage[(r0 + 8) * LDST + c0 + 1] = acc[i][j][3];
                }
        }
        __syncthreads();
        #pragma unroll
        for (int e = 0; e < 64 * TN; e += 256) {
            int idx = e + tid;
            int r = idx / TN, c = idx - r * TN;
            int gm = m0 + step * 64 + r, gn = n0 + c;
            if (gm < M && gn < N) {
                float v = stage[r * LDST + c];
                if (bias)   v += bias[gn];
                if (addend) v += addend[(long)gm * ldadd + gn];
                C[(long)gm * ldc + gn] = v;
            }
        }
        __syncthreads();
    }
}

// ---------------------------------------------------------------------------
// RoPE table + apply
// ---------------------------------------------------------------------------
__global__ void rope_table_kernel(float* __restrict__ T)
{
    int idx = blockIdx.x * blockDim.x + threadIdx.x;
    if (idx >= 2048 * 32) return;
    int i = idx & 31, pos = idx >> 5;
    double inv = exp(-(double)i / 32.0 * log(10000.0));
    double ds, dc;
    sincos((double)pos * inv, &ds, &dc);
    T[pos * 64 + i]      = (float)dc;
    T[pos * 64 + 32 + i] = (float)ds;
}

__global__ void rope_kernel(float* __restrict__ X, const int* __restrict__ pos_ids,
                            const float* __restrict__ T)
{
    int idx = blockIdx.x * blockDim.x + threadIdx.x;
    if (idx >= BB * SS * HH * 32) return;
    int i = idx & 31;
    int h = (idx >> 5) & 15;
    int s = (idx >> 9) & 1023;
    int b = idx >> 19;
    int pos = pos_ids[b * SS + s];
    float c  = T[pos * 64 + i];
    float sn = T[pos * 64 + 32 + i];
    float* p = X + ((size_t)(b * SS + s)) * DM + h * DD + i;
    float x1 = p[0], x2 = p[32];
    p[0]  = x1 * c - x2 * sn;
    p[32] = x2 * c + x1 * sn;
}

// ---------------------------------------------------------------------------
// qbar[b,m,s,d] = sum_n w_pre[n,m] * Q[b,s,n*64+d]
// ---------------------------------------------------------------------------
__global__ void qbar_kernel(const float* __restrict__ Q, const float* __restrict__ wpre,
                            float* __restrict__ qbar)
{
    int idx = blockIdx.x * blockDim.x + threadIdx.x;
    if (idx >= BB * HH * SS * DD) return;
    int d = idx & 63;
    int s = (idx >> 6) & 1023;
    int m = (idx >> 16) & 15;
    int b = idx >> 20;
    const float* qrow = Q + ((size_t)(b * SS + s)) * DM + d;
    float acc = 0.f;
    #pragma unroll
    for (int n = 0; n < 16; n++) acc += __ldg(&wpre[n * 16 + m]) * qrow[n * 64];
    qbar[idx] = acc;
}

// ---------------------------------------------------------------------------
// Fused: pre-mix + rel-K bias + /8 + mask + softmax + post-mix + A' extraction
// ---------------------------------------------------------------------------
#define MIX_SMEM ((16*1024 + 16*257 + 256 + 256 + 16 + 16) * 4)

__global__ void __launch_bounds__(512)
mix_softmax_kernel(float* __restrict__ S, const float* __restrict__ Rbar,
                   const float* __restrict__ wpre, const float* __restrict__ wpost,
                   float* __restrict__ Ap)
{
    extern __shared__ float shm[];
    float* sm     = shm;
    float* srb    = sm + 16 * 1024;
    float* swpre  = srb + 16 * 257;
    float* swpost = swpre + 256;
    float* sinv   = swpost + 256;
    float* stail  = sinv + 16;

    int q = blockIdx.x, b = blockIdx.y;
    int tid = threadIdx.x;
    int wid = tid >> 5, lane = tid & 31;

    if (tid < 256) { swpre[tid] = wpre[tid]; swpost[tid] = wpost[tid]; }
    #pragma unroll
    for (int n = 0; n < 16; n++) {
        const float* src = S + (((size_t)(b * 16 + n) * SS + q) * SS);
        for (int k = tid; k < SS; k += 512) sm[n * 1024 + k] = src[k];
    }
    for (int t = tid; t < 16 * NREL; t += 512) {
        int m = t / NREL, j = t - m * NREL;
        srb[t] = Rbar[((size_t)(b * 16 + m) * SS + q) * NREL + j];
    }
    __syncthreads();

    for (int k = tid; k < SS; k += 512) {
        float r[16];
        #pragma unroll
        for (int n = 0; n < 16; n++) r[n] = sm[n * 1024 + k];
        int d = q - k;
        int cl = d > 128 ? 128 : (d < -128 ? -128 : d);
        int idx = cl + 128;
        bool masked = (k > q);
        #pragma unroll
        for (int m = 0; m < 16; m++) {
            float accv = 0.f;
            #pragma unroll
            for (int n = 0; n < 16; n++) accv += swpre[n * 16 + m] * r[n];
            float v = (accv + srb[m * NREL + idx]) * 0.125f;
            sm[m * 1024 + k] = masked ? -1e30f : v;
        }
    }
    __syncthreads();

    {
        int m = wid;
        float mx = -1e30f;
        for (int k = lane; k <= q; k += 32) mx = fmaxf(mx, sm[m * 1024 + k]);
        #pragma unroll
        for (int o = 16; o; o >>= 1) mx = fmaxf(mx, __shfl_xor_sync(0xffffffffu, mx, o));
        float sum = 0.f;
        for (int k = lane; k <= q; k += 32) {
            float p = __expf(sm[m * 1024 + k] - mx);
            sm[m * 1024 + k] = p;
            sum += p;
        }
        #pragma unroll
        for (int o = 16; o; o >>= 1) sum += __shfl_xor_sync(0xffffffffu, sum, o);
        for (int k = q + 1 + lane; k < SS; k += 32) sm[m * 1024 + k] = 0.f;
        if (lane == 0) sinv[m] = 1.f / sum;
    }
    __syncthreads();

    float inv[16];
    #pragma unroll
    for (int m = 0; m < 16; m++) inv[m] = sinv[m];
    for (int k = tid; k < SS; k += 512) {
        float p[16];
        #pragma unroll
        for (int m = 0; m < 16; m++) p[m] = sm[m * 1024 + k] * inv[m];
        #pragma unroll
        for (int n = 0; n < 16; n++) {
            float accv = 0.f;
            #pragma unroll
            for (int m = 0; m < 16; m++) accv += p[m] * swpost[m * 16 + n];
            sm[n * 1024 + k] = accv;
        }
    }
    __syncthreads();

    #pragma unroll
    for (int n = 0; n < 16; n++) {
        float* dst = S + (((size_t)(b * 16 + n) * SS + q) * SS);
        for (int k = tid; k < SS; k += 512) dst[k] = sm[n * 1024 + k];
    }
    {
        int m = wid;
        float ts = 0.f;
        for (int k = lane; k <= q - 128; k += 32) ts += sm[m * 1024 + k];
        #pragma unroll
        for (int o = 16; o; o >>= 1) ts += __shfl_xor_sync(0xffffffffu, ts, o);
        if (lane == 0) stail[m] = ts;
    }
    __syncthreads();

    for (int t = tid; t < 16 * NREL; t += 512) {
        int n = t / NREL, j = t - n * NREL;
        float v = 0.f;
        if (j == 256) v = stail[n];
        else if (j >= 128) {
            int k = q - (j - 128);
            if (k >= 0) v = sm[n * 1024 + k];
        }
        Ap[((size_t)(b * 16 + n) * SS + q) * NREL + j] = v;
    }
}

// ---------------------------------------------------------------------------
// Launch sequence
// ---------------------------------------------------------------------------
extern "C" void kernel_launch(void* const* d_in, const int* in_sizes, int n_in,
                              void* d_out, int out_size)
{
    const float* query = (const float*)d_in[0];
    const float* key_  = (const float*)d_in[1];
    const float* value = (const float*)d_in[2];
    const int*   qpos  = (const int*)d_in[4];
    const int*   kpos  = (const int*)d_in[5];
    const float* Wq = (const float*)d_in[6];  const float* bq = (const float*)d_in[7];
    const float* Wk = (const float*)d_in[8];  const float* bk = (const float*)d_in[9];
    const float* Wv = (const float*)d_in[10]; const float* bv = (const float*)d_in[11];
    const float* Wo = (const float*)d_in[12]; const float* bo = (const float*)d_in[13];
    const float* relk  = (const float*)d_in[14];
    const float* relv  = (const float*)d_in[15];
    const float* wpre  = (const float*)d_in[16];
    const float* wpost = (const float*)d_in[17];
    float* out = (float*)d_out;

    float *Q, *Kc, *V, *qbar, *Rbar, *Sc, *Ap, *Y, *ctx, *ropeT;
    cudaGetSymbolAddress((void**)&Q,     g_Q);
    cudaGetSymbolAddress((void**)&Kc,    g_K);
    cudaGetSymbolAddress((void**)&V,     g_V);
    cudaGetSymbolAddress((void**)&qbar,  g_qbar);
    cudaGetSymbolAddress((void**)&Rbar,  g_Rbar);
    cudaGetSymbolAddress((void**)&Sc,    g_S);
    cudaGetSymbolAddress((void**)&Ap,    g_Ap);
    cudaGetSymbolAddress((void**)&Y,     g_Y);
    cudaGetSymbolAddress((void**)&ctx,   g_ctx);
    cudaGetSymbolAddress((void**)&ropeT, g_ropeT);

    dim3 blk(256);
    const long S2 = (long)SS * SS;
    const long SD = (long)SS * DM;

    rope_table_kernel<<<256, 256>>>(ropeT);

    // Projections (bf16 3-pass, 128x128 tile)
    gemm_bf16_kernel<true, 128><<<dim3(8, 16, 1), blk>>>(query, Wq, Q, 2048, 1024, 1024,
        1024, 1024, 1024, bq);
    gemm_bf16_kernel<true, 128><<<dim3(8, 16, 1), blk>>>(key_, Wk, Kc, 2048, 1024, 1024,
        1024, 1024, 1024, bk);
    gemm_bf16_kernel<true, 128><<<dim3(8, 16, 1), blk>>>(value, Wv, V, 2048, 1024, 1024,
        1024, 1024, 1024, bv);

    rope_kernel<<<4096, 256>>>(Q, qpos, ropeT);
    rope_kernel<<<4096, 256>>>(Kc, kpos, ropeT);

    qbar_kernel<<<8192, 256>>>(Q, wpre, qbar);
    // Rbar = qbar @ relk^T (tf32)
    gemm_tf32_kernel<true, 64><<<dim3(5, 256, 1), blk>>>(qbar, relk, Rbar, 32768, NREL, 64,
        64, 64, NREL, 0, 0, 0, 0, 0, 0, 1, nullptr, nullptr, 0, 0, 0);

    // QK^T per head (tf32), batch = 32 over (b, n)
    gemm_tf32_kernel<true, 128><<<dim3(8, 8, 32), blk>>>(Q, Kc, Sc, 1024, 1024, 64,
        1024, 1024, 1024,
        64L, SD, 64L, SD, S2, 16L * S2,
        16, nullptr, nullptr, 0, 0, 0);

    cudaFuncSetAttribute(mix_softmax_kernel,
                         cudaFuncAttributeMaxDynamicSharedMemorySize, MIX_SMEM);
    mix_softmax_kernel<<<dim3(1024, 2), 512, MIX_SMEM>>>(Sc, Rbar, wpre, wpost, Ap);

    // Y = A' @ relv (tf32)
    gemm_tf32_kernel<false, 64><<<dim3(1, 256, 1), blk>>>(Ap, relv, Y, 32768, 64, NREL,
        NREL, 64, 64, 0, 0, 0, 0, 0, 0, 1, nullptr, nullptr, 0, 0, 0);

    // ctx = attn @ v + Y (tf32), batch = 32
    gemm_tf32_kernel<false, 64><<<dim3(1, 8, 32), blk>>>(Sc, V, ctx, 1024, 64, 1024,
        1024, 1024, 1024,
        S2, 16L * S2, 64L, SD, 64L, SD,
        16, nullptr,
        Y, 64, 65536L, 16L * 65536L);

    // out = ctx @ Wo^T + bo (bf16 3-pass)
    gemm_bf16_kernel<true, 128><<<dim3(8, 16, 1), blk>>>(ctx, Wo, out, 2048, 1024, 1024,
        1024, 1024, 1024, bo);
}

// round 5
// speedup vs baseline: 2.1474x; 1.3727x over previous
#include <cuda_runtime.h>
#include <cuda_bf16.h>
#include <math.h>

// Problem constants
#define BB 2
#define SS 1024
#define HH 16
#define DD 64
#define DM 1024
#define NREL 257

// Scratch (device globals)
__device__ float g_Q[BB*SS*DM];
__device__ float g_K[BB*SS*DM];
__device__ float g_V[BB*SS*DM];
__device__ float g_qbar[BB*HH*SS*DD];
__device__ float g_Rbar[BB*HH*SS*NREL];
__device__ float g_S[BB*HH*SS*SS];
__device__ float g_Ap[BB*HH*SS*NREL];
__device__ float g_Y[BB*HH*SS*DD];
__device__ float g_ctx[BB*SS*DM];
__device__ float g_ropeT[2048*64];

// ---------------------------------------------------------------------------
// tf32 GEMM via PTX mma.sync.aligned.m16n8k8.row.col.f32.tf32.tf32.f32.
// CTA tile 128 x TN, 256 threads (8 warps: 4x2), K-step 32, double-buffered.
// ---------------------------------------------------------------------------
__device__ __forceinline__ unsigned f2tf32(float v) {
    unsigned u;
    asm("cvt.rna.tf32.f32 %0, %1;" : "=r"(u) : "f"(v));
    return u;
}

__device__ __forceinline__ void mma_tf32(float c[4],
                                         unsigned a0, unsigned a1, unsigned a2, unsigned a3,
                                         unsigned b0, unsigned b1) {
    asm volatile("mma.sync.aligned.m16n8k8.row.col.f32.tf32.tf32.f32 "
                 "{%0,%1,%2,%3}, {%4,%5,%6,%7}, {%8,%9}, {%0,%1,%2,%3};"
                 : "+f"(c[0]), "+f"(c[1]), "+f"(c[2]), "+f"(c[3])
                 : "r"(a0), "r"(a1), "r"(a2), "r"(a3), "r"(b0), "r"(b1));
}

template<int TN> struct GemmSmem {
    static constexpr int LDA = 36;
    static constexpr int LDB = TN + 8;
    static constexpr int LDST = TN + 4;
    static constexpr int ASZ = 128 * LDA;        // words
    static constexpr int BSZ = 32 * LDB;
    static constexpr int MAIN = 2 * (ASZ + BSZ) * 4;   // bytes
    static constexpr int ST = 64 * LDST * 4;
    static constexpr int BYTES = MAIN > ST ? MAIN : ST;
};

template<bool TRANSB, int TN>
__global__ void __launch_bounds__(256)
gemm_tf32_kernel(const float* __restrict__ A, const float* __restrict__ Bm,
                 float* __restrict__ C,
                 int M, int N, int K, int lda, int ldb, int ldc,
                 long sAin, long sAout, long sBin, long sBout, long sCin, long sCout,
                 int bInner,
                 const float* __restrict__ bias,
                 const float* __restrict__ addend, int ldadd, long sAddIn, long sAddOut)
{
    using SM = GemmSmem<TN>;
    constexpr int LDA = SM::LDA;
    constexpr int LDB = SM::LDB;
    constexpr int LDST = SM::LDST;
    constexpr int NJ = TN / 16;
    constexpr int APF = 128 * 32 / 256;   // 16 prefetch elems / thread
    constexpr int BPF = TN * 32 / 256;    // 16 or 8

    extern __shared__ __align__(16) unsigned char dynsm[];
    unsigned* base = (unsigned*)dynsm;
    float* stage = (float*)dynsm;

    int z = blockIdx.z;
    int zo = z / bInner, zi = z - zo * bInner;
    A  += zo * sAout + zi * sAin;
    Bm += zo * sBout + zi * sBin;
    C  += zo * sCout + zi * sCin;
    if (addend) addend += zo * sAddOut + zi * sAddIn;

    int tid = threadIdx.x;
    int wid = tid >> 5, lane = tid & 31;
    int wm = wid >> 1;                      // rows wm*32
    int wn = wid & 1;                       // cols wn*(TN/2)
    int g = lane >> 2, t = lane & 3;
    int m0 = blockIdx.y * 128, n0 = blockIdx.x * TN;

    // loader coords
    int ra = tid >> 5, ka = tid & 31;                       // A: row, k

    float acc[2][NJ][4];
    #pragma unroll
    for (int i = 0; i < 2; i++)
        #pragma unroll
        for (int j = 0; j < NJ; j++)
            #pragma unroll
            for (int e = 0; e < 4; e++) acc[i][j][e] = 0.f;

    float aPf[APF], bPf[BPF];

    // ---- fetch helpers (inlined manually via lambdas) ----
    auto fetchA = [&](int kt) {
        #pragma unroll
        for (int u = 0; u < APF; u++) {
            int r = ra + u * 8;             // 256 threads / 32 k = 8 rows per step
            int gm = m0 + r, gk = kt + ka;
            aPf[u] = (gm < M && gk < K) ? A[(long)gm * lda + gk] : 0.f;
        }
    };
    auto fetchB = [&](int kt) {
        #pragma unroll
        for (int u = 0; u < BPF; u++) {
            int idx = tid + u * 256;
            float v;
            if (TRANSB) {
                int n = idx >> 5, kk = idx & 31;
                int gn = n0 + n, gk = kt + kk;
                v = (gn < N && gk < K) ? Bm[(long)gn * ldb + gk] : 0.f;
            } else {
                int kk = idx / TN, n = idx - kk * TN;
                int gk = kt + kk, gn = n0 + n;
                v = (gk < K && gn < N) ? Bm[(long)gk * ldb + gn] : 0.f;
            }
            bPf[u] = v;
        }
    };
    auto storeBuf = [&](int buf) {
        unsigned* Af = base + buf * (SM::ASZ + SM::BSZ);
        unsigned* Bf = Af + SM::ASZ;
        #pragma unroll
        for (int u = 0; u < APF; u++) {
            int r = ra + u * 8;
            Af[r * LDA + ka] = f2tf32(aPf[u]);
        }
        #pragma unroll
        for (int u = 0; u < BPF; u++) {
            int idx = tid + u * 256;
            int n, kk;
            if (TRANSB) { n = idx >> 5; kk = idx & 31; }
            else        { kk = idx / TN; n = idx - kk * TN; }
            Bf[kk * LDB + n] = f2tf32(bPf[u]);
        }
    };

    // prologue
    fetchA(0); fetchB(0);
    storeBuf(0);
    __syncthreads();

    int cur = 0;
    for (int kt = 0; kt < K; kt += 32) {
        bool hn = (kt + 32) < K;
        if (hn) { fetchA(kt + 32); fetchB(kt + 32); }

        unsigned* Af = base + cur * (SM::ASZ + SM::BSZ);
        unsigned* Bf = Af + SM::ASZ;
        #pragma unroll
        for (int ks = 0; ks < 32; ks += 8) {
            unsigned a[2][4];
            #pragma unroll
            for (int i = 0; i < 2; i++) {
                int rb = wm * 32 + i * 16;
                a[i][0] = Af[(rb + g    ) * LDA + ks + t    ];
                a[i][1] = Af[(rb + g + 8) * LDA + ks + t    ];
                a[i][2] = Af[(rb + g    ) * LDA + ks + t + 4];
                a[i][3] = Af[(rb + g + 8) * LDA + ks + t + 4];
            }
            #pragma unroll
            for (int j = 0; j < NJ; j++) {
                int nb = wn * (TN / 2) + j * 8;
                unsigned b0 = Bf[(ks + t    ) * LDB + nb + g];
                unsigned b1 = Bf[(ks + t + 4) * LDB + nb + g];
                #pragma unroll
                for (int i = 0; i < 2; i++)
                    mma_tf32(acc[i][j], a[i][0], a[i][1], a[i][2], a[i][3], b0, b1);
            }
        }

        if (hn) storeBuf(cur ^ 1);
        __syncthreads();
        cur ^= 1;
    }

    // Epilogue: two 64-row windows via smem stage
    #pragma unroll
    for (int step = 0; step < 2; step++) {
        if ((wm >> 1) == step) {
            int rbase = (wm & 1) * 32;
            #pragma unroll
            for (int i = 0; i < 2; i++)
                #pragma unroll
                for (int j = 0; j < NJ; j++) {
                    int r0 = rbase + i * 16 + g;
                    int c0 = wn * (TN / 2) + j * 8 + 2 * t;
                    stage[ r0      * LDST + c0    ] = acc[i][j][0];
                    stage[ r0      * LDST + c0 + 1] = acc[i][j][1];
                    stage[(r0 + 8) * LDST + c0    ] = acc[i][j][2];
                    stage[(r0 + 8) * LDST + c0 + 1] = acc[i][j][3];
                }
        }
        __syncthreads();
        #pragma unroll
        for (int e = 0; e < 64 * TN; e += 256) {
            int idx = e + tid;
            int r = idx / TN, c = idx - r * TN;
            int gm = m0 + step * 64 + r, gn = n0 + c;
            if (gm < M && gn < N) {
                float v = stage[r * LDST + c];
                if (bias)   v += bias[gn];
                if (addend) v += addend[(long)gm * ldadd + gn];
                C[(long)gm * ldc + gn] = v;
            }
        }
        __syncthreads();
    }
}

// ---------------------------------------------------------------------------
// RoPE table + apply
// ---------------------------------------------------------------------------
__global__ void rope_table_kernel(float* __restrict__ T)
{
    int idx = blockIdx.x * blockDim.x + threadIdx.x;
    if (idx >= 2048 * 32) return;
    int i = idx & 31, pos = idx >> 5;
    double inv = exp(-(double)i / 32.0 * log(10000.0));
    double ds, dc;
    sincos((double)pos * inv, &ds, &dc);
    T[pos * 64 + i]      = (float)dc;
    T[pos * 64 + 32 + i] = (float)ds;
}

__global__ void rope_kernel(float* __restrict__ X, const int* __restrict__ pos_ids,
                            const float* __restrict__ T)
{
    int idx = blockIdx.x * blockDim.x + threadIdx.x;
    if (idx >= BB * SS * HH * 32) return;
    int i = idx & 31;
    int h = (idx >> 5) & 15;
    int s = (idx >> 9) & 1023;
    int b = idx >> 19;
    int pos = pos_ids[b * SS + s];
    float c  = T[pos * 64 + i];
    float sn = T[pos * 64 + 32 + i];
    float* p = X + ((size_t)(b * SS + s)) * DM + h * DD + i;
    float x1 = p[0], x2 = p[32];
    p[0]  = x1 * c - x2 * sn;
    p[32] = x2 * c + x1 * sn;
}

// ---------------------------------------------------------------------------
// qbar[b,m,s,d] = sum_n w_pre[n,m] * Q[b,s,n*64+d]
// ---------------------------------------------------------------------------
__global__ void qbar_kernel(const float* __restrict__ Q, const float* __restrict__ wpre,
                            float* __restrict__ qbar)
{
    int idx = blockIdx.x * blockDim.x + threadIdx.x;
    if (idx >= BB * HH * SS * DD) return;
    int d = idx & 63;
    int s = (idx >> 6) & 1023;
    int m = (idx >> 16) & 15;
    int b = idx >> 20;
    const float* qrow = Q + ((size_t)(b * SS + s)) * DM + d;
    float acc = 0.f;
    #pragma unroll
    for (int n = 0; n < 16; n++) acc += __ldg(&wpre[n * 16 + m]) * qrow[n * 64];
    qbar[idx] = acc;
}

// ---------------------------------------------------------------------------
// Fused: pre-mix + rel-K bias + /8 + mask + softmax + post-mix + A' extraction
// ---------------------------------------------------------------------------
#define MIX_SMEM ((16*1024 + 16*257 + 256 + 256 + 16 + 16) * 4)

__global__ void __launch_bounds__(512)
mix_softmax_kernel(float* __restrict__ S, const float* __restrict__ Rbar,
                   const float* __restrict__ wpre, const float* __restrict__ wpost,
                   float* __restrict__ Ap)
{
    extern __shared__ float shm[];
    float* sm     = shm;
    float* srb    = sm + 16 * 1024;
    float* swpre  = srb + 16 * 257;
    float* swpost = swpre + 256;
    float* sinv   = swpost + 256;
    float* stail  = sinv + 16;

    int q = blockIdx.x, b = blockIdx.y;
    int tid = threadIdx.x;
    int wid = tid >> 5, lane = tid & 31;

    if (tid < 256) { swpre[tid] = wpre[tid]; swpost[tid] = wpost[tid]; }
    #pragma unroll
    for (int n = 0; n < 16; n++) {
        const float* src = S + (((size_t)(b * 16 + n) * SS + q) * SS);
        for (int k = tid; k < SS; k += 512) sm[n * 1024 + k] = src[k];
    }
    for (int t = tid; t < 16 * NREL; t += 512) {
        int m = t / NREL, j = t - m * NREL;
        srb[t] = Rbar[((size_t)(b * 16 + m) * SS + q) * NREL + j];
    }
    __syncthreads();

    for (int k = tid; k < SS; k += 512) {
        float r[16];
        #pragma unroll
        for (int n = 0; n < 16; n++) r[n] = sm[n * 1024 + k];
        int d = q - k;
        int cl = d > 128 ? 128 : (d < -128 ? -128 : d);
        int idx = cl + 128;
        bool masked = (k > q);
        #pragma unroll
        for (int m = 0; m < 16; m++) {
            float accv = 0.f;
            #pragma unroll
            for (int n = 0; n < 16; n++) accv += swpre[n * 16 + m] * r[n];
            float v = (accv + srb[m * NREL + idx]) * 0.125f;
            sm[m * 1024 + k] = masked ? -1e30f : v;
        }
    }
    __syncthreads();

    {
        int m = wid;
        float mx = -1e30f;
        for (int k = lane; k <= q; k += 32) mx = fmaxf(mx, sm[m * 1024 + k]);
        #pragma unroll
        for (int o = 16; o; o >>= 1) mx = fmaxf(mx, __shfl_xor_sync(0xffffffffu, mx, o));
        float sum = 0.f;
        for (int k = lane; k <= q; k += 32) {
            float p = __expf(sm[m * 1024 + k] - mx);
            sm[m * 1024 + k] = p;
            sum += p;
        }
        #pragma unroll
        for (int o = 16; o; o >>= 1) sum += __shfl_xor_sync(0xffffffffu, sum, o);
        for (int k = q + 1 + lane; k < SS; k += 32) sm[m * 1024 + k] = 0.f;
        if (lane == 0) sinv[m] = 1.f / sum;
    }
    __syncthreads();

    float inv[16];
    #pragma unroll
    for (int m = 0; m < 16; m++) inv[m] = sinv[m];
    for (int k = tid; k < SS; k += 512) {
        float p[16];
        #pragma unroll
        for (int m = 0; m < 16; m++) p[m] = sm[m * 1024 + k] * inv[m];
        #pragma unroll
        for (int n = 0; n < 16; n++) {
            float accv = 0.f;
            #pragma unroll
            for (int m = 0; m < 16; m++) accv += p[m] * swpost[m * 16 + n];
            sm[n * 1024 + k] = accv;
        }
    }
    __syncthreads();

    #pragma unroll
    for (int n = 0; n < 16; n++) {
        float* dst = S + (((size_t)(b * 16 + n) * SS + q) * SS);
        for (int k = tid; k < SS; k += 512) dst[k] = sm[n * 1024 + k];
    }
    {
        int m = wid;
        float ts = 0.f;
        for (int k = lane; k <= q - 128; k += 32) ts += sm[m * 1024 + k];
        #pragma unroll
        for (int o = 16; o; o >>= 1) ts += __shfl_xor_sync(0xffffffffu, ts, o);
        if (lane == 0) stail[m] = ts;
    }
    __syncthreads();

    for (int t = tid; t < 16 * NREL; t += 512) {
        int n = t / NREL, j = t - n * NREL;
        float v = 0.f;
        if (j == 256) v = stail[n];
        else if (j >= 128) {
            int k = q - (j - 128);
            if (k >= 0) v = sm[n * 1024 + k];
        }
        Ap[((size_t)(b * 16 + n) * SS + q) * NREL + j] = v;
    }
}

// ---------------------------------------------------------------------------
// Launch sequence
// ---------------------------------------------------------------------------
extern "C" void kernel_launch(void* const* d_in, const int* in_sizes, int n_in,
                              void* d_out, int out_size)
{
    const float* query = (const float*)d_in[0];
    const float* key_  = (const float*)d_in[1];
    const float* value = (const float*)d_in[2];
    const int*   qpos  = (const int*)d_in[4];
    const int*   kpos  = (const int*)d_in[5];
    const float* Wq = (const float*)d_in[6];  const float* bq = (const float*)d_in[7];
    const float* Wk = (const float*)d_in[8];  const float* bk = (const float*)d_in[9];
    const float* Wv = (const float*)d_in[10]; const float* bv = (const float*)d_in[11];
    const float* Wo = (const float*)d_in[12]; const float* bo = (const float*)d_in[13];
    const float* relk  = (const float*)d_in[14];
    const float* relv  = (const float*)d_in[15];
    const float* wpre  = (const float*)d_in[16];
    const float* wpost = (const float*)d_in[17];
    float* out = (float*)d_out;

    float *Q, *Kc, *V, *qbar, *Rbar, *Sc, *Ap, *Y, *ctx, *ropeT;
    cudaGetSymbolAddress((void**)&Q,     g_Q);
    cudaGetSymbolAddress((void**)&Kc,    g_K);
    cudaGetSymbolAddress((void**)&V,     g_V);
    cudaGetSymbolAddress((void**)&qbar,  g_qbar);
    cudaGetSymbolAddress((void**)&Rbar,  g_Rbar);
    cudaGetSymbolAddress((void**)&Sc,    g_S);
    cudaGetSymbolAddress((void**)&Ap,    g_Ap);
    cudaGetSymbolAddress((void**)&Y,     g_Y);
    cudaGetSymbolAddress((void**)&ctx,   g_ctx);
    cudaGetSymbolAddress((void**)&ropeT, g_ropeT);

    dim3 blk(256);
    const long S2 = (long)SS * SS;
    const long SD = (long)SS * DM;

    const int SM128 = GemmSmem<128>::BYTES;
    const int SM64  = GemmSmem<64>::BYTES;
    cudaFuncSetAttribute(gemm_tf32_kernel<true, 128>,
                         cudaFuncAttributeMaxDynamicSharedMemorySize, SM128);
    cudaFuncSetAttribute(gemm_tf32_kernel<true, 64>,
                         cudaFuncAttributeMaxDynamicSharedMemorySize, SM64);
    cudaFuncSetAttribute(gemm_tf32_kernel<false, 64>,
                         cudaFuncAttributeMaxDynamicSharedMemorySize, SM64);

    rope_table_kernel<<<256, 256>>>(ropeT);

    // Projections (tf32 single-pass): [2048,1024] = X @ W^T + b
    gemm_tf32_kernel<true, 128><<<dim3(8, 16, 1), blk, SM128>>>(query, Wq, Q, 2048, 1024, 1024,
        1024, 1024, 1024, 0, 0, 0, 0, 0, 0, 1, bq, nullptr, 0, 0, 0);
    gemm_tf32_kernel<true, 128><<<dim3(8, 16, 1), blk, SM128>>>(key_, Wk, Kc, 2048, 1024, 1024,
        1024, 1024, 1024, 0, 0, 0, 0, 0, 0, 1, bk, nullptr, 0, 0, 0);
    gemm_tf32_kernel<true, 128><<<dim3(8, 16, 1), blk, SM128>>>(value, Wv, V, 2048, 1024, 1024,
        1024, 1024, 1024, 0, 0, 0, 0, 0, 0, 1, bv, nullptr, 0, 0, 0);

    rope_kernel<<<4096, 256>>>(Q, qpos, ropeT);
    rope_kernel<<<4096, 256>>>(Kc, kpos, ropeT);

    qbar_kernel<<<8192, 256>>>(Q, wpre, qbar);
    // Rbar = qbar @ relk^T (tf32)
    gemm_tf32_kernel<true, 64><<<dim3(5, 256, 1), blk, SM64>>>(qbar, relk, Rbar, 32768, NREL, 64,
        64, 64, NREL, 0, 0, 0, 0, 0, 0, 1, nullptr, nullptr, 0, 0, 0);

    // QK^T per head (tf32), batch = 32 over (b, n)
    gemm_tf32_kernel<true, 128><<<dim3(8, 8, 32), blk, SM128>>>(Q, Kc, Sc, 1024, 1024, 64,
        1024, 1024, 1024,
        64L, SD, 64L, SD, S2, 16L * S2,
        16, nullptr, nullptr, 0, 0, 0);

    cudaFuncSetAttribute(mix_softmax_kernel,
                         cudaFuncAttributeMaxDynamicSharedMemorySize, MIX_SMEM);
    mix_softmax_kernel<<<dim3(1024, 2), 512, MIX_SMEM>>>(Sc, Rbar, wpre, wpost, Ap);

    // Y = A' @ relv (tf32)
    gemm_tf32_kernel<false, 64><<<dim3(1, 256, 1), blk, SM64>>>(Ap, relv, Y, 32768, 64, NREL,
        NREL, 64, 64, 0, 0, 0, 0, 0, 0, 1, nullptr, nullptr, 0, 0, 0);

    // ctx = attn @ v + Y (tf32), batch = 32
    gemm_tf32_kernel<false, 64><<<dim3(1, 8, 32), blk, SM64>>>(Sc, V, ctx, 1024, 64, 1024,
        1024, 1024, 1024,
        S2, 16L * S2, 64L, SD, 64L, SD,
        16, nullptr,
        Y, 64, 65536L, 16L * 65536L);

    // out = ctx @ Wo^T + bo (tf32)
    gemm_tf32_kernel<true, 128><<<dim3(8, 16, 1), blk, SM128>>>(ctx, Wo, out, 2048, 1024, 1024,
        1024, 1024, 1024, 0, 0, 0, 0, 0, 0, 1, bo, nullptr, 0, 0, 0);
}

// round 6
// speedup vs baseline: 2.8102x; 1.3087x over previous
#include <cuda_runtime.h>
#include <cuda_bf16.h>
#include <math.h>

// Problem constants
#define BB 2
#define SS 1024
#define HH 16
#define DD 64
#define DM 1024
#define NREL 257

// Scratch (device globals)
__device__ float g_Q[BB*SS*DM];
__device__ float g_K[BB*SS*DM];
__device__ float g_V[BB*SS*DM];
__device__ float g_qbar[BB*HH*SS*DD];
__device__ float g_Rbar[BB*HH*SS*NREL];
__device__ float g_S[BB*HH*SS*SS];
__device__ float g_Ap[BB*HH*SS*NREL];
__device__ float g_Y[BB*HH*SS*DD];
__device__ float g_ctx[BB*SS*DM];
__device__ float g_ropeT[2048*64];

// ---------------------------------------------------------------------------
// tf32 GEMM via PTX mma.sync.aligned.m16n8k8 (row.col, f32 accum).
// CTA tile 128x64, 256 threads (8 warps: 4 row-slabs x 2 col-slabs of 32),
// K-step 32, double-buffered, 2 CTAs/SM.
// causalMode: 0=none, 1=skip tiles with n0 >= m0+128 (QK^T), 2=K limited
// to m0+128 (AV: attention rows are zero beyond the diagonal).
// ---------------------------------------------------------------------------
__device__ __forceinline__ unsigned f2tf32(float v) {
    unsigned u;
    asm("cvt.rna.tf32.f32 %0, %1;" : "=r"(u) : "f"(v));
    return u;
}

__device__ __forceinline__ void mma_tf32(float c[4],
                                         unsigned a0, unsigned a1, unsigned a2, unsigned a3,
                                         unsigned b0, unsigned b1) {
    asm volatile("mma.sync.aligned.m16n8k8.row.col.f32.tf32.tf32.f32 "
                 "{%0,%1,%2,%3}, {%4,%5,%6,%7}, {%8,%9}, {%0,%1,%2,%3};"
                 : "+f"(c[0]), "+f"(c[1]), "+f"(c[2]), "+f"(c[3])
                 : "r"(a0), "r"(a1), "r"(a2), "r"(a3), "r"(b0), "r"(b1));
}

#define G_LDA 36
#define G_LDB 72
#define G_LDST 68
#define G_ASZ (128*G_LDA)
#define G_BSZ (32*G_LDB)
#define G_BUF (G_ASZ + G_BSZ)
#define G_SMEM_BYTES (2 * G_BUF * 4)       // 55296 > stage (64*68*4=17408)

template<bool TRANSB, bool GUARD>
__global__ void __launch_bounds__(256, 2)
gemm_tf32_kernel(const float* __restrict__ A, const float* __restrict__ Bm,
                 float* __restrict__ C,
                 int M, int N, int K, int lda, int ldb, int ldc,
                 long sAin, long sAout, long sBin, long sBout, long sCin, long sCout,
                 int bInner,
                 const float* __restrict__ bias,
                 const float* __restrict__ addend, int ldadd, long sAddIn, long sAddOut,
                 int causalMode)
{
    constexpr int APF = 16;   // A prefetch elems/thread (128*32/256)
    constexpr int BPF = 8;    // B prefetch elems/thread (64*32/256)

    extern __shared__ __align__(16) unsigned char dynsm[];
    unsigned* base = (unsigned*)dynsm;
    float* stage = (float*)dynsm;

    int m0 = blockIdx.y * 128, n0 = blockIdx.x * 64;
    if (causalMode == 1 && n0 >= m0 + 128) return;   // fully-masked QK tile
    int Keff = K;
    if (causalMode == 2) { int kl = m0 + 128; Keff = kl < K ? kl : K; }

    int z = blockIdx.z;
    int zo = z / bInner, zi = z - zo * bInner;
    A  += zo * sAout + zi * sAin;
    Bm += zo * sBout + zi * sBin;
    C  += zo * sCout + zi * sCin;
    if (addend) addend += zo * sAddOut + zi * sAddIn;

    int tid = threadIdx.x;
    int wid = tid >> 5, lane = tid & 31;
    int wm = wid >> 1;                   // rows wm*32
    int wn = wid & 1;                    // cols wn*32
    int g = lane >> 2, t = lane & 3;
    int ra = tid >> 5, ka = tid & 31;    // A loader coords

    float acc[2][4][4];
    #pragma unroll
    for (int i = 0; i < 2; i++)
        #pragma unroll
        for (int j = 0; j < 4; j++)
            #pragma unroll
            for (int e = 0; e < 4; e++) acc[i][j][e] = 0.f;

    float aPf[APF], bPf[BPF];

    auto fetchA = [&](int kt) {
        #pragma unroll
        for (int u = 0; u < APF; u++) {
            int r = ra + u * 8;
            int gm = m0 + r, gk = kt + ka;
            if (GUARD)
                aPf[u] = (gm < M && gk < K) ? A[(long)gm * lda + gk] : 0.f;
            else
                aPf[u] = A[(long)gm * lda + gk];
        }
    };
    auto fetchB = [&](int kt) {
        #pragma unroll
        for (int u = 0; u < BPF; u++) {
            int idx = tid + u * 256;
            if (TRANSB) {
                int n = idx >> 5, kk = idx & 31;
                int gn = n0 + n, gk = kt + kk;
                if (GUARD)
                    bPf[u] = (gn < N && gk < K) ? Bm[(long)gn * ldb + gk] : 0.f;
                else
                    bPf[u] = Bm[(long)gn * ldb + gk];
            } else {
                int kk = idx >> 6, n = idx & 63;
                int gk = kt + kk, gn = n0 + n;
                if (GUARD)
                    bPf[u] = (gk < K && gn < N) ? Bm[(long)gk * ldb + gn] : 0.f;
                else
                    bPf[u] = Bm[(long)gk * ldb + gn];
            }
        }
    };
    auto storeBuf = [&](int buf) {
        unsigned* Af = base + buf * G_BUF;
        unsigned* Bf = Af + G_ASZ;
        #pragma unroll
        for (int u = 0; u < APF; u++)
            Af[(ra + u * 8) * G_LDA + ka] = f2tf32(aPf[u]);
        #pragma unroll
        for (int u = 0; u < BPF; u++) {
            int idx = tid + u * 256;
            int n, kk;
            if (TRANSB) { n = idx >> 5; kk = idx & 31; }
            else        { kk = idx >> 6; n = idx & 63; }
            Bf[kk * G_LDB + n] = f2tf32(bPf[u]);
        }
    };

    fetchA(0); fetchB(0);
    storeBuf(0);
    __syncthreads();

    int cur = 0;
    for (int kt = 0; kt < Keff; kt += 32) {
        bool hn = (kt + 32) < Keff;
        if (hn) { fetchA(kt + 32); fetchB(kt + 32); }

        unsigned* Af = base + cur * G_BUF;
        unsigned* Bf = Af + G_ASZ;
        #pragma unroll
        for (int ks = 0; ks < 32; ks += 8) {
            unsigned a[2][4];
            #pragma unroll
            for (int i = 0; i < 2; i++) {
                int rb = wm * 32 + i * 16;
                a[i][0] = Af[(rb + g    ) * G_LDA + ks + t    ];
                a[i][1] = Af[(rb + g + 8) * G_LDA + ks + t    ];
                a[i][2] = Af[(rb + g    ) * G_LDA + ks + t + 4];
                a[i][3] = Af[(rb + g + 8) * G_LDA + ks + t + 4];
            }
            #pragma unroll
            for (int j = 0; j < 4; j++) {
                int nb = wn * 32 + j * 8;
                unsigned b0 = Bf[(ks + t    ) * G_LDB + nb + g];
                unsigned b1 = Bf[(ks + t + 4) * G_LDB + nb + g];
                #pragma unroll
                for (int i = 0; i < 2; i++)
                    mma_tf32(acc[i][j], a[i][0], a[i][1], a[i][2], a[i][3], b0, b1);
            }
        }

        if (hn) storeBuf(cur ^ 1);
        __syncthreads();
        cur ^= 1;
    }

    // Epilogue: two 64-row windows via smem stage
    #pragma unroll
    for (int step = 0; step < 2; step++) {
        if ((wm >> 1) == step) {
            int rbase = (wm & 1) * 32;
            #pragma unroll
            for (int i = 0; i < 2; i++)
                #pragma unroll
                for (int j = 0; j < 4; j++) {
                    int r0 = rbase + i * 16 + g;
                    int c0 = wn * 32 + j * 8 + 2 * t;
                    stage[ r0      * G_LDST + c0    ] = acc[i][j][0];
                    stage[ r0      * G_LDST + c0 + 1] = acc[i][j][1];
                    stage[(r0 + 8) * G_LDST + c0    ] = acc[i][j][2];
                    stage[(r0 + 8) * G_LDST + c0 + 1] = acc[i][j][3];
                }
        }
        __syncthreads();
        if (GUARD) {
            #pragma unroll
            for (int u = 0; u < 16; u++) {
                int idx = tid + u * 256;
                int r = idx >> 6, c = idx & 63;
                int gm = m0 + step * 64 + r, gn = n0 + c;
                if (gm < M && gn < N) {
                    float v = stage[r * G_LDST + c];
                    if (bias)   v += bias[gn];
                    if (addend) v += addend[(long)gm * ldadd + gn];
                    C[(long)gm * ldc + gn] = v;
                }
            }
        } else {
            #pragma unroll
            for (int u = 0; u < 4; u++) {
                int idx = tid + u * 256;
                int r = idx >> 4, c4 = idx & 15;
                int gm = m0 + step * 64 + r;
                float4 v = *(const float4*)(stage + r * G_LDST + c4 * 4);
                if (bias) {
                    float4 bv = *(const float4*)(bias + n0 + c4 * 4);
                    v.x += bv.x; v.y += bv.y; v.z += bv.z; v.w += bv.w;
                }
                if (addend) {
                    float4 av = *(const float4*)(addend + (long)gm * ldadd + n0 + c4 * 4);
                    v.x += av.x; v.y += av.y; v.z += av.z; v.w += av.w;
                }
                *(float4*)(C + (long)gm * ldc + n0 + c4 * 4) = v;
            }
        }
        __syncthreads();
    }
}

// ---------------------------------------------------------------------------
// RoPE table + apply
// ---------------------------------------------------------------------------
__global__ void rope_table_kernel(float* __restrict__ T)
{
    int idx = blockIdx.x * blockDim.x + threadIdx.x;
    if (idx >= 2048 * 32) return;
    int i = idx & 31, pos = idx >> 5;
    double inv = exp(-(double)i / 32.0 * log(10000.0));
    double ds, dc;
    sincos((double)pos * inv, &ds, &dc);
    T[pos * 64 + i]      = (float)dc;
    T[pos * 64 + 32 + i] = (float)ds;
}

__global__ void rope_kernel(float* __restrict__ X, const int* __restrict__ pos_ids,
                            const float* __restrict__ T)
{
    int idx = blockIdx.x * blockDim.x + threadIdx.x;
    if (idx >= BB * SS * HH * 32) return;
    int i = idx & 31;
    int h = (idx >> 5) & 15;
    int s = (idx >> 9) & 1023;
    int b = idx >> 19;
    int pos = pos_ids[b * SS + s];
    float c  = T[pos * 64 + i];
    float sn = T[pos * 64 + 32 + i];
    float* p = X + ((size_t)(b * SS + s)) * DM + h * DD + i;
    float x1 = p[0], x2 = p[32];
    p[0]  = x1 * c - x2 * sn;
    p[32] = x2 * c + x1 * sn;
}

// ---------------------------------------------------------------------------
// qbar[b,m,s,d] = sum_n w_pre[n,m] * Q[b,s,n*64+d]
// ---------------------------------------------------------------------------
__global__ void qbar_kernel(const float* __restrict__ Q, const float* __restrict__ wpre,
                            float* __restrict__ qbar)
{
    int idx = blockIdx.x * blockDim.x + threadIdx.x;
    if (idx >= BB * HH * SS * DD) return;
    int d = idx & 63;
    int s = (idx >> 6) & 1023;
    int m = (idx >> 16) & 15;
    int b = idx >> 20;
    const float* qrow = Q + ((size_t)(b * SS + s)) * DM + d;
    float acc = 0.f;
    #pragma unroll
    for (int n = 0; n < 16; n++) acc += __ldg(&wpre[n * 16 + m]) * qrow[n * 64];
    qbar[idx] = acc;
}

// ---------------------------------------------------------------------------
// Fused: pre-mix + rel-K bias + /8 + mask + softmax + post-mix + A' extraction
// Causal-aware: phases 1 and 3 only touch k <= q.
// ---------------------------------------------------------------------------
#define MIX_SMEM ((16*1024 + 16*257 + 256 + 256 + 16 + 16) * 4)

__global__ void __launch_bounds__(512)
mix_softmax_kernel(float* __restrict__ S, const float* __restrict__ Rbar,
                   const float* __restrict__ wpre, const float* __restrict__ wpost,
                   float* __restrict__ Ap)
{
    extern __shared__ float shm[];
    float* sm     = shm;
    float* srb    = sm + 16 * 1024;
    float* swpre  = srb + 16 * 257;
    float* swpost = swpre + 256;
    float* sinv   = swpost + 256;
    float* stail  = sinv + 16;

    int q = blockIdx.x, b = blockIdx.y;
    int tid = threadIdx.x;
    int wid = tid >> 5, lane = tid & 31;

    if (tid < 256) { swpre[tid] = wpre[tid]; swpost[tid] = wpost[tid]; }
    // Vectorized load of all 16 score rows (full rows; k>q region unused)
    {
        const long rowBase = ((long)(b * 16) * SS + q) * SS;
        for (int tt = tid; tt < 16 * 256; tt += 512) {
            int n = tt >> 8, k4 = tt & 255;
            ((float4*)sm)[n * 256 + k4] =
                *(const float4*)(S + rowBase + (long)n * SS * SS + k4 * 4);
        }
    }
    for (int tt = tid; tt < 16 * NREL; tt += 512) {
        int m = tt / NREL, j = tt - m * NREL;
        srb[tt] = Rbar[((size_t)(b * 16 + m) * SS + q) * NREL + j];
    }
    __syncthreads();

    // Phase 1: pre-mix + rel bias + scale (only k <= q)
    for (int k = tid; k <= q; k += 512) {
        float r[16];
        #pragma unroll
        for (int n = 0; n < 16; n++) r[n] = sm[n * 1024 + k];
        int d = q - k;                       // >= 0 here
        int cl = d > 128 ? 128 : d;
        int idx = cl + 128;
        #pragma unroll
        for (int m = 0; m < 16; m++) {
            float accv = 0.f;
            #pragma unroll
            for (int n = 0; n < 16; n++) accv += swpre[n * 16 + m] * r[n];
            sm[m * 1024 + k] = (accv + srb[m * NREL + idx]) * 0.125f;
        }
    }
    __syncthreads();

    // Phase 2: softmax (warp per head) over k <= q; zero-fill k > q
    {
        int m = wid;
        float mx = -1e30f;
        for (int k = lane; k <= q; k += 32) mx = fmaxf(mx, sm[m * 1024 + k]);
        #pragma unroll
        for (int o = 16; o; o >>= 1) mx = fmaxf(mx, __shfl_xor_sync(0xffffffffu, mx, o));
        float sum = 0.f;
        for (int k = lane; k <= q; k += 32) {
            float p = __expf(sm[m * 1024 + k] - mx);
            sm[m * 1024 + k] = p;
            sum += p;
        }
        #pragma unroll
        for (int o = 16; o; o >>= 1) sum += __shfl_xor_sync(0xffffffffu, sum, o);
        for (int k = q + 1 + lane; k < SS; k += 32) sm[m * 1024 + k] = 0.f;
        if (lane == 0) sinv[m] = 1.f / sum;
    }
    __syncthreads();

    // Phase 3: post-mix (only k <= q; rest already zero)
    float inv[16];
    #pragma unroll
    for (int m = 0; m < 16; m++) inv[m] = sinv[m];
    for (int k = tid; k <= q; k += 512) {
        float p[16];
        #pragma unroll
        for (int m = 0; m < 16; m++) p[m] = sm[m * 1024 + k] * inv[m];
        #pragma unroll
        for (int n = 0; n < 16; n++) {
            float accv = 0.f;
            #pragma unroll
            for (int m = 0; m < 16; m++) accv += p[m] * swpost[m * 16 + n];
            sm[n * 1024 + k] = accv;
        }
    }
    __syncthreads();

    // Vectorized writeback of attention
    {
        const long rowBase = ((long)(b * 16) * SS + q) * SS;
        for (int tt = tid; tt < 16 * 256; tt += 512) {
            int n = tt >> 8, k4 = tt & 255;
            *(float4*)(S + rowBase + (long)n * SS * SS + k4 * 4) =
                ((float4*)sm)[n * 256 + k4];
        }
    }
    // Tail sums
    {
        int m = wid;
        float ts = 0.f;
        for (int k = lane; k <= q - 128; k += 32) ts += sm[m * 1024 + k];
        #pragma unroll
        for (int o = 16; o; o >>= 1) ts += __shfl_xor_sync(0xffffffffu, ts, o);
        if (lane == 0) stail[m] = ts;
    }
    __syncthreads();

    // A'[b,n,q,j]
    for (int tt = tid; tt < 16 * NREL; tt += 512) {
        int n = tt / NREL, j = tt - n * NREL;
        float v = 0.f;
        if (j == 256) v = stail[n];
        else if (j >= 128) {
            int k = q - (j - 128);
            if (k >= 0) v = sm[n * 1024 + k];
        }
        Ap[((size_t)(b * 16 + n) * SS + q) * NREL + j] = v;
    }
}

// ---------------------------------------------------------------------------
// Launch sequence
// ---------------------------------------------------------------------------
extern "C" void kernel_launch(void* const* d_in, const int* in_sizes, int n_in,
                              void* d_out, int out_size)
{
    const float* query = (const float*)d_in[0];
    const float* key_  = (const float*)d_in[1];
    const float* value = (const float*)d_in[2];
    const int*   qpos  = (const int*)d_in[4];
    const int*   kpos  = (const int*)d_in[5];
    const float* Wq = (const float*)d_in[6];  const float* bq = (const float*)d_in[7];
    const float* Wk = (const float*)d_in[8];  const float* bk = (const float*)d_in[9];
    const float* Wv = (const float*)d_in[10]; const float* bv = (const float*)d_in[11];
    const float* Wo = (const float*)d_in[12]; const float* bo = (const float*)d_in[13];
    const float* relk  = (const float*)d_in[14];
    const float* relv  = (const float*)d_in[15];
    const float* wpre  = (const float*)d_in[16];
    const float* wpost = (const float*)d_in[17];
    float* out = (float*)d_out;

    float *Q, *Kc, *V, *qbar, *Rbar, *Sc, *Ap, *Y, *ctx, *ropeT;
    cudaGetSymbolAddress((void**)&Q,     g_Q);
    cudaGetSymbolAddress((void**)&Kc,    g_K);
    cudaGetSymbolAddress((void**)&V,     g_V);
    cudaGetSymbolAddress((void**)&qbar,  g_qbar);
    cudaGetSymbolAddress((void**)&Rbar,  g_Rbar);
    cudaGetSymbolAddress((void**)&Sc,    g_S);
    cudaGetSymbolAddress((void**)&Ap,    g_Ap);
    cudaGetSymbolAddress((void**)&Y,     g_Y);
    cudaGetSymbolAddress((void**)&ctx,   g_ctx);
    cudaGetSymbolAddress((void**)&ropeT, g_ropeT);

    dim3 blk(256);
    const long S2 = (long)SS * SS;
    const long SD = (long)SS * DM;
    const int GS = G_SMEM_BYTES;

    cudaFuncSetAttribute(gemm_tf32_kernel<true,  false>,
                         cudaFuncAttributeMaxDynamicSharedMemorySize, GS);
    cudaFuncSetAttribute(gemm_tf32_kernel<true,  true>,
                         cudaFuncAttributeMaxDynamicSharedMemorySize, GS);
    cudaFuncSetAttribute(gemm_tf32_kernel<false, false>,
                         cudaFuncAttributeMaxDynamicSharedMemorySize, GS);
    cudaFuncSetAttribute(gemm_tf32_kernel<false, true>,
                         cudaFuncAttributeMaxDynamicSharedMemorySize, GS);

    rope_table_kernel<<<256, 256>>>(ropeT);

    // Projections: [2048,1024] = X @ W^T + b
    gemm_tf32_kernel<true, false><<<dim3(16, 16, 1), blk, GS>>>(query, Wq, Q, 2048, 1024, 1024,
        1024, 1024, 1024, 0, 0, 0, 0, 0, 0, 1, bq, nullptr, 0, 0, 0, 0);
    gemm_tf32_kernel<true, false><<<dim3(16, 16, 1), blk, GS>>>(key_, Wk, Kc, 2048, 1024, 1024,
        1024, 1024, 1024, 0, 0, 0, 0, 0, 0, 1, bk, nullptr, 0, 0, 0, 0);
    gemm_tf32_kernel<true, false><<<dim3(16, 16, 1), blk, GS>>>(value, Wv, V, 2048, 1024, 1024,
        1024, 1024, 1024, 0, 0, 0, 0, 0, 0, 1, bv, nullptr, 0, 0, 0, 0);

    rope_kernel<<<4096, 256>>>(Q, qpos, ropeT);
    rope_kernel<<<4096, 256>>>(Kc, kpos, ropeT);

    qbar_kernel<<<8192, 256>>>(Q, wpre, qbar);
    // Rbar = qbar @ relk^T  (N=257 -> guarded)
    gemm_tf32_kernel<true, true><<<dim3(5, 256, 1), blk, GS>>>(qbar, relk, Rbar, 32768, NREL, 64,
        64, 64, NREL, 0, 0, 0, 0, 0, 0, 1, nullptr, nullptr, 0, 0, 0, 0);

    // QK^T per head, causal tile-skip, batch = 32 over (b, n)
    gemm_tf32_kernel<true, false><<<dim3(16, 8, 32), blk, GS>>>(Q, Kc, Sc, 1024, 1024, 64,
        1024, 1024, 1024,
        64L, SD, 64L, SD, S2, 16L * S2,
        16, nullptr, nullptr, 0, 0, 0, 1);

    cudaFuncSetAttribute(mix_softmax_kernel,
                         cudaFuncAttributeMaxDynamicSharedMemorySize, MIX_SMEM);
    mix_softmax_kernel<<<dim3(1024, 2), 512, MIX_SMEM>>>(Sc, Rbar, wpre, wpost, Ap);

    // Y = A' @ relv  (K=257 -> guarded)
    gemm_tf32_kernel<false, true><<<dim3(1, 256, 1), blk, GS>>>(Ap, relv, Y, 32768, 64, NREL,
        NREL, 64, 64, 0, 0, 0, 0, 0, 0, 1, nullptr, nullptr, 0, 0, 0, 0);

    // ctx = attn @ v + Y, causal K-limit, batch = 32
    gemm_tf32_kernel<false, false><<<dim3(1, 8, 32), blk, GS>>>(Sc, V, ctx, 1024, 64, 1024,
        1024, 1024, 1024,
        S2, 16L * S2, 64L, SD, 64L, SD,
        16, nullptr,
        Y, 64, 65536L, 16L * 65536L, 2);

    // out = ctx @ Wo^T + bo
    gemm_tf32_kernel<true, false><<<dim3(16, 16, 1), blk, GS>>>(ctx, Wo, out, 2048, 1024, 1024,
        1024, 1024, 1024, 0, 0, 0, 0, 0, 0, 1, bo, nullptr, 0, 0, 0, 0);
}

// round 7
// speedup vs baseline: 2.9951x; 1.0658x over previous
#include <cuda_runtime.h>
#include <cuda_bf16.h>
#include <math.h>

// Problem constants
#define BB 2
#define SS 1024
#define HH 16
#define DD 64
#define DM 1024
#define NREL 257

// Scratch (device globals)
__device__ float g_Q[BB*SS*DM];
__device__ float g_K[BB*SS*DM];
__device__ float g_V[BB*SS*DM];
__device__ float g_qbar[BB*HH*SS*DD];
__device__ float g_Rbar[BB*HH*SS*NREL];
__device__ float g_S[BB*HH*SS*SS];
__device__ float g_Ap[BB*HH*SS*NREL];
__device__ float g_Y[BB*HH*SS*DD];
__device__ float g_ctx[BB*SS*DM];
__device__ float g_ropeT[2048*64];

// ---------------------------------------------------------------------------
// tf32 GEMM, PTX m16n8k8, fragment-order smem staging.
// CTA tile 128x64, 256 threads (8 warps: 4 row-slabs x 2 col-slabs of 32),
// K-step 32, double-buffered, 2 CTAs/SM.
//
// Smem layout (words):
//   A frags: [block16(8)][ks8(4)][lane(32)][word(4)]  = 4096 words
//     lane = (rowInBlk&7)*4 + (k&3); word = (rowInBlk>=8) + 2*(k&7>=4)
//   B frags: [nb8(8)][ks8(4)][lane(32)][word(2)]      = 2048 words
//     lane = (n&7)*4 + (k&3); word = (k&7>=4)
// Mainloop: A fragment = one LDS.128, B fragment = one LDS.64.
//
// causalMode: 0=none, 1=skip tiles n0>=m0+128 (QK^T), 2=Keff=m0+128 (AV).
// ropeTab/posIds: fused RoPE in epilogue (GUARD=false path only).
// ---------------------------------------------------------------------------
__device__ __forceinline__ unsigned f2tf32(float v) {
    unsigned u;
    asm("cvt.rna.tf32.f32 %0, %1;" : "=r"(u) : "f"(v));
    return u;
}

__device__ __forceinline__ void mma_tf32(float c[4],
                                         unsigned a0, unsigned a1, unsigned a2, unsigned a3,
                                         unsigned b0, unsigned b1) {
    asm volatile("mma.sync.aligned.m16n8k8.row.col.f32.tf32.tf32.f32 "
                 "{%0,%1,%2,%3}, {%4,%5,%6,%7}, {%8,%9}, {%0,%1,%2,%3};"
                 : "+f"(c[0]), "+f"(c[1]), "+f"(c[2]), "+f"(c[3])
                 : "r"(a0), "r"(a1), "r"(a2), "r"(a3), "r"(b0), "r"(b1));
}

#define G_AWORDS 4096
#define G_BWORDS 2048
#define G_BUF (G_AWORDS + G_BWORDS)
#define G_LDST 68
#define G_SMEM_BYTES (2 * G_BUF * 4)       // 49152; stage (64*68*4=17408) fits

template<bool TRANSB, bool GUARD>
__global__ void __launch_bounds__(256, 2)
gemm_tf32_kernel(const float* __restrict__ A, const float* __restrict__ Bm,
                 float* __restrict__ C,
                 int M, int N, int K, int lda, int ldb, int ldc,
                 long sAin, long sAout, long sBin, long sBout, long sCin, long sCout,
                 int bInner,
                 const float* __restrict__ bias,
                 const float* __restrict__ addend, int ldadd,
                 long sAddIn, long sAddOut,
                 int causalMode,
                 const float* __restrict__ ropeTab, const int* __restrict__ posIds)
{
    extern __shared__ __align__(16) unsigned char dynsm[];
    unsigned* base = (unsigned*)dynsm;
    float* stage = (float*)dynsm;

    int m0 = blockIdx.y * 128, n0 = blockIdx.x * 64;
    if (causalMode == 1 && n0 >= m0 + 128) return;
    int Keff = K;
    if (causalMode == 2) { int kl = m0 + 128; Keff = kl < K ? kl : K; }

    int z = blockIdx.z;
    int zo = z / bInner, zi = z - zo * bInner;
    A  += zo * sAout + zi * sAin;
    Bm += zo * sBout + zi * sBin;
    C  += zo * sCout + zi * sCin;
    if (addend) addend += zo * sAddOut + zi * sAddIn;

    int tid = threadIdx.x;
    int wid = tid >> 5, lane = tid & 31;
    int wm = wid >> 1;                   // rows wm*32
    int wn = wid & 1;                    // cols wn*32
    int g = lane >> 2, t = lane & 3;
    int ra = tid >> 5, ka = tid & 31;    // A loader: row=ra+8u, k=ka

    float acc[2][4][4];
    #pragma unroll
    for (int i = 0; i < 2; i++)
        #pragma unroll
        for (int j = 0; j < 4; j++)
            #pragma unroll
            for (int e = 0; e < 4; e++) acc[i][j][e] = 0.f;

    float aPf[16], bPf[8];

    auto fetchA = [&](int kt) {
        #pragma unroll
        for (int u = 0; u < 16; u++) {
            int r = ra + u * 8;
            int gm = m0 + r, gk = kt + ka;
            if (GUARD)
                aPf[u] = (gm < M && gk < K) ? A[(long)gm * lda + gk] : 0.f;
            else
                aPf[u] = A[(long)gm * lda + gk];
        }
    };
    auto fetchB = [&](int kt) {
        #pragma unroll
        for (int u = 0; u < 8; u++) {
            int idx = tid + u * 256;
            if (TRANSB) {
                int n = idx >> 5, kk = idx & 31;
                int gn = n0 + n, gk = kt + kk;
                if (GUARD)
                    bPf[u] = (gn < N && gk < K) ? Bm[(long)gn * ldb + gk] : 0.f;
                else
                    bPf[u] = Bm[(long)gn * ldb + gk];
            } else {
                int kk = idx >> 6, n = idx & 63;
                int gk = kt + kk, gn = n0 + n;
                if (GUARD)
                    bPf[u] = (gk < K && gn < N) ? Bm[(long)gk * ldb + gn] : 0.f;
                else
                    bPf[u] = Bm[(long)gk * ldb + gn];
            }
        }
    };
    auto storeBuf = [&](int buf) {
        unsigned* Af = base + buf * G_BUF;
        unsigned* Bf = Af + G_AWORDS;
        #pragma unroll
        for (int u = 0; u < 16; u++) {
            int r = ra + u * 8, kk = ka;
            int blk = r >> 4, rr = r & 15;
            int ks8 = kk >> 3, kt7 = kk & 7;
            int dl = ((rr & 7) << 2) | (kt7 & 3);
            int w  = ((rr >> 3) & 1) | ((kt7 >> 2) << 1);
            Af[(((blk << 2) + ks8) << 7) + (dl << 2) + w] = f2tf32(aPf[u]);
        }
        #pragma unroll
        for (int u = 0; u < 8; u++) {
            int idx = tid + u * 256;
            int n, kk;
            if (TRANSB) { n = idx >> 5; kk = idx & 31; }
            else        { kk = idx >> 6; n = idx & 63; }
            int nb8 = n >> 3, gg = n & 7;
            int ks8 = kk >> 3, kt7 = kk & 7;
            int dl = (gg << 2) | (kt7 & 3);
            int w  = (kt7 >> 2) & 1;
            Bf[(((nb8 << 2) + ks8) << 6) + (dl << 1) + w] = f2tf32(bPf[u]);
        }
    };

    fetchA(0); fetchB(0);
    storeBuf(0);
    __syncthreads();

    int cur = 0;
    for (int kt = 0; kt < Keff; kt += 32) {
        bool hn = (kt + 32) < Keff;
        if (hn) { fetchA(kt + 32); fetchB(kt + 32); }

        unsigned* Af = base + cur * G_BUF;
        unsigned* Bf = Af + G_AWORDS;
        #pragma unroll
        for (int ks8 = 0; ks8 < 4; ks8++) {
            uint4 av[2];
            #pragma unroll
            for (int i = 0; i < 2; i++) {
                int blk = wm * 2 + i;
                av[i] = *(const uint4*)&Af[(((blk << 2) + ks8) << 7) + (lane << 2)];
            }
            #pragma unroll
            for (int j = 0; j < 4; j++) {
                int nb8 = wn * 4 + j;
                uint2 bv = *(const uint2*)&Bf[(((nb8 << 2) + ks8) << 6) + (lane << 1)];
                #pragma unroll
                for (int i = 0; i < 2; i++)
                    mma_tf32(acc[i][j], av[i].x, av[i].y, av[i].z, av[i].w, bv.x, bv.y);
            }
        }

        if (hn) storeBuf(cur ^ 1);
        __syncthreads();
        cur ^= 1;
    }

    // Epilogue: two 64-row windows via smem stage
    #pragma unroll
    for (int step = 0; step < 2; step++) {
        if ((wm >> 1) == step) {
            int rbase = (wm & 1) * 32;
            #pragma unroll
            for (int i = 0; i < 2; i++)
                #pragma unroll
                for (int j = 0; j < 4; j++) {
                    int r0 = rbase + i * 16 + g;
                    int c0 = wn * 32 + j * 8 + 2 * t;
                    stage[ r0      * G_LDST + c0    ] = acc[i][j][0];
                    stage[ r0      * G_LDST + c0 + 1] = acc[i][j][1];
                    stage[(r0 + 8) * G_LDST + c0    ] = acc[i][j][2];
                    stage[(r0 + 8) * G_LDST + c0 + 1] = acc[i][j][3];
                }
        }
        __syncthreads();
        if (GUARD) {
            #pragma unroll
            for (int u = 0; u < 16; u++) {
                int idx = tid + u * 256;
                int r = idx >> 6, c = idx & 63;
                int gm = m0 + step * 64 + r, gn = n0 + c;
                if (gm < M && gn < N) {
                    float v = stage[r * G_LDST + c];
                    if (bias)   v += bias[gn];
                    if (addend) v += addend[(long)gm * ldadd + gn];
                    C[(long)gm * ldc + gn] = v;
                }
            }
        } else {
            #pragma unroll
            for (int u = 0; u < 4; u++) {
                int idx = tid + u * 256;
                int r = idx >> 4, c4 = idx & 15;
                int c = c4 * 4;
                int gm = m0 + step * 64 + r;
                float4 v = *(const float4*)(stage + r * G_LDST + c);
                if (bias) {
                    float4 bv = *(const float4*)(bias + n0 + c);
                    v.x += bv.x; v.y += bv.y; v.z += bv.z; v.w += bv.w;
                }
                if (ropeTab) {
                    // partner columns (c ^ 32), with their bias applied
                    float4 w = *(const float4*)(stage + r * G_LDST + (c ^ 32));
                    if (bias) {
                        float4 bw = *(const float4*)(bias + n0 + (c ^ 32));
                        w.x += bw.x; w.y += bw.y; w.z += bw.z; w.w += bw.w;
                    }
                    int b = gm >> 10, s = gm & 1023;
                    int pos = posIds[(b << 10) + s];
                    int i0 = c & 31;
                    float4 co = *(const float4*)(ropeTab + pos * 64 + i0);
                    float4 si = *(const float4*)(ropeTab + pos * 64 + 32 + i0);
                    if (c < 32) {
                        v.x = v.x * co.x - w.x * si.x;
                        v.y = v.y * co.y - w.y * si.y;
                        v.z = v.z * co.z - w.z * si.z;
                        v.w = v.w * co.w - w.w * si.w;
                    } else {
                        v.x = v.x * co.x + w.x * si.x;
                        v.y = v.y * co.y + w.y * si.y;
                        v.z = v.z * co.z + w.z * si.z;
                        v.w = v.w * co.w + w.w * si.w;
                    }
                }
                if (addend) {
                    float4 av = *(const float4*)(addend + (long)gm * ldadd + n0 + c);
                    v.x += av.x; v.y += av.y; v.z += av.z; v.w += av.w;
                }
                *(float4*)(C + (long)gm * ldc + n0 + c) = v;
            }
        }
        __syncthreads();
    }
}

// ---------------------------------------------------------------------------
// RoPE table
// ---------------------------------------------------------------------------
__global__ void rope_table_kernel(float* __restrict__ T)
{
    int idx = blockIdx.x * blockDim.x + threadIdx.x;
    if (idx >= 2048 * 32) return;
    int i = idx & 31, pos = idx >> 5;
    double inv = exp(-(double)i / 32.0 * log(10000.0));
    double ds, dc;
    sincos((double)pos * inv, &ds, &dc);
    T[pos * 64 + i]      = (float)dc;
    T[pos * 64 + 32 + i] = (float)ds;
}

// ---------------------------------------------------------------------------
// qbar[b,m,s,d] = sum_n w_pre[n,m] * Q[b,s,n*64+d]
// ---------------------------------------------------------------------------
__global__ void qbar_kernel(const float* __restrict__ Q, const float* __restrict__ wpre,
                            float* __restrict__ qbar)
{
    int idx = blockIdx.x * blockDim.x + threadIdx.x;
    if (idx >= BB * HH * SS * DD) return;
    int d = idx & 63;
    int s = (idx >> 6) & 1023;
    int m = (idx >> 16) & 15;
    int b = idx >> 20;
    const float* qrow = Q + ((size_t)(b * SS + s)) * DM + d;
    float acc = 0.f;
    #pragma unroll
    for (int n = 0; n < 16; n++) acc += __ldg(&wpre[n * 16 + m]) * qrow[n * 64];
    qbar[idx] = acc;
}

// ---------------------------------------------------------------------------
// Fused: pre-mix + rel-K bias + /8 + mask + softmax + post-mix + A' extraction
// ---------------------------------------------------------------------------
#define MIX_SMEM ((16*1024 + 16*257 + 256 + 256 + 16 + 16) * 4)

__global__ void __launch_bounds__(512)
mix_softmax_kernel(float* __restrict__ S, const float* __restrict__ Rbar,
                   const float* __restrict__ wpre, const float* __restrict__ wpost,
                   float* __restrict__ Ap)
{
    extern __shared__ float shm[];
    float* sm     = shm;
    float* srb    = sm + 16 * 1024;
    float* swpre  = srb + 16 * 257;
    float* swpost = swpre + 256;
    float* sinv   = swpost + 256;
    float* stail  = sinv + 16;

    int q = blockIdx.x, b = blockIdx.y;
    int tid = threadIdx.x;
    int wid = tid >> 5, lane = tid & 31;

    if (tid < 256) { swpre[tid] = wpre[tid]; swpost[tid] = wpost[tid]; }
    {
        const long rowBase = ((long)(b * 16) * SS + q) * SS;
        for (int tt = tid; tt < 16 * 256; tt += 512) {
            int n = tt >> 8, k4 = tt & 255;
            ((float4*)sm)[n * 256 + k4] =
                *(const float4*)(S + rowBase + (long)n * SS * SS + k4 * 4);
        }
    }
    for (int tt = tid; tt < 16 * NREL; tt += 512) {
        int m = tt / NREL, j = tt - m * NREL;
        srb[tt] = Rbar[((size_t)(b * 16 + m) * SS + q) * NREL + j];
    }
    __syncthreads();

    for (int k = tid; k <= q; k += 512) {
        float r[16];
        #pragma unroll
        for (int n = 0; n < 16; n++) r[n] = sm[n * 1024 + k];
        int d = q - k;
        int cl = d > 128 ? 128 : d;
        int idx = cl + 128;
        #pragma unroll
        for (int m = 0; m < 16; m++) {
            float accv = 0.f;
            #pragma unroll
            for (int n = 0; n < 16; n++) accv += swpre[n * 16 + m] * r[n];
            sm[m * 1024 + k] = (accv + srb[m * NREL + idx]) * 0.125f;
        }
    }
    __syncthreads();

    {
        int m = wid;
        float mx = -1e30f;
        for (int k = lane; k <= q; k += 32) mx = fmaxf(mx, sm[m * 1024 + k]);
        #pragma unroll
        for (int o = 16; o; o >>= 1) mx = fmaxf(mx, __shfl_xor_sync(0xffffffffu, mx, o));
        float sum = 0.f;
        for (int k = lane; k <= q; k += 32) {
            float p = __expf(sm[m * 1024 + k] - mx);
            sm[m * 1024 + k] = p;
            sum += p;
        }
        #pragma unroll
        for (int o = 16; o; o >>= 1) sum += __shfl_xor_sync(0xffffffffu, sum, o);
        for (int k = q + 1 + lane; k < SS; k += 32) sm[m * 1024 + k] = 0.f;
        if (lane == 0) sinv[m] = 1.f / sum;
    }
    __syncthreads();

    float inv[16];
    #pragma unroll
    for (int m = 0; m < 16; m++) inv[m] = sinv[m];
    for (int k = tid; k <= q; k += 512) {
        float p[16];
        #pragma unroll
        for (int m = 0; m < 16; m++) p[m] = sm[m * 1024 + k] * inv[m];
        #pragma unroll
        for (int n = 0; n < 16; n++) {
            float accv = 0.f;
            #pragma unroll
            for (int m = 0; m < 16; m++) accv += p[m] * swpost[m * 16 + n];
            sm[n * 1024 + k] = accv;
        }
    }
    __syncthreads();

    {
        const long rowBase = ((long)(b * 16) * SS + q) * SS;
        for (int tt = tid; tt < 16 * 256; tt += 512) {
            int n = tt >> 8, k4 = tt & 255;
            *(float4*)(S + rowBase + (long)n * SS * SS + k4 * 4) =
                ((float4*)sm)[n * 256 + k4];
        }
    }
    {
        int m = wid;
        float ts = 0.f;
        for (int k = lane; k <= q - 128; k += 32) ts += sm[m * 1024 + k];
        #pragma unroll
        for (int o = 16; o; o >>= 1) ts += __shfl_xor_sync(0xffffffffu, ts, o);
        if (lane == 0) stail[m] = ts;
    }
    __syncthreads();

    for (int tt = tid; tt < 16 * NREL; tt += 512) {
        int n = tt / NREL, j = tt - n * NREL;
        float v = 0.f;
        if (j == 256) v = stail[n];
        else if (j >= 128) {
            int k = q - (j - 128);
            if (k >= 0) v = sm[n * 1024 + k];
        }
        Ap[((size_t)(b * 16 + n) * SS + q) * NREL + j] = v;
    }
}

// ---------------------------------------------------------------------------
// Launch sequence
// ---------------------------------------------------------------------------
extern "C" void kernel_launch(void* const* d_in, const int* in_sizes, int n_in,
                              void* d_out, int out_size)
{
    const float* query = (const float*)d_in[0];
    const float* key_  = (const float*)d_in[1];
    const float* value = (const float*)d_in[2];
    const int*   qpos  = (const int*)d_in[4];
    const int*   kpos  = (const int*)d_in[5];
    const float* Wq = (const float*)d_in[6];  const float* bq = (const float*)d_in[7];
    const float* Wk = (const float*)d_in[8];  const float* bk = (const float*)d_in[9];
    const float* Wv = (const float*)d_in[10]; const float* bv = (const float*)d_in[11];
    const float* Wo = (const float*)d_in[12]; const float* bo = (const float*)d_in[13];
    const float* relk  = (const float*)d_in[14];
    const float* relv  = (const float*)d_in[15];
    const float* wpre  = (const float*)d_in[16];
    const float* wpost = (const float*)d_in[17];
    float* out = (float*)d_out;

    float *Q, *Kc, *V, *qbar, *Rbar, *Sc, *Ap, *Y, *ctx, *ropeT;
    cudaGetSymbolAddress((void**)&Q,     g_Q);
    cudaGetSymbolAddress((void**)&Kc,    g_K);
    cudaGetSymbolAddress((void**)&V,     g_V);
    cudaGetSymbolAddress((void**)&qbar,  g_qbar);
    cudaGetSymbolAddress((void**)&Rbar,  g_Rbar);
    cudaGetSymbolAddress((void**)&Sc,    g_S);
    cudaGetSymbolAddress((void**)&Ap,    g_Ap);
    cudaGetSymbolAddress((void**)&Y,     g_Y);
    cudaGetSymbolAddress((void**)&ctx,   g_ctx);
    cudaGetSymbolAddress((void**)&ropeT, g_ropeT);

    dim3 blk(256);
    const long S2 = (long)SS * SS;
    const long SD = (long)SS * DM;
    const int GS = G_SMEM_BYTES;

    cudaFuncSetAttribute(gemm_tf32_kernel<true,  false>,
                         cudaFuncAttributeMaxDynamicSharedMemorySize, GS);
    cudaFuncSetAttribute(gemm_tf32_kernel<true,  true>,
                         cudaFuncAttributeMaxDynamicSharedMemorySize, GS);
    cudaFuncSetAttribute(gemm_tf32_kernel<false, false>,
                         cudaFuncAttributeMaxDynamicSharedMemorySize, GS);
    cudaFuncSetAttribute(gemm_tf32_kernel<false, true>,
                         cudaFuncAttributeMaxDynamicSharedMemorySize, GS);

    rope_table_kernel<<<256, 256>>>(ropeT);

    // Projections with fused RoPE (Q, K) and plain (V)
    gemm_tf32_kernel<true, false><<<dim3(16, 16, 1), blk, GS>>>(query, Wq, Q, 2048, 1024, 1024,
        1024, 1024, 1024, 0, 0, 0, 0, 0, 0, 1, bq, nullptr, 0, 0, 0, 0, ropeT, qpos);
    gemm_tf32_kernel<true, false><<<dim3(16, 16, 1), blk, GS>>>(key_, Wk, Kc, 2048, 1024, 1024,
        1024, 1024, 1024, 0, 0, 0, 0, 0, 0, 1, bk, nullptr, 0, 0, 0, 0, ropeT, kpos);
    gemm_tf32_kernel<true, false><<<dim3(16, 16, 1), blk, GS>>>(value, Wv, V, 2048, 1024, 1024,
        1024, 1024, 1024, 0, 0, 0, 0, 0, 0, 1, bv, nullptr, 0, 0, 0, 0, nullptr, nullptr);

    qbar_kernel<<<8192, 256>>>(Q, wpre, qbar);
    // Rbar = qbar @ relk^T  (N=257 -> guarded)
    gemm_tf32_kernel<true, true><<<dim3(5, 256, 1), blk, GS>>>(qbar, relk, Rbar, 32768, NREL, 64,
        64, 64, NREL, 0, 0, 0, 0, 0, 0, 1, nullptr, nullptr, 0, 0, 0, 0, nullptr, nullptr);

    // QK^T per head, causal tile-skip, batch = 32 over (b, n)
    gemm_tf32_kernel<true, false><<<dim3(16, 8, 32), blk, GS>>>(Q, Kc, Sc, 1024, 1024, 64,
        1024, 1024, 1024,
        64L, SD, 64L, SD, S2, 16L * S2,
        16, nullptr, nullptr, 0, 0, 0, 1, nullptr, nullptr);

    cudaFuncSetAttribute(mix_softmax_kernel,
                         cudaFuncAttributeMaxDynamicSharedMemorySize, MIX_SMEM);
    mix_softmax_kernel<<<dim3(1024, 2), 512, MIX_SMEM>>>(Sc, Rbar, wpre, wpost, Ap);

    // Y = A' @ relv  (K=257 -> guarded)
    gemm_tf32_kernel<false, true><<<dim3(1, 256, 1), blk, GS>>>(Ap, relv, Y, 32768, 64, NREL,
        NREL, 64, 64, 0, 0, 0, 0, 0, 0, 1, nullptr, nullptr, 0, 0, 0, 0, nullptr, nullptr);

    // ctx = attn @ v + Y, causal K-limit, batch = 32
    gemm_tf32_kernel<false, false><<<dim3(1, 8, 32), blk, GS>>>(Sc, V, ctx, 1024, 64, 1024,
        1024, 1024, 1024,
        S2, 16L * S2, 64L, SD, 64L, SD,
        16, nullptr,
        Y, 64, 65536L, 16L * 65536L, 2, nullptr, nullptr);

    // out = ctx @ Wo^T + bo
    gemm_tf32_kernel<true, false><<<dim3(16, 16, 1), blk, GS>>>(ctx, Wo, out, 2048, 1024, 1024,
        1024, 1024, 1024, 0, 0, 0, 0, 0, 0, 1, bo, nullptr, 0, 0, 0, 0, nullptr, nullptr);
}

// round 9
// speedup vs baseline: 3.1341x; 1.0464x over previous
#include <cuda_runtime.h>
#include <cuda_bf16.h>
#include <math.h>
#include <stdint.h>

// Problem constants
#define BB 2
#define SS 1024
#define HH 16
#define DD 64
#define DM 1024
#define NREL 257

// Scratch (device globals)
__device__ float g_Q[BB*SS*DM];
__device__ float g_K[BB*SS*DM];
__device__ float g_V[BB*SS*DM];
__device__ float g_qbar[BB*HH*SS*DD];
__device__ float g_Rbar[BB*HH*SS*NREL];
__device__ float g_S[BB*HH*SS*SS];
__device__ float g_Ap[BB*HH*SS*NREL];
__device__ float g_Y[BB*HH*SS*DD];
__device__ float g_ctx[BB*SS*DM];
__device__ float g_ropeT[2048*64];

__device__ __forceinline__ unsigned f2tf32(float v) {
    unsigned u;
    asm("cvt.rna.tf32.f32 %0, %1;" : "=r"(u) : "f"(v));
    return u;
}

__device__ __forceinline__ void mma_tf32(float c[4],
                                         unsigned a0, unsigned a1, unsigned a2, unsigned a3,
                                         unsigned b0, unsigned b1) {
    asm volatile("mma.sync.aligned.m16n8k8.row.col.f32.tf32.tf32.f32 "
                 "{%0,%1,%2,%3}, {%4,%5,%6,%7}, {%8,%9}, {%0,%1,%2,%3};"
                 : "+f"(c[0]), "+f"(c[1]), "+f"(c[2]), "+f"(c[3])
                 : "r"(a0), "r"(a1), "r"(a2), "r"(a3), "r"(b0), "r"(b1));
}

// ===========================================================================
// 128x128 tf32 GEMM core (warp tile 64x32, K-step 16, double buffered).
// 8 warps: wm = wid>>2 (2 row-slabs of 64), wn = wid&3 (4 col-slabs of 32).
// Fragment-order smem: A [blk16(8)][ks8(2)][lane(32)][w(4)], B [nb8(16)][ks8(2)][lane][w(2)]
// ===========================================================================
#define T_AW 2048
#define T_BW 2048
#define T_BUF (T_AW + T_BW)
#define T_LDST 132
#define T_SMEM_BYTES (64 * T_LDST * 4)     // 33792 > 2*T_BUF*4 = 32768

// --- shared mainloop macro (A row-major [*,lda], B selected by TRANSB) ---
#define GEMM128_BODY(TRANSB_, KTOT, Aptr, Bptr, lda_, ldb_)                          \
    float acc[4][4][4];                                                              \
    _Pragma("unroll")                                                                \
    for (int i = 0; i < 4; i++)                                                      \
        _Pragma("unroll")                                                            \
        for (int j = 0; j < 4; j++)                                                  \
            _Pragma("unroll")                                                        \
            for (int e = 0; e < 4; e++) acc[i][j][e] = 0.f;                          \
    float aPf[8], bPf[8];                                                            \
    int ra = tid >> 4, ka = tid & 15;                                                \
    auto fetchA = [&](int kt) {                                                      \
        _Pragma("unroll")                                                            \
        for (int u = 0; u < 8; u++)                                                  \
            aPf[u] = Aptr[(long)(m0 + ra + u * 16) * lda_ + kt + ka];                \
    };                                                                               \
    auto fetchB = [&](int kt) {                                                      \
        _Pragma("unroll")                                                            \
        for (int u = 0; u < 8; u++) {                                                \
            int idx = tid + u * 256;                                                 \
            if (TRANSB_) {                                                           \
                int n = idx >> 4, kk = idx & 15;                                     \
                bPf[u] = Bptr[(long)(n0 + n) * ldb_ + kt + kk];                      \
            } else {                                                                 \
                int kk = idx >> 7, n = idx & 127;                                    \
                bPf[u] = Bptr[(long)(kt + kk) * ldb_ + n0 + n];                      \
            }                                                                        \
        }                                                                            \
    };                                                                               \
    auto storeBuf = [&](int buf) {                                                   \
        unsigned* Af = base + buf * T_BUF;                                           \
        unsigned* Bf = Af + T_AW;                                                    \
        _Pragma("unroll")                                                            \
        for (int u = 0; u < 8; u++) {                                                \
            int r = ra + u * 16, kk = ka;                                            \
            int blk = r >> 4, rr = r & 15;                                           \
            int ks8 = kk >> 3, kt7 = kk & 7;                                         \
            int dl = ((rr & 7) << 2) | (kt7 & 3);                                    \
            int w  = ((rr >> 3) & 1) | ((kt7 >> 2) << 1);                            \
            Af[(((blk << 1) | ks8) << 7) + (dl << 2) + w] = f2tf32(aPf[u]);          \
        }                                                                            \
        _Pragma("unroll")                                                            \
        for (int u = 0; u < 8; u++) {                                                \
            int idx = tid + u * 256;                                                 \
            int n, kk;                                                               \
            if (TRANSB_) { n = idx >> 4; kk = idx & 15; }                            \
            else         { kk = idx >> 7; n = idx & 127; }                           \
            int nb8 = n >> 3, gg = n & 7;                                            \
            int ks8 = kk >> 3, kt7 = kk & 7;                                         \
            int dl = (gg << 2) | (kt7 & 3);                                          \
            int w  = (kt7 >> 2) & 1;                                                 \
            Bf[(((nb8 << 1) | ks8) << 6) + (dl << 1) + w] = f2tf32(bPf[u]);          \
        }                                                                            \
    };                                                                               \
    fetchA(0); fetchB(0);                                                            \
    storeBuf(0);                                                                     \
    __syncthreads();                                                                 \
    int cur = 0;                                                                     \
    for (int kt = 0; kt < (KTOT); kt += 16) {                                        \
        bool hn = (kt + 16) < (KTOT);                                                \
        if (hn) { fetchA(kt + 16); fetchB(kt + 16); }                                \
        unsigned* Af = base + cur * T_BUF;                                           \
        unsigned* Bf = Af + T_AW;                                                    \
        _Pragma("unroll")                                                            \
        for (int ks8 = 0; ks8 < 2; ks8++) {                                          \
            uint4 av[4];                                                             \
            _Pragma("unroll")                                                        \
            for (int i = 0; i < 4; i++) {                                            \
                int blk = wm * 4 + i;                                                \
                av[i] = *(const uint4*)&Af[(((blk << 1) | ks8) << 7) + (lane << 2)]; \
            }                                                                        \
            _Pragma("unroll")                                                        \
            for (int j = 0; j < 4; j++) {                                            \
                int nb8 = wn * 4 + j;                                                \
                uint2 bv = *(const uint2*)&Bf[(((nb8 << 1) | ks8) << 6) + (lane << 1)]; \
                _Pragma("unroll")                                                    \
                for (int i = 0; i < 4; i++)                                          \
                    mma_tf32(acc[i][j], av[i].x, av[i].y, av[i].z, av[i].w, bv.x, bv.y); \
            }                                                                        \
        }                                                                            \
        if (hn) storeBuf(cur ^ 1);                                                   \
        __syncthreads();                                                             \
        cur ^= 1;                                                                    \
    }

#define STAGE_STORE(step_)                                                           \
    if (wm == (step_)) {                                                             \
        _Pragma("unroll")                                                            \
        for (int i = 0; i < 4; i++)                                                  \
            _Pragma("unroll")                                                        \
            for (int j = 0; j < 4; j++) {                                            \
                int r0 = i * 16 + g;                                                 \
                int c0 = wn * 32 + j * 8 + 2 * t;                                    \
                stage[ r0      * T_LDST + c0    ] = acc[i][j][0];                    \
                stage[ r0      * T_LDST + c0 + 1] = acc[i][j][1];                    \
                stage[(r0 + 8) * T_LDST + c0    ] = acc[i][j][2];                    \
                stage[(r0 + 8) * T_LDST + c0 + 1] = acc[i][j][3];                    \
            }                                                                        \
    }

// ---------------------------------------------------------------------------
// Projection kernel: C[z] = A[z] @ W[z]^T + bias[z], optional fused RoPE.
// z = blockIdx.z selects the pointer triple. Grid (8, 16, nz).
// ---------------------------------------------------------------------------
struct Proj3 {
    const float* A[3];
    const float* W[3];
    float*       C[3];
    const float* bias[3];
    const int*   pos[3];
};

__global__ void __launch_bounds__(256, 2)
proj128_kernel(Proj3 p, const float* __restrict__ ropeTab)
{
    extern __shared__ __align__(16) unsigned char dynsm[];
    unsigned* base = (unsigned*)dynsm;
    float* stage = (float*)dynsm;

    int z = blockIdx.z;
    const float* A = p.A[z];
    const float* W = p.W[z];
    float* C = p.C[z];
    const float* bias = p.bias[z];
    const int* posIds = p.pos[z];

    int tid = threadIdx.x;
    int wid = tid >> 5, lane = tid & 31;
    int wm = wid >> 2, wn = wid & 3;
    int g = lane >> 2, t = lane & 3;
    int m0 = blockIdx.y * 128, n0 = blockIdx.x * 128;

    GEMM128_BODY(true, DM, A, W, DM, DM)

    #pragma unroll
    for (int step = 0; step < 2; step++) {
        STAGE_STORE(step)
        __syncthreads();
        #pragma unroll
        for (int u = 0; u < 8; u++) {
            int idx = tid + u * 256;
            int r = idx >> 5, c4 = idx & 31;
            int c = c4 * 4;
            int gm = m0 + step * 64 + r;
            float4 v = *(const float4*)(stage + r * T_LDST + c);
            float4 bv = *(const float4*)(bias + n0 + c);
            v.x += bv.x; v.y += bv.y; v.z += bv.z; v.w += bv.w;
            if (posIds) {
                float4 w = *(const float4*)(stage + r * T_LDST + (c ^ 32));
                float4 bw = *(const float4*)(bias + n0 + (c ^ 32));
                w.x += bw.x; w.y += bw.y; w.z += bw.z; w.w += bw.w;
                int b = gm >> 10, s = gm & 1023;
                int pos = posIds[(b << 10) + s];
                int i0 = c & 31;
                float4 co = *(const float4*)(ropeTab + pos * 64 + i0);
                float4 si = *(const float4*)(ropeTab + pos * 64 + 32 + i0);
                if ((c & 32) == 0) {
                    v.x = v.x * co.x - w.x * si.x;
                    v.y = v.y * co.y - w.y * si.y;
                    v.z = v.z * co.z - w.z * si.z;
                    v.w = v.w * co.w - w.w * si.w;
                } else {
                    v.x = v.x * co.x + w.x * si.x;
                    v.y = v.y * co.y + w.y * si.y;
                    v.z = v.z * co.z + w.z * si.z;
                    v.w = v.w * co.w + w.w * si.w;
                }
            }
            *(float4*)(C + (long)gm * DM + n0 + c) = v;
        }
        __syncthreads();
    }
}

// ---------------------------------------------------------------------------
// QK^T kernel: S[b,h] = Qh @ Kh^T, causal tile skip. Grid (8, 8, 32).
// ---------------------------------------------------------------------------
__global__ void __launch_bounds__(256, 2)
qk128_kernel(const float* __restrict__ Qm, const float* __restrict__ Km,
             float* __restrict__ S)
{
    extern __shared__ __align__(16) unsigned char dynsm[];
    unsigned* base = (unsigned*)dynsm;
    float* stage = (float*)dynsm;

    int m0 = blockIdx.y * 128, n0 = blockIdx.x * 128;
    if (n0 > m0) return;    // fully masked (keep diagonal tile n0 == m0)

    int z = blockIdx.z;
    int b = z >> 4, h = z & 15;
    const float* A = Qm + (long)b * SS * DM + h * 64;
    const float* Bp = Km + (long)b * SS * DM + h * 64;
    float* C = S + (long)z * SS * SS;

    int tid = threadIdx.x;
    int wid = tid >> 5, lane = tid & 31;
    int wm = wid >> 2, wn = wid & 3;
    int g = lane >> 2, t = lane & 3;

    GEMM128_BODY(true, 64, A, Bp, DM, DM)

    #pragma unroll
    for (int step = 0; step < 2; step++) {
        STAGE_STORE(step)
        __syncthreads();
        #pragma unroll
        for (int u = 0; u < 8; u++) {
            int idx = tid + u * 256;
            int r = idx >> 5, c4 = idx & 31;
            int c = c4 * 4;
            int gm = m0 + step * 64 + r;
            float4 v = *(const float4*)(stage + r * T_LDST + c);
            *(float4*)(C + (long)gm * SS + n0 + c) = v;
        }
        __syncthreads();
    }
}

// ---------------------------------------------------------------------------
// TN=64 tf32 GEMM (round-7 kernel) for Rbar / Y / AV
// ---------------------------------------------------------------------------
#define G_AWORDS 4096
#define G_BWORDS 2048
#define G_BUF (G_AWORDS + G_BWORDS)
#define G_LDST 68
#define G_SMEM_BYTES (2 * G_BUF * 4)

template<bool TRANSB, bool GUARD>
__global__ void __launch_bounds__(256, 2)
gemm_tf32_kernel(const float* __restrict__ A, const float* __restrict__ Bm,
                 float* __restrict__ C,
                 int M, int N, int K, int lda, int ldb, int ldc,
                 long sAin, long sAout, long sBin, long sBout, long sCin, long sCout,
                 int bInner,
                 const float* __restrict__ bias,
                 const float* __restrict__ addend, int ldadd,
                 long sAddIn, long sAddOut,
                 int causalMode)
{
    extern __shared__ __align__(16) unsigned char dynsm[];
    unsigned* base = (unsigned*)dynsm;
    float* stage = (float*)dynsm;

    int m0 = blockIdx.y * 128, n0 = blockIdx.x * 64;
    int Keff = K;
    if (causalMode == 2) { int kl = m0 + 128; Keff = kl < K ? kl : K; }

    int z = blockIdx.z;
    int zo = z / bInner, zi = z - zo * bInner;
    A  += zo * sAout + zi * sAin;
    Bm += zo * sBout + zi * sBin;
    C  += zo * sCout + zi * sCin;
    if (addend) addend += zo * sAddOut + zi * sAddIn;

    int tid = threadIdx.x;
    int wid = tid >> 5, lane = tid & 31;
    int wm = wid >> 1;
    int wn = wid & 1;
    int g = lane >> 2, t = lane & 3;
    int ra = tid >> 5, ka = tid & 31;

    float acc[2][4][4];
    #pragma unroll
    for (int i = 0; i < 2; i++)
        #pragma unroll
        for (int j = 0; j < 4; j++)
            #pragma unroll
            for (int e = 0; e < 4; e++) acc[i][j][e] = 0.f;

    float aPf[16], bPf[8];

    auto fetchA = [&](int kt) {
        #pragma unroll
        for (int u = 0; u < 16; u++) {
            int r = ra + u * 8;
            int gm = m0 + r, gk = kt + ka;
            if (GUARD)
                aPf[u] = (gm < M && gk < K) ? A[(long)gm * lda + gk] : 0.f;
            else
                aPf[u] = A[(long)gm * lda + gk];
        }
    };
    auto fetchB = [&](int kt) {
        #pragma unroll
        for (int u = 0; u < 8; u++) {
            int idx = tid + u * 256;
            if (TRANSB) {
                int n = idx >> 5, kk = idx & 31;
                int gn = n0 + n, gk = kt + kk;
                if (GUARD)
                    bPf[u] = (gn < N && gk < K) ? Bm[(long)gn * ldb + gk] : 0.f;
                else
                    bPf[u] = Bm[(long)gn * ldb + gk];
            } else {
                int kk = idx >> 6, n = idx & 63;
                int gk = kt + kk, gn = n0 + n;
                if (GUARD)
                    bPf[u] = (gk < K && gn < N) ? Bm[(long)gk * ldb + gn] : 0.f;
                else
                    bPf[u] = Bm[(long)gk * ldb + gn];
            }
        }
    };
    auto storeBuf = [&](int buf) {
        unsigned* Af = base + buf * G_BUF;
        unsigned* Bf = Af + G_AWORDS;
        #pragma unroll
        for (int u = 0; u < 16; u++) {
            int r = ra + u * 8, kk = ka;
            int blk = r >> 4, rr = r & 15;
            int ks8 = kk >> 3, kt7 = kk & 7;
            int dl = ((rr & 7) << 2) | (kt7 & 3);
            int w  = ((rr >> 3) & 1) | ((kt7 >> 2) << 1);
            Af[(((blk << 2) + ks8) << 7) + (dl << 2) + w] = f2tf32(aPf[u]);
        }
        #pragma unroll
        for (int u = 0; u < 8; u++) {
            int idx = tid + u * 256;
            int n, kk;
            if (TRANSB) { n = idx >> 5; kk = idx & 31; }
            else        { kk = idx >> 6; n = idx & 63; }
            int nb8 = n >> 3, gg = n & 7;
            int ks8 = kk >> 3, kt7 = kk & 7;
            int dl = (gg << 2) | (kt7 & 3);
            int w  = (kt7 >> 2) & 1;
            Bf[(((nb8 << 2) + ks8) << 6) + (dl << 1) + w] = f2tf32(bPf[u]);
        }
    };

    fetchA(0); fetchB(0);
    storeBuf(0);
    __syncthreads();

    int cur = 0;
    for (int kt = 0; kt < Keff; kt += 32) {
        bool hn = (kt + 32) < Keff;
        if (hn) { fetchA(kt + 32); fetchB(kt + 32); }

        unsigned* Af = base + cur * G_BUF;
        unsigned* Bf = Af + G_AWORDS;
        #pragma unroll
        for (int ks8 = 0; ks8 < 4; ks8++) {
            uint4 av[2];
            #pragma unroll
            for (int i = 0; i < 2; i++) {
                int blk = wm * 2 + i;
                av[i] = *(const uint4*)&Af[(((blk << 2) + ks8) << 7) + (lane << 2)];
            }
            #pragma unroll
            for (int j = 0; j < 4; j++) {
                int nb8 = wn * 4 + j;
                uint2 bv = *(const uint2*)&Bf[(((nb8 << 2) + ks8) << 6) + (lane << 1)];
                #pragma unroll
                for (int i = 0; i < 2; i++)
                    mma_tf32(acc[i][j], av[i].x, av[i].y, av[i].z, av[i].w, bv.x, bv.y);
            }
        }

        if (hn) storeBuf(cur ^ 1);
        __syncthreads();
        cur ^= 1;
    }

    #pragma unroll
    for (int step = 0; step < 2; step++) {
        if ((wm >> 1) == step) {
            int rbase = (wm & 1) * 32;
            #pragma unroll
            for (int i = 0; i < 2; i++)
                #pragma unroll
                for (int j = 0; j < 4; j++) {
                    int r0 = rbase + i * 16 + g;
                    int c0 = wn * 32 + j * 8 + 2 * t;
                    stage[ r0      * G_LDST + c0    ] = acc[i][j][0];
                    stage[ r0      * G_LDST + c0 + 1] = acc[i][j][1];
                    stage[(r0 + 8) * G_LDST + c0    ] = acc[i][j][2];
                    stage[(r0 + 8) * G_LDST + c0 + 1] = acc[i][j][3];
                }
        }
        __syncthreads();
        if (GUARD) {
            #pragma unroll
            for (int u = 0; u < 16; u++) {
                int idx = tid + u * 256;
                int r = idx >> 6, c = idx & 63;
                int gm = m0 + step * 64 + r, gn = n0 + c;
                if (gm < M && gn < N) {
                    float v = stage[r * G_LDST + c];
                    if (bias)   v += bias[gn];
                    if (addend) v += addend[(long)gm * ldadd + gn];
                    C[(long)gm * ldc + gn] = v;
                }
            }
        } else {
            #pragma unroll
            for (int u = 0; u < 4; u++) {
                int idx = tid + u * 256;
                int r = idx >> 4, c4 = idx & 15;
                int c = c4 * 4;
                int gm = m0 + step * 64 + r;
                float4 v = *(const float4*)(stage + r * G_LDST + c);
                if (bias) {
                    float4 bv = *(const float4*)(bias + n0 + c);
                    v.x += bv.x; v.y += bv.y; v.z += bv.z; v.w += bv.w;
                }
                if (addend) {
                    float4 av = *(const float4*)(addend + (long)gm * ldadd + n0 + c);
                    v.x += av.x; v.y += av.y; v.z += av.z; v.w += av.w;
                }
                *(float4*)(C + (long)gm * ldc + n0 + c) = v;
            }
        }
        __syncthreads();
    }
}

// ---------------------------------------------------------------------------
// RoPE table
// ---------------------------------------------------------------------------
__global__ void rope_table_kernel(float* __restrict__ T)
{
    int idx = blockIdx.x * blockDim.x + threadIdx.x;
    if (idx >= 2048 * 32) return;
    int i = idx & 31, pos = idx >> 5;
    double inv = exp(-(double)i / 32.0 * log(10000.0));
    double ds, dc;
    sincos((double)pos * inv, &ds, &dc);
    T[pos * 64 + i]      = (float)dc;
    T[pos * 64 + 32 + i] = (float)ds;
}

// ---------------------------------------------------------------------------
// qbar
// ---------------------------------------------------------------------------
__global__ void qbar_kernel(const float* __restrict__ Q, const float* __restrict__ wpre,
                            float* __restrict__ qbar)
{
    int idx = blockIdx.x * blockDim.x + threadIdx.x;
    if (idx >= BB * HH * SS * DD) return;
    int d = idx & 63;
    int s = (idx >> 6) & 1023;
    int m = (idx >> 16) & 15;
    int b = idx >> 20;
    const float* qrow = Q + ((size_t)(b * SS + s)) * DM + d;
    float acc = 0.f;
    #pragma unroll
    for (int n = 0; n < 16; n++) acc += __ldg(&wpre[n * 16 + m]) * qrow[n * 64];
    qbar[idx] = acc;
}

// ---------------------------------------------------------------------------
// mix_softmax with causal I/O: only KW = roundup128(q+1) columns touched.
// ---------------------------------------------------------------------------
#define MIX_SMEM ((16*1024 + 16*257 + 256 + 256 + 16 + 16) * 4)

__global__ void __launch_bounds__(512)
mix_softmax_kernel(float* __restrict__ S, const float* __restrict__ Rbar,
                   const float* __restrict__ wpre, const float* __restrict__ wpost,
                   float* __restrict__ Ap)
{
    extern __shared__ float shm[];
    float* sm     = shm;
    float* srb    = sm + 16 * 1024;
    float* swpre  = srb + 16 * 257;
    float* swpost = swpre + 256;
    float* sinv   = swpost + 256;
    float* stail  = sinv + 16;

    int q = blockIdx.x, b = blockIdx.y;
    int tid = threadIdx.x;
    int wid = tid >> 5, lane = tid & 31;
    int KW4 = ((q >> 7) + 1) << 5;       // float4s per row actually needed
    int KW  = KW4 << 2;

    if (tid < 256) { swpre[tid] = wpre[tid]; swpost[tid] = wpost[tid]; }
    {
        const long rowBase = ((long)(b * 16) * SS + q) * SS;
        for (int tt = tid; tt < 16 * 256; tt += 512) {
            int n = tt >> 8, k4 = tt & 255;
            if (k4 < KW4)
                ((float4*)sm)[n * 256 + k4] =
                    *(const float4*)(S + rowBase + (long)n * SS * SS + k4 * 4);
        }
    }
    for (int tt = tid; tt < 16 * NREL; tt += 512) {
        int m = tt / NREL, j = tt - m * NREL;
        srb[tt] = Rbar[((size_t)(b * 16 + m) * SS + q) * NREL + j];
    }
    __syncthreads();

    for (int k = tid; k <= q; k += 512) {
        float r[16];
        #pragma unroll
        for (int n = 0; n < 16; n++) r[n] = sm[n * 1024 + k];
        int d = q - k;
        int cl = d > 128 ? 128 : d;
        int idx = cl + 128;
        #pragma unroll
        for (int m = 0; m < 16; m++) {
            float accv = 0.f;
            #pragma unroll
            for (int n = 0; n < 16; n++) accv += swpre[n * 16 + m] * r[n];
            sm[m * 1024 + k] = (accv + srb[m * NREL + idx]) * 0.125f;
        }
    }
    __syncthreads();

    {
        int m = wid;
        float mx = -1e30f;
        for (int k = lane; k <= q; k += 32) mx = fmaxf(mx, sm[m * 1024 + k]);
        #pragma unroll
        for (int o = 16; o; o >>= 1) mx = fmaxf(mx, __shfl_xor_sync(0xffffffffu, mx, o));
        float sum = 0.f;
        for (int k = lane; k <= q; k += 32) {
            float p = __expf(sm[m * 1024 + k] - mx);
            sm[m * 1024 + k] = p;
            sum += p;
        }
        #pragma unroll
        for (int o = 16; o; o >>= 1) sum += __shfl_xor_sync(0xffffffffu, sum, o);
        for (int k = q + 1 + lane; k < KW; k += 32) sm[m * 1024 + k] = 0.f;
        if (lane == 0) sinv[m] = 1.f / sum;
    }
    __syncthreads();

    float inv[16];
    #pragma unroll
    for (int m = 0; m < 16; m++) inv[m] = sinv[m];
    for (int k = tid; k <= q; k += 512) {
        float p[16];
        #pragma unroll
        for (int m = 0; m < 16; m++) p[m] = sm[m * 1024 + k] * inv[m];
        #pragma unroll
        for (int n = 0; n < 16; n++) {
            float accv = 0.f;
            #pragma unroll
            for (int m = 0; m < 16; m++) accv += p[m] * swpost[m * 16 + n];
            sm[n * 1024 + k] = accv;
        }
    }
    __syncthreads();

    {
        const long rowBase = ((long)(b * 16) * SS + q) * SS;
        for (int tt = tid; tt < 16 * 256; tt += 512) {
            int n = tt >> 8, k4 = tt & 255;
            if (k4 < KW4)
                *(float4*)(S + rowBase + (long)n * SS * SS + k4 * 4) =
                    ((float4*)sm)[n * 256 + k4];
        }
    }
    {
        int m = wid;
        float ts = 0.f;
        for (int k = lane; k <= q - 128; k += 32) ts += sm[m * 1024 + k];
        #pragma unroll
        for (int o = 16; o; o >>= 1) ts += __shfl_xor_sync(0xffffffffu, ts, o);
        if (lane == 0) stail[m] = ts;
    }
    __syncthreads();

    for (int tt = tid; tt < 16 * NREL; tt += 512) {
        int n = tt / NREL, j = tt - n * NREL;
        float v = 0.f;
        if (j == 256) v = stail[n];
        else if (j >= 128) {
            int k = q - (j - 128);
            if (k >= 0) v = sm[n * 1024 + k];
        }
        Ap[((size_t)(b * 16 + n) * SS + q) * NREL + j] = v;
    }
}

// ---------------------------------------------------------------------------
// Launch sequence
// ---------------------------------------------------------------------------
extern "C" void kernel_launch(void* const* d_in, const int* in_sizes, int n_in,
                              void* d_out, int out_size)
{
    const float* query = (const float*)d_in[0];
    const float* key_  = (const float*)d_in[1];
    const float* value = (const float*)d_in[2];
    const int*   qpos  = (const int*)d_in[4];
    const int*   kpos  = (const int*)d_in[5];
    const float* Wq = (const float*)d_in[6];  const float* bq = (const float*)d_in[7];
    const float* Wk = (const float*)d_in[8];  const float* bk = (const float*)d_in[9];
    const float* Wv = (const float*)d_in[10]; const float* bv = (const float*)d_in[11];
    const float* Wo = (const float*)d_in[12]; const float* bo = (const float*)d_in[13];
    const float* relk  = (const float*)d_in[14];
    const float* relv  = (const float*)d_in[15];
    const float* wpre  = (const float*)d_in[16];
    const float* wpost = (const float*)d_in[17];
    float* out = (float*)d_out;

    float *Q, *Kc, *V, *qbar, *Rbar, *Sc, *Ap, *Y, *ctx, *ropeT;
    cudaGetSymbolAddress((void**)&Q,     g_Q);
    cudaGetSymbolAddress((void**)&Kc,    g_K);
    cudaGetSymbolAddress((void**)&V,     g_V);
    cudaGetSymbolAddress((void**)&qbar,  g_qbar);
    cudaGetSymbolAddress((void**)&Rbar,  g_Rbar);
    cudaGetSymbolAddress((void**)&Sc,    g_S);
    cudaGetSymbolAddress((void**)&Ap,    g_Ap);
    cudaGetSymbolAddress((void**)&Y,     g_Y);
    cudaGetSymbolAddress((void**)&ctx,   g_ctx);
    cudaGetSymbolAddress((void**)&ropeT, g_ropeT);

    dim3 blk(256);
    const long S2 = (long)SS * SS;
    const long SD = (long)SS * DM;
    const int GS = G_SMEM_BYTES;
    const int TS = T_SMEM_BYTES;

    cudaFuncSetAttribute(gemm_tf32_kernel<true,  true>,
                         cudaFuncAttributeMaxDynamicSharedMemorySize, GS);
    cudaFuncSetAttribute(gemm_tf32_kernel<false, false>,
                         cudaFuncAttributeMaxDynamicSharedMemorySize, GS);
    cudaFuncSetAttribute(gemm_tf32_kernel<false, true>,
                         cudaFuncAttributeMaxDynamicSharedMemorySize, GS);
    cudaFuncSetAttribute(proj128_kernel,
                         cudaFuncAttributeMaxDynamicSharedMemorySize, TS);
    cudaFuncSetAttribute(qk128_kernel,
                         cudaFuncAttributeMaxDynamicSharedMemorySize, TS);

    rope_table_kernel<<<256, 256>>>(ropeT);

    // Q, K, V projections in ONE launch (fused bias + RoPE on Q/K)
    Proj3 qkv;
    qkv.A[0] = query; qkv.A[1] = key_; qkv.A[2] = value;
    qkv.W[0] = Wq;    qkv.W[1] = Wk;   qkv.W[2] = Wv;
    qkv.C[0] = Q;     qkv.C[1] = Kc;   qkv.C[2] = V;
    qkv.bias[0] = bq; qkv.bias[1] = bk; qkv.bias[2] = bv;
    qkv.pos[0] = qpos; qkv.pos[1] = kpos; qkv.pos[2] = nullptr;
    proj128_kernel<<<dim3(8, 16, 3), blk, TS>>>(qkv, ropeT);

    qbar_kernel<<<8192, 256>>>(Q, wpre, qbar);
    // Rbar = qbar @ relk^T  (N=257 -> guarded)
    gemm_tf32_kernel<true, true><<<dim3(5, 256, 1), blk, GS>>>(qbar, relk, Rbar, 32768, NREL, 64,
        64, 64, NREL, 0, 0, 0, 0, 0, 0, 1, nullptr, nullptr, 0, 0, 0, 0);

    // QK^T per head, causal tile-skip
    qk128_kernel<<<dim3(8, 8, 32), blk, TS>>>(Q, Kc, Sc);

    cudaFuncSetAttribute(mix_softmax_kernel,
                         cudaFuncAttributeMaxDynamicSharedMemorySize, MIX_SMEM);
    mix_softmax_kernel<<<dim3(1024, 2), 512, MIX_SMEM>>>(Sc, Rbar, wpre, wpost, Ap);

    // Y = A' @ relv  (K=257 -> guarded)
    gemm_tf32_kernel<false, true><<<dim3(1, 256, 1), blk, GS>>>(Ap, relv, Y, 32768, 64, NREL,
        NREL, 64, 64, 0, 0, 0, 0, 0, 0, 1, nullptr, nullptr, 0, 0, 0, 0);

    // ctx = attn @ v + Y, causal K-limit, batch = 32
    gemm_tf32_kernel<false, false><<<dim3(1, 8, 32), blk, GS>>>(Sc, V, ctx, 1024, 64, 1024,
        1024, 1024, 1024,
        S2, 16L * S2, 64L, SD, 64L, SD,
        16, nullptr,
        Y, 64, 65536L, 16L * 65536L, 2);

    // out = ctx @ Wo^T + bo
    Proj3 wo;
    wo.A[0] = ctx; wo.A[1] = nullptr; wo.A[2] = nullptr;
    wo.W[0] = Wo;  wo.W[1] = nullptr; wo.W[2] = nullptr;
    wo.C[0] = out; wo.C[1] = nullptr; wo.C[2] = nullptr;
    wo.bias[0] = bo; wo.bias[1] = nullptr; wo.bias[2] = nullptr;
    wo.pos[0] = nullptr; wo.pos[1] = nullptr; wo.pos[2] = nullptr;
    proj128_kernel<<<dim3(8, 16, 1), blk, TS>>>(wo, ropeT);
}

// round 10
// speedup vs baseline: 3.3675x; 1.0745x over previous
#include <cuda_runtime.h>
#include <cuda_bf16.h>
#include <math.h>
#include <stdint.h>

// Problem constants
#define BB 2
#define SS 1024
#define HH 16
#define DD 64
#define DM 1024
#define NREL 257
#define NRS 129        // slim rel width: indices 128..256 of the full table

// Scratch (device globals)
__device__ float g_Q[BB*SS*DM];
__device__ float g_K[BB*SS*DM];
__device__ float g_V[BB*SS*DM];
__device__ float g_qbar[BB*HH*SS*DD];
__device__ float g_Rbar[BB*HH*SS*NRS];
__device__ float g_S[BB*HH*SS*SS];
__device__ float g_Ap[BB*HH*SS*NRS];
__device__ float g_Y[BB*HH*SS*DD];
__device__ float g_ctx[BB*SS*DM];
__device__ float g_ropeT[2048*64];

__device__ __forceinline__ unsigned f2tf32(float v) {
    unsigned u;
    asm("cvt.rna.tf32.f32 %0, %1;" : "=r"(u) : "f"(v));
    return u;
}

__device__ __forceinline__ void mma_tf32(float c[4],
                                         unsigned a0, unsigned a1, unsigned a2, unsigned a3,
                                         unsigned b0, unsigned b1) {
    asm volatile("mma.sync.aligned.m16n8k8.row.col.f32.tf32.tf32.f32 "
                 "{%0,%1,%2,%3}, {%4,%5,%6,%7}, {%8,%9}, {%0,%1,%2,%3};"
                 : "+f"(c[0]), "+f"(c[1]), "+f"(c[2]), "+f"(c[3])
                 : "r"(a0), "r"(a1), "r"(a2), "r"(a3), "r"(b0), "r"(b1));
}

// ===========================================================================
// 128x128 tf32 GEMM core (warp tile 64x32, K-step 16, double buffered).
// ===========================================================================
#define T_AW 2048
#define T_BW 2048
#define T_BUF (T_AW + T_BW)
#define T_LDST 132
#define T_SMEM_BYTES (64 * T_LDST * 4)

#define GEMM128_BODY(TRANSB_, KTOT, Aptr, Bptr, lda_, ldb_)                          \
    float acc[4][4][4];                                                              \
    _Pragma("unroll")                                                                \
    for (int i = 0; i < 4; i++)                                                      \
        _Pragma("unroll")                                                            \
        for (int j = 0; j < 4; j++)                                                  \
            _Pragma("unroll")                                                        \
            for (int e = 0; e < 4; e++) acc[i][j][e] = 0.f;                          \
    float aPf[8], bPf[8];                                                            \
    int ra = tid >> 4, ka = tid & 15;                                                \
    auto fetchA = [&](int kt) {                                                      \
        _Pragma("unroll")                                                            \
        for (int u = 0; u < 8; u++)                                                  \
            aPf[u] = Aptr[(long)(m0 + ra + u * 16) * lda_ + kt + ka];                \
    };                                                                               \
    auto fetchB = [&](int kt) {                                                      \
        _Pragma("unroll")                                                            \
        for (int u = 0; u < 8; u++) {                                                \
            int idx = tid + u * 256;                                                 \
            if (TRANSB_) {                                                           \
                int n = idx >> 4, kk = idx & 15;                                     \
                bPf[u] = Bptr[(long)(n0 + n) * ldb_ + kt + kk];                      \
            } else {                                                                 \
                int kk = idx >> 7, n = idx & 127;                                    \
                bPf[u] = Bptr[(long)(kt + kk) * ldb_ + n0 + n];                      \
            }                                                                        \
        }                                                                            \
    };                                                                               \
    auto storeBuf = [&](int buf) {                                                   \
        unsigned* Af = base + buf * T_BUF;                                           \
        unsigned* Bf = Af + T_AW;                                                    \
        _Pragma("unroll")                                                            \
        for (int u = 0; u < 8; u++) {                                                \
            int r = ra + u * 16, kk = ka;                                            \
            int blk = r >> 4, rr = r & 15;                                           \
            int ks8 = kk >> 3, kt7 = kk & 7;                                         \
            int dl = ((rr & 7) << 2) | (kt7 & 3);                                    \
            int w  = ((rr >> 3) & 1) | ((kt7 >> 2) << 1);                            \
            Af[(((blk << 1) | ks8) << 7) + (dl << 2) + w] = f2tf32(aPf[u]);          \
        }                                                                            \
        _Pragma("unroll")                                                            \
        for (int u = 0; u < 8; u++) {                                                \
            int idx = tid + u * 256;                                                 \
            int n, kk;                                                               \
            if (TRANSB_) { n = idx >> 4; kk = idx & 15; }                            \
            else         { kk = idx >> 7; n = idx & 127; }                           \
            int nb8 = n >> 3, gg = n & 7;                                            \
            int ks8 = kk >> 3, kt7 = kk & 7;                                         \
            int dl = (gg << 2) | (kt7 & 3);                                          \
            int w  = (kt7 >> 2) & 1;                                                 \
            Bf[(((nb8 << 1) | ks8) << 6) + (dl << 1) + w] = f2tf32(bPf[u]);          \
        }                                                                            \
    };                                                                               \
    fetchA(0); fetchB(0);                                                            \
    storeBuf(0);                                                                     \
    __syncthreads();                                                                 \
    int cur = 0;                                                                     \
    for (int kt = 0; kt < (KTOT); kt += 16) {                                        \
        bool hn = (kt + 16) < (KTOT);                                                \
        if (hn) { fetchA(kt + 16); fetchB(kt + 16); }                                \
        unsigned* Af = base + cur * T_BUF;                                           \
        unsigned* Bf = Af + T_AW;                                                    \
        _Pragma("unroll")                                                            \
        for (int ks8 = 0; ks8 < 2; ks8++) {                                          \
            uint4 av[4];                                                             \
            _Pragma("unroll")                                                        \
            for (int i = 0; i < 4; i++) {                                            \
                int blk = wm * 4 + i;                                                \
                av[i] = *(const uint4*)&Af[(((blk << 1) | ks8) << 7) + (lane << 2)]; \
            }                                                                        \
            _Pragma("unroll")                                                        \
            for (int j = 0; j < 4; j++) {                                            \
                int nb8 = wn * 4 + j;                                                \
                uint2 bv = *(const uint2*)&Bf[(((nb8 << 1) | ks8) << 6) + (lane << 1)]; \
                _Pragma("unroll")                                                    \
                for (int i = 0; i < 4; i++)                                          \
                    mma_tf32(acc[i][j], av[i].x, av[i].y, av[i].z, av[i].w, bv.x, bv.y); \
            }                                                                        \
        }                                                                            \
        if (hn) storeBuf(cur ^ 1);                                                   \
        __syncthreads();                                                             \
        cur ^= 1;                                                                    \
    }

#define STAGE_STORE(step_)                                                           \
    if (wm == (step_)) {                                                             \
        _Pragma("unroll")                                                            \
        for (int i = 0; i < 4; i++)                                                  \
            _Pragma("unroll")                                                        \
            for (int j = 0; j < 4; j++) {                                            \
                int r0 = i * 16 + g;                                                 \
                int c0 = wn * 32 + j * 8 + 2 * t;                                    \
                stage[ r0      * T_LDST + c0    ] = acc[i][j][0];                    \
                stage[ r0      * T_LDST + c0 + 1] = acc[i][j][1];                    \
                stage[(r0 + 8) * T_LDST + c0    ] = acc[i][j][2];                    \
                stage[(r0 + 8) * T_LDST + c0 + 1] = acc[i][j][3];                    \
            }                                                                        \
    }

// ---------------------------------------------------------------------------
// Projection kernel (z selects pointer triple), fused bias + optional RoPE
// ---------------------------------------------------------------------------
struct Proj3 {
    const float* A[3];
    const float* W[3];
    float*       C[3];
    const float* bias[3];
    const int*   pos[3];
};

__global__ void __launch_bounds__(256, 2)
proj128_kernel(Proj3 p, const float* __restrict__ ropeTab)
{
    extern __shared__ __align__(16) unsigned char dynsm[];
    unsigned* base = (unsigned*)dynsm;
    float* stage = (float*)dynsm;

    int z = blockIdx.z;
    const float* A = p.A[z];
    const float* W = p.W[z];
    float* C = p.C[z];
    const float* bias = p.bias[z];
    const int* posIds = p.pos[z];

    int tid = threadIdx.x;
    int wid = tid >> 5, lane = tid & 31;
    int wm = wid >> 2, wn = wid & 3;
    int g = lane >> 2, t = lane & 3;
    int m0 = blockIdx.y * 128, n0 = blockIdx.x * 128;

    GEMM128_BODY(true, DM, A, W, DM, DM)

    #pragma unroll
    for (int step = 0; step < 2; step++) {
        STAGE_STORE(step)
        __syncthreads();
        #pragma unroll
        for (int u = 0; u < 8; u++) {
            int idx = tid + u * 256;
            int r = idx >> 5, c4 = idx & 31;
            int c = c4 * 4;
            int gm = m0 + step * 64 + r;
            float4 v = *(const float4*)(stage + r * T_LDST + c);
            float4 bv = *(const float4*)(bias + n0 + c);
            v.x += bv.x; v.y += bv.y; v.z += bv.z; v.w += bv.w;
            if (posIds) {
                float4 w = *(const float4*)(stage + r * T_LDST + (c ^ 32));
                float4 bw = *(const float4*)(bias + n0 + (c ^ 32));
                w.x += bw.x; w.y += bw.y; w.z += bw.z; w.w += bw.w;
                int b = gm >> 10, s = gm & 1023;
                int pos = posIds[(b << 10) + s];
                int i0 = c & 31;
                float4 co = *(const float4*)(ropeTab + pos * 64 + i0);
                float4 si = *(const float4*)(ropeTab + pos * 64 + 32 + i0);
                if ((c & 32) == 0) {
                    v.x = v.x * co.x - w.x * si.x;
                    v.y = v.y * co.y - w.y * si.y;
                    v.z = v.z * co.z - w.z * si.z;
                    v.w = v.w * co.w - w.w * si.w;
                } else {
                    v.x = v.x * co.x + w.x * si.x;
                    v.y = v.y * co.y + w.y * si.y;
                    v.z = v.z * co.z + w.z * si.z;
                    v.w = v.w * co.w + w.w * si.w;
                }
            }
            *(float4*)(C + (long)gm * DM + n0 + c) = v;
        }
        __syncthreads();
    }
}

// ---------------------------------------------------------------------------
// QK^T kernel, causal tile skip
// ---------------------------------------------------------------------------
__global__ void __launch_bounds__(256, 2)
qk128_kernel(const float* __restrict__ Qm, const float* __restrict__ Km,
             float* __restrict__ S)
{
    extern __shared__ __align__(16) unsigned char dynsm[];
    unsigned* base = (unsigned*)dynsm;
    float* stage = (float*)dynsm;

    int m0 = blockIdx.y * 128, n0 = blockIdx.x * 128;
    if (n0 > m0) return;

    int z = blockIdx.z;
    int b = z >> 4, h = z & 15;
    const float* A = Qm + (long)b * SS * DM + h * 64;
    const float* Bp = Km + (long)b * SS * DM + h * 64;
    float* C = S + (long)z * SS * SS;

    int tid = threadIdx.x;
    int wid = tid >> 5, lane = tid & 31;
    int wm = wid >> 2, wn = wid & 3;
    int g = lane >> 2, t = lane & 3;

    GEMM128_BODY(true, 64, A, Bp, DM, DM)

    #pragma unroll
    for (int step = 0; step < 2; step++) {
        STAGE_STORE(step)
        __syncthreads();
        #pragma unroll
        for (int u = 0; u < 8; u++) {
            int idx = tid + u * 256;
            int r = idx >> 5, c4 = idx & 31;
            int c = c4 * 4;
            int gm = m0 + step * 64 + r;
            float4 v = *(const float4*)(stage + r * T_LDST + c);
            *(float4*)(C + (long)gm * SS + n0 + c) = v;
        }
        __syncthreads();
    }
}

// ---------------------------------------------------------------------------
// TN=64 tf32 GEMM for Rbar / Y / AV
// ---------------------------------------------------------------------------
#define G_AWORDS 4096
#define G_BWORDS 2048
#define G_BUF (G_AWORDS + G_BWORDS)
#define G_LDST 68
#define G_SMEM_BYTES (2 * G_BUF * 4)

template<bool TRANSB, bool GUARD>
__global__ void __launch_bounds__(256, 2)
gemm_tf32_kernel(const float* __restrict__ A, const float* __restrict__ Bm,
                 float* __restrict__ C,
                 int M, int N, int K, int lda, int ldb, int ldc,
                 long sAin, long sAout, long sBin, long sBout, long sCin, long sCout,
                 int bInner,
                 const float* __restrict__ bias,
                 const float* __restrict__ addend, int ldadd,
                 long sAddIn, long sAddOut,
                 int causalMode)
{
    extern __shared__ __align__(16) unsigned char dynsm[];
    unsigned* base = (unsigned*)dynsm;
    float* stage = (float*)dynsm;

    int m0 = blockIdx.y * 128, n0 = blockIdx.x * 64;
    int Keff = K;
    if (causalMode == 2) { int kl = m0 + 128; Keff = kl < K ? kl : K; }

    int z = blockIdx.z;
    int zo = z / bInner, zi = z - zo * bInner;
    A  += zo * sAout + zi * sAin;
    Bm += zo * sBout + zi * sBin;
    C  += zo * sCout + zi * sCin;
    if (addend) addend += zo * sAddOut + zi * sAddIn;

    int tid = threadIdx.x;
    int wid = tid >> 5, lane = tid & 31;
    int wm = wid >> 1;
    int wn = wid & 1;
    int g = lane >> 2, t = lane & 3;
    int ra = tid >> 5, ka = tid & 31;

    float acc[2][4][4];
    #pragma unroll
    for (int i = 0; i < 2; i++)
        #pragma unroll
        for (int j = 0; j < 4; j++)
            #pragma unroll
            for (int e = 0; e < 4; e++) acc[i][j][e] = 0.f;

    float aPf[16], bPf[8];

    auto fetchA = [&](int kt) {
        #pragma unroll
        for (int u = 0; u < 16; u++) {
            int r = ra + u * 8;
            int gm = m0 + r, gk = kt + ka;
            if (GUARD)
                aPf[u] = (gm < M && gk < K) ? A[(long)gm * lda + gk] : 0.f;
            else
                aPf[u] = A[(long)gm * lda + gk];
        }
    };
    auto fetchB = [&](int kt) {
        #pragma unroll
        for (int u = 0; u < 8; u++) {
            int idx = tid + u * 256;
            if (TRANSB) {
                int n = idx >> 5, kk = idx & 31;
                int gn = n0 + n, gk = kt + kk;
                if (GUARD)
                    bPf[u] = (gn < N && gk < K) ? Bm[(long)gn * ldb + gk] : 0.f;
                else
                    bPf[u] = Bm[(long)gn * ldb + gk];
            } else {
                int kk = idx >> 6, n = idx & 63;
                int gk = kt + kk, gn = n0 + n;
                if (GUARD)
                    bPf[u] = (gk < K && gn < N) ? Bm[(long)gk * ldb + gn] : 0.f;
                else
                    bPf[u] = Bm[(long)gk * ldb + gn];
            }
        }
    };
    auto storeBuf = [&](int buf) {
        unsigned* Af = base + buf * G_BUF;
        unsigned* Bf = Af + G_AWORDS;
        #pragma unroll
        for (int u = 0; u < 16; u++) {
            int r = ra + u * 8, kk = ka;
            int blk = r >> 4, rr = r & 15;
            int ks8 = kk >> 3, kt7 = kk & 7;
            int dl = ((rr & 7) << 2) | (kt7 & 3);
            int w  = ((rr >> 3) & 1) | ((kt7 >> 2) << 1);
            Af[(((blk << 2) + ks8) << 7) + (dl << 2) + w] = f2tf32(aPf[u]);
        }
        #pragma unroll
        for (int u = 0; u < 8; u++) {
            int idx = tid + u * 256;
            int n, kk;
            if (TRANSB) { n = idx >> 5; kk = idx & 31; }
            else        { kk = idx >> 6; n = idx & 63; }
            int nb8 = n >> 3, gg = n & 7;
            int ks8 = kk >> 3, kt7 = kk & 7;
            int dl = (gg << 2) | (kt7 & 3);
            int w  = (kt7 >> 2) & 1;
            Bf[(((nb8 << 2) + ks8) << 6) + (dl << 1) + w] = f2tf32(bPf[u]);
        }
    };

    fetchA(0); fetchB(0);
    storeBuf(0);
    __syncthreads();

    int cur = 0;
    for (int kt = 0; kt < Keff; kt += 32) {
        bool hn = (kt + 32) < Keff;
        if (hn) { fetchA(kt + 32); fetchB(kt + 32); }

        unsigned* Af = base + cur * G_BUF;
        unsigned* Bf = Af + G_AWORDS;
        #pragma unroll
        for (int ks8 = 0; ks8 < 4; ks8++) {
            uint4 av[2];
            #pragma unroll
            for (int i = 0; i < 2; i++) {
                int blk = wm * 2 + i;
                av[i] = *(const uint4*)&Af[(((blk << 2) + ks8) << 7) + (lane << 2)];
            }
            #pragma unroll
            for (int j = 0; j < 4; j++) {
                int nb8 = wn * 4 + j;
                uint2 bv = *(const uint2*)&Bf[(((nb8 << 2) + ks8) << 6) + (lane << 1)];
                #pragma unroll
                for (int i = 0; i < 2; i++)
                    mma_tf32(acc[i][j], av[i].x, av[i].y, av[i].z, av[i].w, bv.x, bv.y);
            }
        }

        if (hn) storeBuf(cur ^ 1);
        __syncthreads();
        cur ^= 1;
    }

    #pragma unroll
    for (int step = 0; step < 2; step++) {
        if ((wm >> 1) == step) {
            int rbase = (wm & 1) * 32;
            #pragma unroll
            for (int i = 0; i < 2; i++)
                #pragma unroll
                for (int j = 0; j < 4; j++) {
                    int r0 = rbase + i * 16 + g;
                    int c0 = wn * 32 + j * 8 + 2 * t;
                    stage[ r0      * G_LDST + c0    ] = acc[i][j][0];
                    stage[ r0      * G_LDST + c0 + 1] = acc[i][j][1];
                    stage[(r0 + 8) * G_LDST + c0    ] = acc[i][j][2];
                    stage[(r0 + 8) * G_LDST + c0 + 1] = acc[i][j][3];
                }
        }
        __syncthreads();
        if (GUARD) {
            #pragma unroll
            for (int u = 0; u < 16; u++) {
                int idx = tid + u * 256;
                int r = idx >> 6, c = idx & 63;
                int gm = m0 + step * 64 + r, gn = n0 + c;
                if (gm < M && gn < N) {
                    float v = stage[r * G_LDST + c];
                    if (bias)   v += bias[gn];
                    if (addend) v += addend[(long)gm * ldadd + gn];
                    C[(long)gm * ldc + gn] = v;
                }
            }
        } else {
            #pragma unroll
            for (int u = 0; u < 4; u++) {
                int idx = tid + u * 256;
                int r = idx >> 4, c4 = idx & 15;
                int c = c4 * 4;
                int gm = m0 + step * 64 + r;
                float4 v = *(const float4*)(stage + r * G_LDST + c);
                if (bias) {
                    float4 bv = *(const float4*)(bias + n0 + c);
                    v.x += bv.x; v.y += bv.y; v.z += bv.z; v.w += bv.w;
                }
                if (addend) {
                    float4 av = *(const float4*)(addend + (long)gm * ldadd + n0 + c);
                    v.x += av.x; v.y += av.y; v.z += av.z; v.w += av.w;
                }
                *(float4*)(C + (long)gm * ldc + n0 + c) = v;
            }
        }
        __syncthreads();
    }
}

// ---------------------------------------------------------------------------
// RoPE table
// ---------------------------------------------------------------------------
__global__ void rope_table_kernel(float* __restrict__ T)
{
    int idx = blockIdx.x * blockDim.x + threadIdx.x;
    if (idx >= 2048 * 32) return;
    int i = idx & 31, pos = idx >> 5;
    double inv = exp(-(double)i / 32.0 * log(10000.0));
    double ds, dc;
    sincos((double)pos * inv, &ds, &dc);
    T[pos * 64 + i]      = (float)dc;
    T[pos * 64 + 32 + i] = (float)ds;
}

// ---------------------------------------------------------------------------
// qbar
// ---------------------------------------------------------------------------
__global__ void qbar_kernel(const float* __restrict__ Q, const float* __restrict__ wpre,
                            float* __restrict__ qbar)
{
    int idx = blockIdx.x * blockDim.x + threadIdx.x;
    if (idx >= BB * HH * SS * DD) return;
    int d = idx & 63;
    int s = (idx >> 6) & 1023;
    int m = (idx >> 16) & 15;
    int b = idx >> 20;
    const float* qrow = Q + ((size_t)(b * SS + s)) * DM + d;
    float acc = 0.f;
    #pragma unroll
    for (int n = 0; n < 16; n++) acc += __ldg(&wpre[n * 16 + m]) * qrow[n * 64];
    qbar[idx] = acc;
}

// ---------------------------------------------------------------------------
// mix_softmax — slim rel layout (NRS = 129 columns, j' = clamp(q-k,0,128))
// ---------------------------------------------------------------------------
#define MIX_SMEM ((16*1024 + 16*NRS + 256 + 256 + 16 + 16) * 4)

__global__ void __launch_bounds__(512)
mix_softmax_kernel(float* __restrict__ S, const float* __restrict__ Rbar,
                   const float* __restrict__ wpre, const float* __restrict__ wpost,
                   float* __restrict__ Ap)
{
    extern __shared__ float shm[];
    float* sm     = shm;
    float* srb    = sm + 16 * 1024;
    float* swpre  = srb + 16 * NRS;
    float* swpost = swpre + 256;
    float* sinv   = swpost + 256;
    float* stail  = sinv + 16;

    int q = blockIdx.x, b = blockIdx.y;
    int tid = threadIdx.x;
    int wid = tid >> 5, lane = tid & 31;
    int KW4 = ((q >> 7) + 1) << 5;
    int KW  = KW4 << 2;

    if (tid < 256) { swpre[tid] = wpre[tid]; swpost[tid] = wpost[tid]; }
    {
        const long rowBase = ((long)(b * 16) * SS + q) * SS;
        for (int tt = tid; tt < 16 * 256; tt += 512) {
            int n = tt >> 8, k4 = tt & 255;
            if (k4 < KW4)
                ((float4*)sm)[n * 256 + k4] =
                    *(const float4*)(S + rowBase + (long)n * SS * SS + k4 * 4);
        }
    }
    for (int tt = tid; tt < 16 * NRS; tt += 512) {
        int m = tt / NRS, j = tt - m * NRS;
        srb[tt] = Rbar[((size_t)(b * 16 + m) * SS + q) * NRS + j];
    }
    __syncthreads();

    for (int k = tid; k <= q; k += 512) {
        float r[16];
        #pragma unroll
        for (int n = 0; n < 16; n++) r[n] = sm[n * 1024 + k];
        int d = q - k;
        int cl = d > 128 ? 128 : d;         // slim index: 0..128
        #pragma unroll
        for (int m = 0; m < 16; m++) {
            float accv = 0.f;
            #pragma unroll
            for (int n = 0; n < 16; n++) accv += swpre[n * 16 + m] * r[n];
            sm[m * 1024 + k] = (accv + srb[m * NRS + cl]) * 0.125f;
        }
    }
    __syncthreads();

    {
        int m = wid;
        float mx = -1e30f;
        for (int k = lane; k <= q; k += 32) mx = fmaxf(mx, sm[m * 1024 + k]);
        #pragma unroll
        for (int o = 16; o; o >>= 1) mx = fmaxf(mx, __shfl_xor_sync(0xffffffffu, mx, o));
        float sum = 0.f;
        for (int k = lane; k <= q; k += 32) {
            float p = __expf(sm[m * 1024 + k] - mx);
            sm[m * 1024 + k] = p;
            sum += p;
        }
        #pragma unroll
        for (int o = 16; o; o >>= 1) sum += __shfl_xor_sync(0xffffffffu, sum, o);
        for (int k = q + 1 + lane; k < KW; k += 32) sm[m * 1024 + k] = 0.f;
        if (lane == 0) sinv[m] = 1.f / sum;
    }
    __syncthreads();

    float inv[16];
    #pragma unroll
    for (int m = 0; m < 16; m++) inv[m] = sinv[m];
    for (int k = tid; k <= q; k += 512) {
        float p[16];
        #pragma unroll
        for (int m = 0; m < 16; m++) p[m] = sm[m * 1024 + k] * inv[m];
        #pragma unroll
        for (int n = 0; n < 16; n++) {
            float accv = 0.f;
            #pragma unroll
            for (int m = 0; m < 16; m++) accv += p[m] * swpost[m * 16 + n];
            sm[n * 1024 + k] = accv;
        }
    }
    __syncthreads();

    {
        const long rowBase = ((long)(b * 16) * SS + q) * SS;
        for (int tt = tid; tt < 16 * 256; tt += 512) {
            int n = tt >> 8, k4 = tt & 255;
            if (k4 < KW4)
                *(float4*)(S + rowBase + (long)n * SS * SS + k4 * 4) =
                    ((float4*)sm)[n * 256 + k4];
        }
    }
    {
        int m = wid;
        float ts = 0.f;
        for (int k = lane; k <= q - 128; k += 32) ts += sm[m * 1024 + k];
        #pragma unroll
        for (int o = 16; o; o >>= 1) ts += __shfl_xor_sync(0xffffffffu, ts, o);
        if (lane == 0) stail[m] = ts;
    }
    __syncthreads();

    // A' slim: j' in [0,127] -> single element k = q - j'; j' == 128 -> tail
    for (int tt = tid; tt < 16 * NRS; tt += 512) {
        int n = tt / NRS, j = tt - n * NRS;
        float v = 0.f;
        if (j == 128) v = stail[n];
        else {
            int k = q - j;
            if (k >= 0) v = sm[n * 1024 + k];
        }
        Ap[((size_t)(b * 16 + n) * SS + q) * NRS + j] = v;
    }
}

// ---------------------------------------------------------------------------
// Launch sequence
// ---------------------------------------------------------------------------
extern "C" void kernel_launch(void* const* d_in, const int* in_sizes, int n_in,
                              void* d_out, int out_size)
{
    const float* query = (const float*)d_in[0];
    const float* key_  = (const float*)d_in[1];
    const float* value = (const float*)d_in[2];
    const int*   qpos  = (const int*)d_in[4];
    const int*   kpos  = (const int*)d_in[5];
    const float* Wq = (const float*)d_in[6];  const float* bq = (const float*)d_in[7];
    const float* Wk = (const float*)d_in[8];  const float* bk = (const float*)d_in[9];
    const float* Wv = (const float*)d_in[10]; const float* bv = (const float*)d_in[11];
    const float* Wo = (const float*)d_in[12]; const float* bo = (const float*)d_in[13];
    const float* relk  = (const float*)d_in[14];
    const float* relv  = (const float*)d_in[15];
    const float* wpre  = (const float*)d_in[16];
    const float* wpost = (const float*)d_in[17];
    float* out = (float*)d_out;

    float *Q, *Kc, *V, *qbar, *Rbar, *Sc, *Ap, *Y, *ctx, *ropeT;
    cudaGetSymbolAddress((void**)&Q,     g_Q);
    cudaGetSymbolAddress((void**)&Kc,    g_K);
    cudaGetSymbolAddress((void**)&V,     g_V);
    cudaGetSymbolAddress((void**)&qbar,  g_qbar);
    cudaGetSymbolAddress((void**)&Rbar,  g_Rbar);
    cudaGetSymbolAddress((void**)&Sc,    g_S);
    cudaGetSymbolAddress((void**)&Ap,    g_Ap);
    cudaGetSymbolAddress((void**)&Y,     g_Y);
    cudaGetSymbolAddress((void**)&ctx,   g_ctx);
    cudaGetSymbolAddress((void**)&ropeT, g_ropeT);

    dim3 blk(256);
    const long S2 = (long)SS * SS;
    const long SD = (long)SS * DM;
    const int GS = G_SMEM_BYTES;
    const int TS = T_SMEM_BYTES;

    cudaFuncSetAttribute(gemm_tf32_kernel<true,  true>,
                         cudaFuncAttributeMaxDynamicSharedMemorySize, GS);
    cudaFuncSetAttribute(gemm_tf32_kernel<false, false>,
                         cudaFuncAttributeMaxDynamicSharedMemorySize, GS);
    cudaFuncSetAttribute(gemm_tf32_kernel<false, true>,
                         cudaFuncAttributeMaxDynamicSharedMemorySize, GS);
    cudaFuncSetAttribute(proj128_kernel,
                         cudaFuncAttributeMaxDynamicSharedMemorySize, TS);
    cudaFuncSetAttribute(qk128_kernel,
                         cudaFuncAttributeMaxDynamicSharedMemorySize, TS);

    rope_table_kernel<<<256, 256>>>(ropeT);

    // Q, K, V projections in ONE launch (fused bias + RoPE on Q/K)
    Proj3 qkv;
    qkv.A[0] = query; qkv.A[1] = key_; qkv.A[2] = value;
    qkv.W[0] = Wq;    qkv.W[1] = Wk;   qkv.W[2] = Wv;
    qkv.C[0] = Q;     qkv.C[1] = Kc;   qkv.C[2] = V;
    qkv.bias[0] = bq; qkv.bias[1] = bk; qkv.bias[2] = bv;
    qkv.pos[0] = qpos; qkv.pos[1] = kpos; qkv.pos[2] = nullptr;
    proj128_kernel<<<dim3(8, 16, 3), blk, TS>>>(qkv, ropeT);

    qbar_kernel<<<8192, 256>>>(Q, wpre, qbar);

    // Rbar slim = qbar @ relk[128:257]^T  (N = 129 -> guarded, 3 n-tiles)
    gemm_tf32_kernel<true, true><<<dim3(3, 256, 1), blk, GS>>>(qbar, relk + 128 * DD, Rbar,
        32768, NRS, 64,
        64, 64, NRS, 0, 0, 0, 0, 0, 0, 1, nullptr, nullptr, 0, 0, 0, 0);

    // QK^T per head, causal tile-skip
    qk128_kernel<<<dim3(8, 8, 32), blk, TS>>>(Q, Kc, Sc);

    cudaFuncSetAttribute(mix_softmax_kernel,
                         cudaFuncAttributeMaxDynamicSharedMemorySize, MIX_SMEM);
    mix_softmax_kernel<<<dim3(1024, 2), 512, MIX_SMEM>>>(Sc, Rbar, wpre, wpost, Ap);

    // Y = A'_slim @ relv[128:257]  (K = 129 -> guarded)
    gemm_tf32_kernel<false, true><<<dim3(1, 256, 1), blk, GS>>>(Ap, relv + 128 * DD, Y,
        32768, 64, NRS,
        NRS, 64, 64, 0, 0, 0, 0, 0, 0, 1, nullptr, nullptr, 0, 0, 0, 0);

    // ctx = attn @ v + Y, causal K-limit, batch = 32
    gemm_tf32_kernel<false, false><<<dim3(1, 8, 32), blk, GS>>>(Sc, V, ctx, 1024, 64, 1024,
        1024, 1024, 1024,
        S2, 16L * S2, 64L, SD, 64L, SD,
        16, nullptr,
        Y, 64, 65536L, 16L * 65536L, 2);

    // out = ctx @ Wo^T + bo
    Proj3 wo;
    wo.A[0] = ctx; wo.A[1] = nullptr; wo.A[2] = nullptr;
    wo.W[0] = Wo;  wo.W[1] = nullptr; wo.W[2] = nullptr;
    wo.C[0] = out; wo.C[1] = nullptr; wo.C[2] = nullptr;
    wo.bias[0] = bo; wo.bias[1] = nullptr; wo.bias[2] = nullptr;
    wo.pos[0] = nullptr; wo.pos[1] = nullptr; wo.pos[2] = nullptr;
    proj128_kernel<<<dim3(8, 16, 1), blk, TS>>>(wo, ropeT);
}

// round 11
// speedup vs baseline: 3.6590x; 1.0866x over previous
#include <cuda_runtime.h>
#include <cuda_bf16.h>
#include <math.h>
#include <stdint.h>

// Problem constants
#define BB 2
#define SS 1024
#define HH 16
#define DD 64
#define DM 1024
#define NRS 129        // slim rel width: indices 128..256 of the full table

// Scratch (device globals)
__device__ float g_Q[BB*SS*DM];
__device__ float g_K[BB*SS*DM];
__device__ float g_V[BB*SS*DM];
__device__ float g_qbar[BB*HH*SS*DD];
__device__ float g_Rbar[BB*HH*SS*NRS];
__device__ float g_S[BB*HH*SS*SS];
__device__ float g_Ap[BB*HH*SS*NRS];
__device__ float g_ctx[BB*SS*DM];
__device__ float g_ropeT[2048*64];

__device__ __forceinline__ unsigned f2tf32(float v) {
    unsigned u;
    asm("cvt.rna.tf32.f32 %0, %1;" : "=r"(u) : "f"(v));
    return u;
}

__device__ __forceinline__ void mma_tf32(float c[4],
                                         unsigned a0, unsigned a1, unsigned a2, unsigned a3,
                                         unsigned b0, unsigned b1) {
    asm volatile("mma.sync.aligned.m16n8k8.row.col.f32.tf32.tf32.f32 "
                 "{%0,%1,%2,%3}, {%4,%5,%6,%7}, {%8,%9}, {%0,%1,%2,%3};"
                 : "+f"(c[0]), "+f"(c[1]), "+f"(c[2]), "+f"(c[3])
                 : "r"(a0), "r"(a1), "r"(a2), "r"(a3), "r"(b0), "r"(b1));
}

// ===========================================================================
// 128x128 tf32 GEMM core (warp tile 64x32, K-step 16, double buffered).
// ===========================================================================
#define T_AW 2048
#define T_BW 2048
#define T_BUF (T_AW + T_BW)
#define T_LDST 132
#define T_SMEM_BYTES (64 * T_LDST * 4)

#define GEMM128_BODY(TRANSB_, KTOT, Aptr, Bptr, lda_, ldb_)                          \
    float acc[4][4][4];                                                              \
    _Pragma("unroll")                                                                \
    for (int i = 0; i < 4; i++)                                                      \
        _Pragma("unroll")                                                            \
        for (int j = 0; j < 4; j++)                                                  \
            _Pragma("unroll")                                                        \
            for (int e = 0; e < 4; e++) acc[i][j][e] = 0.f;                          \
    float aPf[8], bPf[8];                                                            \
    int ra = tid >> 4, ka = tid & 15;                                                \
    auto fetchA = [&](int kt) {                                                      \
        _Pragma("unroll")                                                            \
        for (int u = 0; u < 8; u++)                                                  \
            aPf[u] = Aptr[(long)(m0 + ra + u * 16) * lda_ + kt + ka];                \
    };                                                                               \
    auto fetchB = [&](int kt) {                                                      \
        _Pragma("unroll")                                                            \
        for (int u = 0; u < 8; u++) {                                                \
            int idx = tid + u * 256;                                                 \
            if (TRANSB_) {                                                           \
                int n = idx >> 4, kk = idx & 15;                                     \
                bPf[u] = Bptr[(long)(n0 + n) * ldb_ + kt + kk];                      \
            } else {                                                                 \
                int kk = idx >> 7, n = idx & 127;                                    \
                bPf[u] = Bptr[(long)(kt + kk) * ldb_ + n0 + n];                      \
            }                                                                        \
        }                                                                            \
    };                                                                               \
    auto storeBuf = [&](int buf) {                                                   \
        unsigned* Af = base + buf * T_BUF;                                           \
        unsigned* Bf = Af + T_AW;                                                    \
        _Pragma("unroll")                                                            \
        for (int u = 0; u < 8; u++) {                                                \
            int r = ra + u * 16, kk = ka;                                            \
            int blk = r >> 4, rr = r & 15;                                           \
            int ks8 = kk >> 3, kt7 = kk & 7;                                         \
            int dl = ((rr & 7) << 2) | (kt7 & 3);                                    \
            int w  = ((rr >> 3) & 1) | ((kt7 >> 2) << 1);                            \
            Af[(((blk << 1) | ks8) << 7) + (dl << 2) + w] = f2tf32(aPf[u]);          \
        }                                                                            \
        _Pragma("unroll")                                                            \
        for (int u = 0; u < 8; u++) {                                                \
            int idx = tid + u * 256;                                                 \
            int n, kk;                                                               \
            if (TRANSB_) { n = idx >> 4; kk = idx & 15; }                            \
            else         { kk = idx >> 7; n = idx & 127; }                           \
            int nb8 = n >> 3, gg = n & 7;                                            \
            int ks8 = kk >> 3, kt7 = kk & 7;                                         \
            int dl = (gg << 2) | (kt7 & 3);                                          \
            int w  = (kt7 >> 2) & 1;                                                 \
            Bf[(((nb8 << 1) | ks8) << 6) + (dl << 1) + w] = f2tf32(bPf[u]);          \
        }                                                                            \
    };                                                                               \
    fetchA(0); fetchB(0);                                                            \
    storeBuf(0);                                                                     \
    __syncthreads();                                                                 \
    int cur = 0;                                                                     \
    for (int kt = 0; kt < (KTOT); kt += 16) {                                        \
        bool hn = (kt + 16) < (KTOT);                                                \
        if (hn) { fetchA(kt + 16); fetchB(kt + 16); }                                \
        unsigned* Af = base + cur * T_BUF;                                           \
        unsigned* Bf = Af + T_AW;                                                    \
        _Pragma("unroll")                                                            \
        for (int ks8 = 0; ks8 < 2; ks8++) {                                          \
            uint4 av[4];                                                             \
            _Pragma("unroll")                                                        \
            for (int i = 0; i < 4; i++) {                                            \
                int blk = wm * 4 + i;                                                \
                av[i] = *(const uint4*)&Af[(((blk << 1) | ks8) << 7) + (lane << 2)]; \
            }                                                                        \
            _Pragma("unroll")                                                        \
            for (int j = 0; j < 4; j++) {                                            \
                int nb8 = wn * 4 + j;                                                \
                uint2 bv = *(const uint2*)&Bf[(((nb8 << 1) | ks8) << 6) + (lane << 1)]; \
                _Pragma("unroll")                                                    \
                for (int i = 0; i < 4; i++)                                          \
                    mma_tf32(acc[i][j], av[i].x, av[i].y, av[i].z, av[i].w, bv.x, bv.y); \
            }                                                                        \
        }                                                                            \
        if (hn) storeBuf(cur ^ 1);                                                   \
        __syncthreads();                                                             \
        cur ^= 1;                                                                    \
    }

#define STAGE_STORE(step_)                                                           \
    if (wm == (step_)) {                                                             \
        _Pragma("unroll")                                                            \
        for (int i = 0; i < 4; i++)                                                  \
            _Pragma("unroll")                                                        \
            for (int j = 0; j < 4; j++) {                                            \
                int r0 = i * 16 + g;                                                 \
                int c0 = wn * 32 + j * 8 + 2 * t;                                    \
                stage[ r0      * T_LDST + c0    ] = acc[i][j][0];                    \
                stage[ r0      * T_LDST + c0 + 1] = acc[i][j][1];                    \
                stage[(r0 + 8) * T_LDST + c0    ] = acc[i][j][2];                    \
                stage[(r0 + 8) * T_LDST + c0 + 1] = acc[i][j][3];                    \
            }                                                                        \
    }

// ---------------------------------------------------------------------------
// Projection kernel (z selects pointer triple), fused bias + optional RoPE
// ---------------------------------------------------------------------------
struct Proj3 {
    const float* A[3];
    const float* W[3];
    float*       C[3];
    const float* bias[3];
    const int*   pos[3];
};

__global__ void __launch_bounds__(256, 2)
proj128_kernel(Proj3 p, const float* __restrict__ ropeTab)
{
    extern __shared__ __align__(16) unsigned char dynsm[];
    unsigned* base = (unsigned*)dynsm;
    float* stage = (float*)dynsm;

    int z = blockIdx.z;
    const float* A = p.A[z];
    const float* W = p.W[z];
    float* C = p.C[z];
    const float* bias = p.bias[z];
    const int* posIds = p.pos[z];

    int tid = threadIdx.x;
    int wid = tid >> 5, lane = tid & 31;
    int wm = wid >> 2, wn = wid & 3;
    int g = lane >> 2, t = lane & 3;
    int m0 = blockIdx.y * 128, n0 = blockIdx.x * 128;

    GEMM128_BODY(true, DM, A, W, DM, DM)

    #pragma unroll
    for (int step = 0; step < 2; step++) {
        STAGE_STORE(step)
        __syncthreads();
        #pragma unroll
        for (int u = 0; u < 8; u++) {
            int idx = tid + u * 256;
            int r = idx >> 5, c4 = idx & 31;
            int c = c4 * 4;
            int gm = m0 + step * 64 + r;
            float4 v = *(const float4*)(stage + r * T_LDST + c);
            float4 bv = *(const float4*)(bias + n0 + c);
            v.x += bv.x; v.y += bv.y; v.z += bv.z; v.w += bv.w;
            if (posIds) {
                float4 w = *(const float4*)(stage + r * T_LDST + (c ^ 32));
                float4 bw = *(const float4*)(bias + n0 + (c ^ 32));
                w.x += bw.x; w.y += bw.y; w.z += bw.z; w.w += bw.w;
                int b = gm >> 10, s = gm & 1023;
                int pos = posIds[(b << 10) + s];
                int i0 = c & 31;
                float4 co = *(const float4*)(ropeTab + pos * 64 + i0);
                float4 si = *(const float4*)(ropeTab + pos * 64 + 32 + i0);
                if ((c & 32) == 0) {
                    v.x = v.x * co.x - w.x * si.x;
                    v.y = v.y * co.y - w.y * si.y;
                    v.z = v.z * co.z - w.z * si.z;
                    v.w = v.w * co.w - w.w * si.w;
                } else {
                    v.x = v.x * co.x + w.x * si.x;
                    v.y = v.y * co.y + w.y * si.y;
                    v.z = v.z * co.z + w.z * si.z;
                    v.w = v.w * co.w + w.w * si.w;
                }
            }
            *(float4*)(C + (long)gm * DM + n0 + c) = v;
        }
        __syncthreads();
    }
}

// ---------------------------------------------------------------------------
// QK^T kernel, causal tile skip
// ---------------------------------------------------------------------------
__global__ void __launch_bounds__(256, 2)
qk128_kernel(const float* __restrict__ Qm, const float* __restrict__ Km,
             float* __restrict__ S)
{
    extern __shared__ __align__(16) unsigned char dynsm[];
    unsigned* base = (unsigned*)dynsm;
    float* stage = (float*)dynsm;

    int m0 = blockIdx.y * 128, n0 = blockIdx.x * 128;
    if (n0 > m0) return;

    int z = blockIdx.z;
    int b = z >> 4, h = z & 15;
    const float* A = Qm + (long)b * SS * DM + h * 64;
    const float* Bp = Km + (long)b * SS * DM + h * 64;
    float* C = S + (long)z * SS * SS;

    int tid = threadIdx.x;
    int wid = tid >> 5, lane = tid & 31;
    int wm = wid >> 2, wn = wid & 3;
    int g = lane >> 2, t = lane & 3;

    GEMM128_BODY(true, 64, A, Bp, DM, DM)

    #pragma unroll
    for (int step = 0; step < 2; step++) {
        STAGE_STORE(step)
        __syncthreads();
        #pragma unroll
        for (int u = 0; u < 8; u++) {
            int idx = tid + u * 256;
            int r = idx >> 5, c4 = idx & 31;
            int c = c4 * 4;
            int gm = m0 + step * 64 + r;
            float4 v = *(const float4*)(stage + r * T_LDST + c);
            *(float4*)(C + (long)gm * SS + n0 + c) = v;
        }
        __syncthreads();
    }
}

// ---------------------------------------------------------------------------
// TN=64 tf32 GEMM (guarded) for Rbar
// ---------------------------------------------------------------------------
#define G_AWORDS 4096
#define G_BWORDS 2048
#define G_BUF (G_AWORDS + G_BWORDS)
#define G_LDST 68
#define G_SMEM_BYTES (2 * G_BUF * 4)

// common TN=64 loader/mma machinery as macros (GUARDED variant)
#define G64_DECLS                                                                   \
    int tid = threadIdx.x;                                                          \
    int wid = tid >> 5, lane = tid & 31;                                            \
    int wm = wid >> 1;                                                              \
    int wn = wid & 1;                                                               \
    int g = lane >> 2, t = lane & 3;                                                \
    int ra = tid >> 5, ka = tid & 31;                                               \
    float acc[2][4][4];                                                             \
    _Pragma("unroll")                                                               \
    for (int i = 0; i < 2; i++)                                                     \
        _Pragma("unroll")                                                           \
        for (int j = 0; j < 4; j++)                                                 \
            _Pragma("unroll")                                                       \
            for (int e = 0; e < 4; e++) acc[i][j][e] = 0.f;                         \
    float aPf[16], bPf[8];

#define G64_STOREBUF(buf, TRANSB_)                                                  \
    {                                                                               \
        unsigned* Af = base + (buf) * G_BUF;                                        \
        unsigned* Bf = Af + G_AWORDS;                                               \
        _Pragma("unroll")                                                           \
        for (int u = 0; u < 16; u++) {                                              \
            int r = ra + u * 8, kk = ka;                                            \
            int blk = r >> 4, rr = r & 15;                                          \
            int ks8 = kk >> 3, kt7 = kk & 7;                                        \
            int dl = ((rr & 7) << 2) | (kt7 & 3);                                   \
            int w  = ((rr >> 3) & 1) | ((kt7 >> 2) << 1);                           \
            Af[(((blk << 2) + ks8) << 7) + (dl << 2) + w] = f2tf32(aPf[u]);         \
        }                                                                           \
        _Pragma("unroll")                                                           \
        for (int u = 0; u < 8; u++) {                                               \
            int idx = tid + u * 256;                                                \
            int n, kk;                                                              \
            if (TRANSB_) { n = idx >> 5; kk = idx & 31; }                           \
            else         { kk = idx >> 6; n = idx & 63; }                           \
            int nb8 = n >> 3, gg = n & 7;                                           \
            int ks8 = kk >> 3, kt7 = kk & 7;                                        \
            int dl = (gg << 2) | (kt7 & 3);                                         \
            int w  = (kt7 >> 2) & 1;                                                \
            Bf[(((nb8 << 2) + ks8) << 6) + (dl << 1) + w] = f2tf32(bPf[u]);         \
        }                                                                           \
    }

#define G64_MMA(bufc)                                                               \
    {                                                                               \
        unsigned* Af = base + (bufc) * G_BUF;                                       \
        unsigned* Bf = Af + G_AWORDS;                                               \
        _Pragma("unroll")                                                           \
        for (int ks8 = 0; ks8 < 4; ks8++) {                                         \
            uint4 av[2];                                                            \
            _Pragma("unroll")                                                       \
            for (int i = 0; i < 2; i++) {                                           \
                int blk = wm * 2 + i;                                               \
                av[i] = *(const uint4*)&Af[(((blk << 2) + ks8) << 7) + (lane << 2)];\
            }                                                                       \
            _Pragma("unroll")                                                       \
            for (int j = 0; j < 4; j++) {                                           \
                int nb8 = wn * 4 + j;                                               \
                uint2 bv = *(const uint2*)&Bf[(((nb8 << 2) + ks8) << 6) + (lane << 1)]; \
                _Pragma("unroll")                                                   \
                for (int i = 0; i < 2; i++)                                         \
                    mma_tf32(acc[i][j], av[i].x, av[i].y, av[i].z, av[i].w, bv.x, bv.y); \
            }                                                                       \
        }                                                                           \
    }

// Rbar kernel: C[32768, 129] = A[32768,64] @ B[129,64]^T (guarded)
__global__ void __launch_bounds__(256, 2)
rbar_kernel(const float* __restrict__ A, const float* __restrict__ Bm,
            float* __restrict__ C)
{
    extern __shared__ __align__(16) unsigned char dynsm[];
    unsigned* base = (unsigned*)dynsm;
    float* stage = (float*)dynsm;

    const int M = 32768, N = NRS, K = 64;
    int m0 = blockIdx.y * 128, n0 = blockIdx.x * 64;

    G64_DECLS

    auto fetchA = [&](int kt) {
        #pragma unroll
        for (int u = 0; u < 16; u++) {
            int r = ra + u * 8;
            aPf[u] = A[(long)(m0 + r) * 64 + kt + ka];   // M,K exact multiples
        }
    };
    auto fetchB = [&](int kt) {
        #pragma unroll
        for (int u = 0; u < 8; u++) {
            int idx = tid + u * 256;
            int n = idx >> 5, kk = idx & 31;
            int gn = n0 + n;
            bPf[u] = (gn < N) ? Bm[(long)gn * 64 + kt + kk] : 0.f;
        }
    };

    fetchA(0); fetchB(0);
    G64_STOREBUF(0, true)
    __syncthreads();
    int cur = 0;
    for (int kt = 0; kt < K; kt += 32) {
        bool hn = (kt + 32) < K;
        if (hn) { fetchA(kt + 32); fetchB(kt + 32); }
        G64_MMA(cur)
        if (hn) G64_STOREBUF(cur ^ 1, true)
        __syncthreads();
        cur ^= 1;
    }

    #pragma unroll
    for (int step = 0; step < 2; step++) {
        if ((wm >> 1) == step) {
            int rbase = (wm & 1) * 32;
            #pragma unroll
            for (int i = 0; i < 2; i++)
                #pragma unroll
                for (int j = 0; j < 4; j++) {
                    int r0 = rbase + i * 16 + g;
                    int c0 = wn * 32 + j * 8 + 2 * t;
                    stage[ r0      * G_LDST + c0    ] = acc[i][j][0];
                    stage[ r0      * G_LDST + c0 + 1] = acc[i][j][1];
                    stage[(r0 + 8) * G_LDST + c0    ] = acc[i][j][2];
                    stage[(r0 + 8) * G_LDST + c0 + 1] = acc[i][j][3];
                }
        }
        __syncthreads();
        #pragma unroll
        for (int u = 0; u < 16; u++) {
            int idx = tid + u * 256;
            int r = idx >> 6, c = idx & 63;
            int gm = m0 + step * 64 + r, gn = n0 + c;
            if (gn < N)
                C[(long)gm * NRS + gn] = stage[r * G_LDST + c];
        }
        __syncthreads();
    }
}

// ---------------------------------------------------------------------------
// Fused AV kernel: ctx[b,s,h*64+d] = attn[b,h] @ V[b,:,h] + Ap[b,h] @ relv'
// Grid (1, 8, 32). Primary loop K = m0+128 (causal), secondary K2 = 129 guarded.
// ---------------------------------------------------------------------------
__global__ void __launch_bounds__(256, 2)
av_fused_kernel(const float* __restrict__ Sc, const float* __restrict__ Vm,
                const float* __restrict__ Ap, const float* __restrict__ relv2,
                float* __restrict__ ctx)
{
    extern __shared__ __align__(16) unsigned char dynsm[];
    unsigned* base = (unsigned*)dynsm;
    float* stage = (float*)dynsm;

    int m0 = blockIdx.y * 128, n0 = 0;
    int z = blockIdx.z;
    int b = z >> 4, h = z & 15;
    int Keff = m0 + 128;                      // causal limit

    const float* A  = Sc + (long)z * SS * SS;              // attn [1024,1024]
    const float* Bv = Vm + (long)b * SS * DM + h * 64;     // V rows [1024, ld=DM]
    const float* A2 = Ap + (long)z * SS * NRS;             // [1024, 129]
    float* C = ctx + (long)b * SS * DM + h * 64;

    G64_DECLS

    // ---- primary: attn @ V (unguarded; Keff multiple of 32... 128*y+128 yes) ----
    auto fetchA1 = [&](int kt) {
        #pragma unroll
        for (int u = 0; u < 16; u++)
            aPf[u] = A[(long)(m0 + ra + u * 8) * SS + kt + ka];
    };
    auto fetchB1 = [&](int kt) {
        #pragma unroll
        for (int u = 0; u < 8; u++) {
            int idx = tid + u * 256;
            int kk = idx >> 6, n = idx & 63;
            bPf[u] = Bv[(long)(kt + kk) * DM + n];
        }
    };
    // ---- secondary: Ap @ relv' (k-guarded at 129) ----
    auto fetchA2 = [&](int kt) {
        #pragma unroll
        for (int u = 0; u < 16; u++) {
            int gk = kt + ka;
            aPf[u] = (gk < NRS) ? A2[(long)(m0 + ra + u * 8) * NRS + gk] : 0.f;
        }
    };
    auto fetchB2 = [&](int kt) {
        #pragma unroll
        for (int u = 0; u < 8; u++) {
            int idx = tid + u * 256;
            int kk = idx >> 6, n = idx & 63;
            int gk = kt + kk;
            bPf[u] = (gk < NRS) ? relv2[(long)gk * 64 + n] : 0.f;
        }
    };

    const int K2 = 160;    // 129 rounded to 32
    fetchA1(0); fetchB1(0);
    G64_STOREBUF(0, false)
    __syncthreads();
    int cur = 0;
    // primary loop; at its end prefetch the secondary's first chunk
    for (int kt = 0; kt < Keff; kt += 32) {
        bool hn = (kt + 32) < Keff;
        if (hn)      { fetchA1(kt + 32); fetchB1(kt + 32); }
        else         { fetchA2(0);       fetchB2(0);       }
        G64_MMA(cur)
        G64_STOREBUF(cur ^ 1, false)
        __syncthreads();
        cur ^= 1;
    }
    // secondary loop
    for (int kt = 0; kt < K2; kt += 32) {
        bool hn = (kt + 32) < K2;
        if (hn) { fetchA2(kt + 32); fetchB2(kt + 32); }
        G64_MMA(cur)
        if (hn) G64_STOREBUF(cur ^ 1, false)
        __syncthreads();
        cur ^= 1;
    }

    #pragma unroll
    for (int step = 0; step < 2; step++) {
        if ((wm >> 1) == step) {
            int rbase = (wm & 1) * 32;
            #pragma unroll
            for (int i = 0; i < 2; i++)
                #pragma unroll
                for (int j = 0; j < 4; j++) {
                    int r0 = rbase + i * 16 + g;
                    int c0 = wn * 32 + j * 8 + 2 * t;
                    stage[ r0      * G_LDST + c0    ] = acc[i][j][0];
                    stage[ r0      * G_LDST + c0 + 1] = acc[i][j][1];
                    stage[(r0 + 8) * G_LDST + c0    ] = acc[i][j][2];
                    stage[(r0 + 8) * G_LDST + c0 + 1] = acc[i][j][3];
                }
        }
        __syncthreads();
        #pragma unroll
        for (int u = 0; u < 4; u++) {
            int idx = tid + u * 256;
            int r = idx >> 4, c4 = idx & 15;
            int c = c4 * 4;
            int gm = m0 + step * 64 + r;
            float4 v = *(const float4*)(stage + r * G_LDST + c);
            *(float4*)(C + (long)gm * DM + c) = v;
        }
        __syncthreads();
    }
}

// ---------------------------------------------------------------------------
// RoPE table
// ---------------------------------------------------------------------------
__global__ void rope_table_kernel(float* __restrict__ T)
{
    int idx = blockIdx.x * blockDim.x + threadIdx.x;
    if (idx >= 2048 * 32) return;
    int i = idx & 31, pos = idx >> 5;
    double inv = exp(-(double)i / 32.0 * log(10000.0));
    double ds, dc;
    sincos((double)pos * inv, &ds, &dc);
    T[pos * 64 + i]      = (float)dc;
    T[pos * 64 + 32 + i] = (float)ds;
}

// ---------------------------------------------------------------------------
// qbar v2: thread per (b,s,d) computes all 16 head-mix outputs
// ---------------------------------------------------------------------------
__global__ void qbar_kernel(const float* __restrict__ Q, const float* __restrict__ wpre,
                            float* __restrict__ qbar)
{
    __shared__ float sw[256];
    if (threadIdx.x < 256) sw[threadIdx.x] = wpre[threadIdx.x];
    __syncthreads();

    int idx = blockIdx.x * blockDim.x + threadIdx.x;   // B*S*D = 131072
    if (idx >= BB * SS * DD) return;
    int d = idx & 63;
    int s = (idx >> 6) & 1023;
    int b = idx >> 16;
    const float* qrow = Q + ((size_t)(b * SS + s)) * DM + d;
    float qv[16];
    #pragma unroll
    for (int n = 0; n < 16; n++) qv[n] = qrow[n * 64];
    #pragma unroll
    for (int m = 0; m < 16; m++) {
        float acc = 0.f;
        #pragma unroll
        for (int n = 0; n < 16; n++) acc += sw[n * 16 + m] * qv[n];
        qbar[(((size_t)(b * 16 + m)) * SS + s) * DD + d] = acc;
    }
}

// ---------------------------------------------------------------------------
// mix_softmax — slim rel layout (NRS = 129)
// ---------------------------------------------------------------------------
#define MIX_SMEM ((16*1024 + 16*NRS + 256 + 256 + 16 + 16) * 4)

__global__ void __launch_bounds__(512)
mix_softmax_kernel(float* __restrict__ S, const float* __restrict__ Rbar,
                   const float* __restrict__ wpre, const float* __restrict__ wpost,
                   float* __restrict__ Ap)
{
    extern __shared__ float shm[];
    float* sm     = shm;
    float* srb    = sm + 16 * 1024;
    float* swpre  = srb + 16 * NRS;
    float* swpost = swpre + 256;
    float* sinv   = swpost + 256;
    float* stail  = sinv + 16;

    int q = blockIdx.x, b = blockIdx.y;
    int tid = threadIdx.x;
    int wid = tid >> 5, lane = tid & 31;
    int KW4 = ((q >> 7) + 1) << 5;
    int KW  = KW4 << 2;

    if (tid < 256) { swpre[tid] = wpre[tid]; swpost[tid] = wpost[tid]; }
    {
        const long rowBase = ((long)(b * 16) * SS + q) * SS;
        for (int tt = tid; tt < 16 * 256; tt += 512) {
            int n = tt >> 8, k4 = tt & 255;
            if (k4 < KW4)
                ((float4*)sm)[n * 256 + k4] =
                    *(const float4*)(S + rowBase + (long)n * SS * SS + k4 * 4);
        }
    }
    for (int tt = tid; tt < 16 * NRS; tt += 512) {
        int m = tt / NRS, j = tt - m * NRS;
        srb[tt] = Rbar[((size_t)(b * 16 + m) * SS + q) * NRS + j];
    }
    __syncthreads();

    for (int k = tid; k <= q; k += 512) {
        float r[16];
        #pragma unroll
        for (int n = 0; n < 16; n++) r[n] = sm[n * 1024 + k];
        int d = q - k;
        int cl = d > 128 ? 128 : d;
        #pragma unroll
        for (int m = 0; m < 16; m++) {
            float accv = 0.f;
            #pragma unroll
            for (int n = 0; n < 16; n++) accv += swpre[n * 16 + m] * r[n];
            sm[m * 1024 + k] = (accv + srb[m * NRS + cl]) * 0.125f;
        }
    }
    __syncthreads();

    {
        int m = wid;
        float mx = -1e30f;
        for (int k = lane; k <= q; k += 32) mx = fmaxf(mx, sm[m * 1024 + k]);
        #pragma unroll
        for (int o = 16; o; o >>= 1) mx = fmaxf(mx, __shfl_xor_sync(0xffffffffu, mx, o));
        float sum = 0.f;
        for (int k = lane; k <= q; k += 32) {
            float p = __expf(sm[m * 1024 + k] - mx);
            sm[m * 1024 + k] = p;
            sum += p;
        }
        #pragma unroll
        for (int o = 16; o; o >>= 1) sum += __shfl_xor_sync(0xffffffffu, sum, o);
        for (int k = q + 1 + lane; k < KW; k += 32) sm[m * 1024 + k] = 0.f;
        if (lane == 0) sinv[m] = 1.f / sum;
    }
    __syncthreads();

    float inv[16];
    #pragma unroll
    for (int m = 0; m < 16; m++) inv[m] = sinv[m];
    for (int k = tid; k <= q; k += 512) {
        float p[16];
        #pragma unroll
        for (int m = 0; m < 16; m++) p[m] = sm[m * 1024 + k] * inv[m];
        #pragma unroll
        for (int n = 0; n < 16; n++) {
            float accv = 0.f;
            #pragma unroll
            for (int m = 0; m < 16; m++) accv += p[m] * swpost[m * 16 + n];
            sm[n * 1024 + k] = accv;
        }
    }
    __syncthreads();

    {
        const long rowBase = ((long)(b * 16) * SS + q) * SS;
        for (int tt = tid; tt < 16 * 256; tt += 512) {
            int n = tt >> 8, k4 = tt & 255;
            if (k4 < KW4)
                *(float4*)(S + rowBase + (long)n * SS * SS + k4 * 4) =
                    ((float4*)sm)[n * 256 + k4];
        }
    }
    {
        int m = wid;
        float ts = 0.f;
        for (int k = lane; k <= q - 128; k += 32) ts += sm[m * 1024 + k];
        #pragma unroll
        for (int o = 16; o; o >>= 1) ts += __shfl_xor_sync(0xffffffffu, ts, o);
        if (lane == 0) stail[m] = ts;
    }
    __syncthreads();

    for (int tt = tid; tt < 16 * NRS; tt += 512) {
        int n = tt / NRS, j = tt - n * NRS;
        float v = 0.f;
        if (j == 128) v = stail[n];
        else {
            int k = q - j;
            if (k >= 0) v = sm[n * 1024 + k];
        }
        Ap[((size_t)(b * 16 + n) * SS + q) * NRS + j] = v;
    }
}

// ---------------------------------------------------------------------------
// Launch sequence
// ---------------------------------------------------------------------------
extern "C" void kernel_launch(void* const* d_in, const int* in_sizes, int n_in,
                              void* d_out, int out_size)
{
    const float* query = (const float*)d_in[0];
    const float* key_  = (const float*)d_in[1];
    const float* value = (const float*)d_in[2];
    const int*   qpos  = (const int*)d_in[4];
    const int*   kpos  = (const int*)d_in[5];
    const float* Wq = (const float*)d_in[6];  const float* bq = (const float*)d_in[7];
    const float* Wk = (const float*)d_in[8];  const float* bk = (const float*)d_in[9];
    const float* Wv = (const float*)d_in[10]; const float* bv = (const float*)d_in[11];
    const float* Wo = (const float*)d_in[12]; const float* bo = (const float*)d_in[13];
    const float* relk  = (const float*)d_in[14];
    const float* relv  = (const float*)d_in[15];
    const float* wpre  = (const float*)d_in[16];
    const float* wpost = (const float*)d_in[17];
    float* out = (float*)d_out;

    float *Q, *Kc, *V, *qbar, *Rbar, *Sc, *Ap, *ctx, *ropeT;
    cudaGetSymbolAddress((void**)&Q,     g_Q);
    cudaGetSymbolAddress((void**)&Kc,    g_K);
    cudaGetSymbolAddress((void**)&V,     g_V);
    cudaGetSymbolAddress((void**)&qbar,  g_qbar);
    cudaGetSymbolAddress((void**)&Rbar,  g_Rbar);
    cudaGetSymbolAddress((void**)&Sc,    g_S);
    cudaGetSymbolAddress((void**)&Ap,    g_Ap);
    cudaGetSymbolAddress((void**)&ctx,   g_ctx);
    cudaGetSymbolAddress((void**)&ropeT, g_ropeT);

    dim3 blk(256);
    const int GS = G_SMEM_BYTES;
    const int TS = T_SMEM_BYTES;

    cudaFuncSetAttribute(rbar_kernel,
                         cudaFuncAttributeMaxDynamicSharedMemorySize, GS);
    cudaFuncSetAttribute(av_fused_kernel,
                         cudaFuncAttributeMaxDynamicSharedMemorySize, GS);
    cudaFuncSetAttribute(proj128_kernel,
                         cudaFuncAttributeMaxDynamicSharedMemorySize, TS);
    cudaFuncSetAttribute(qk128_kernel,
                         cudaFuncAttributeMaxDynamicSharedMemorySize, TS);

    rope_table_kernel<<<256, 256>>>(ropeT);

    // Q, K, V projections in ONE launch (fused bias + RoPE on Q/K)
    Proj3 qkv;
    qkv.A[0] = query; qkv.A[1] = key_; qkv.A[2] = value;
    qkv.W[0] = Wq;    qkv.W[1] = Wk;   qkv.W[2] = Wv;
    qkv.C[0] = Q;     qkv.C[1] = Kc;   qkv.C[2] = V;
    qkv.bias[0] = bq; qkv.bias[1] = bk; qkv.bias[2] = bv;
    qkv.pos[0] = qpos; qkv.pos[1] = kpos; qkv.pos[2] = nullptr;
    proj128_kernel<<<dim3(8, 16, 3), blk, TS>>>(qkv, ropeT);

    qbar_kernel<<<512, 256>>>(Q, wpre, qbar);

    // Rbar slim = qbar @ relk[128:257]^T
    rbar_kernel<<<dim3(3, 256, 1), blk, GS>>>(qbar, relk + 128 * DD, Rbar);

    // QK^T per head, causal tile-skip
    qk128_kernel<<<dim3(8, 8, 32), blk, TS>>>(Q, Kc, Sc);

    cudaFuncSetAttribute(mix_softmax_kernel,
                         cudaFuncAttributeMaxDynamicSharedMemorySize, MIX_SMEM);
    mix_softmax_kernel<<<dim3(1024, 2), 512, MIX_SMEM>>>(Sc, Rbar, wpre, wpost, Ap);

    // ctx = attn @ v + Ap @ relv'  (fused, causal K-limit)
    av_fused_kernel<<<dim3(1, 8, 32), blk, GS>>>(Sc, V, Ap, relv + 128 * DD, ctx);

    // out = ctx @ Wo^T + bo
    Proj3 wo;
    wo.A[0] = ctx; wo.A[1] = nullptr; wo.A[2] = nullptr;
    wo.W[0] = Wo;  wo.W[1] = nullptr; wo.W[2] = nullptr;
    wo.C[0] = out; wo.C[1] = nullptr; wo.C[2] = nullptr;
    wo.bias[0] = bo; wo.bias[1] = nullptr; wo.bias[2] = nullptr;
    wo.pos[0] = nullptr; wo.pos[1] = nullptr; wo.pos[2] = nullptr;
    proj128_kernel<<<dim3(8, 16, 1), blk, TS>>>(wo, ropeT);
}